// round 2
// baseline (speedup 1.0000x reference)
#include <cuda_runtime.h>
#include <math.h>

#define N_NODES 30000
#define F_IN    256
#define N_EDGES 300000
#define HEADS   8
#define CDIM    128
#define HC      1024      // HEADS*CDIM
#define OUTD    64
#define NEG_SLOPE 0.2f

// ---------------- scratch (static device allocations) ----------------
__device__ __align__(256) float    d_h1  [(size_t)N_NODES * HC];   // 122.9 MB
__device__ __align__(256) float    d_agg1[(size_t)N_NODES * HC];   // 122.9 MB
__device__ __align__(256) float    d_asrc1[N_NODES * HEADS];
__device__ __align__(256) float    d_adst1[N_NODES * HEADS];
__device__ __align__(256) unsigned d_m1  [N_NODES * HEADS];
__device__ __align__(256) float    d_s1  [N_NODES * HEADS];
__device__ __align__(256) float    d_h2  [(size_t)N_NODES * OUTD];
__device__ __align__(256) float    d_asrc2[N_NODES];
__device__ __align__(256) float    d_adst2[N_NODES];
__device__ __align__(256) unsigned d_m2  [N_NODES];
__device__ __align__(256) float    d_s2  [N_NODES];

// ---------------- helpers ----------------
__device__ __forceinline__ float lrelu(float x) { return x > 0.f ? x : NEG_SLOPE * x; }

// order-preserving float <-> uint mapping for atomicMax on floats
__device__ __forceinline__ unsigned f2u(float f) {
    unsigned u = __float_as_uint(f);
    return (u & 0x80000000u) ? ~u : (u | 0x80000000u);
}
__device__ __forceinline__ float u2f(unsigned u) {
    return (u & 0x80000000u) ? __uint_as_float(u & 0x7FFFFFFFu) : __uint_as_float(~u);
}

__device__ __forceinline__ void red_add_v4(float* dst, float4 v) {
    asm volatile("red.global.add.v4.f32 [%0], {%1,%2,%3,%4};"
                 :: "l"(dst), "f"(v.x), "f"(v.y), "f"(v.z), "f"(v.w) : "memory");
}

// ---------------- GEMM: C[M,N] = A[M,K] @ B[K,N], N multiple of 128 ----------------
__global__ __launch_bounds__(256) void sgemm_n128(
    const float* __restrict__ A, const float* __restrict__ B,
    float* __restrict__ C, int M, int N, int K)
{
    __shared__ float As[8][128];
    __shared__ float Bs[8][128];
    int bx = blockIdx.x, by = blockIdx.y;
    int tid = threadIdx.x;
    int tx = tid & 15, ty = tid >> 4;     // 16x16 threads, 8x8 micro-tile
    float acc[8][8] = {};

    int arow = tid >> 1, acol = (tid & 1) * 4;       // A tile loader: 1 float4/thread
    int brow = tid >> 5, bcol = (tid & 31) * 4;      // B tile loader: 1 float4/thread
    int gArow = by * 128 + arow;
    const float* Aptr = A + (size_t)gArow * K + acol;
    const float* Bptr = B + (size_t)brow * N + bx * 128 + bcol;

    for (int k0 = 0; k0 < K; k0 += 8) {
        float4 av = (gArow < M) ? *(const float4*)Aptr : make_float4(0.f, 0.f, 0.f, 0.f);
        As[acol + 0][arow] = av.x; As[acol + 1][arow] = av.y;
        As[acol + 2][arow] = av.z; As[acol + 3][arow] = av.w;
        *(float4*)&Bs[brow][bcol] = *(const float4*)Bptr;
        __syncthreads();
#pragma unroll
        for (int k = 0; k < 8; k++) {
            float ra[8], rb[8];
            *(float4*)&ra[0] = *(float4*)&As[k][ty * 8];
            *(float4*)&ra[4] = *(float4*)&As[k][ty * 8 + 4];
            *(float4*)&rb[0] = *(float4*)&Bs[k][tx * 8];
            *(float4*)&rb[4] = *(float4*)&Bs[k][tx * 8 + 4];
#pragma unroll
            for (int i = 0; i < 8; i++)
#pragma unroll
                for (int j = 0; j < 8; j++) acc[i][j] += ra[i] * rb[j];
        }
        __syncthreads();
        Aptr += 8; Bptr += (size_t)8 * N;
    }
#pragma unroll
    for (int i = 0; i < 8; i++) {
        int row = by * 128 + ty * 8 + i;
        if (row < M) {
            float* Cp = C + (size_t)row * N + bx * 128 + tx * 8;
            *(float4*)Cp       = make_float4(acc[i][0], acc[i][1], acc[i][2], acc[i][3]);
            *(float4*)(Cp + 4) = make_float4(acc[i][4], acc[i][5], acc[i][6], acc[i][7]);
        }
    }
}

// ---------------- GEMM: C[M,64] = A[M,K] @ B[K,64] ----------------
__global__ __launch_bounds__(256) void sgemm_n64(
    const float* __restrict__ A, const float* __restrict__ B,
    float* __restrict__ C, int M, int K)
{
    __shared__ float As[16][128];
    __shared__ float Bs[16][64];
    int by = blockIdx.x;
    int tid = threadIdx.x;
    int tx = tid & 15, ty = tid >> 4;     // 8x4 micro-tile
    float acc[8][4] = {};

    int v0 = tid, v1 = tid + 256;         // 2 float4 A loads / thread
    int ar0 = v0 >> 2, ac0 = (v0 & 3) * 4;
    int ar1 = v1 >> 2, ac1 = (v1 & 3) * 4;
    int gr0 = by * 128 + ar0, gr1 = by * 128 + ar1;
    int brow = tid >> 4, bcol = (tid & 15) * 4;

    for (int k0 = 0; k0 < K; k0 += 16) {
        float4 a0 = (gr0 < M) ? *(const float4*)(A + (size_t)gr0 * K + k0 + ac0)
                              : make_float4(0.f, 0.f, 0.f, 0.f);
        float4 a1 = (gr1 < M) ? *(const float4*)(A + (size_t)gr1 * K + k0 + ac1)
                              : make_float4(0.f, 0.f, 0.f, 0.f);
        As[ac0 + 0][ar0] = a0.x; As[ac0 + 1][ar0] = a0.y;
        As[ac0 + 2][ar0] = a0.z; As[ac0 + 3][ar0] = a0.w;
        As[ac1 + 0][ar1] = a1.x; As[ac1 + 1][ar1] = a1.y;
        As[ac1 + 2][ar1] = a1.z; As[ac1 + 3][ar1] = a1.w;
        *(float4*)&Bs[brow][bcol] = *(const float4*)(B + (size_t)(k0 + brow) * 64 + bcol);
        __syncthreads();
#pragma unroll
        for (int k = 0; k < 16; k++) {
            float ra[8], rb[4];
            *(float4*)&ra[0] = *(float4*)&As[k][ty * 8];
            *(float4*)&ra[4] = *(float4*)&As[k][ty * 8 + 4];
            *(float4*)&rb[0] = *(float4*)&Bs[k][tx * 4];
#pragma unroll
            for (int i = 0; i < 8; i++)
#pragma unroll
                for (int j = 0; j < 4; j++) acc[i][j] += ra[i] * rb[j];
        }
        __syncthreads();
    }
#pragma unroll
    for (int i = 0; i < 8; i++) {
        int row = by * 128 + ty * 8 + i;
        if (row < M)
            *(float4*)(C + (size_t)row * 64 + tx * 4) =
                make_float4(acc[i][0], acc[i][1], acc[i][2], acc[i][3]);
    }
}

// ---------------- layer-1 attention scores (warp per (node, head)) ----------------
__global__ void scores1_k(const float* __restrict__ att_s, const float* __restrict__ att_d)
{
    int w = (blockIdx.x * blockDim.x + threadIdx.x) >> 5;
    int lane = threadIdx.x & 31;
    if (w >= N_NODES * HEADS) return;
    int n = w / HEADS, h = w - n * HEADS;
    const float4* hp = (const float4*)(d_h1 + (size_t)n * HC + h * CDIM);
    const float4* as = (const float4*)(att_s + h * CDIM);
    const float4* ad = (const float4*)(att_d + h * CDIM);
    float4 hv = hp[lane], a1 = as[lane], a2 = ad[lane];
    float ss = hv.x * a1.x + hv.y * a1.y + hv.z * a1.z + hv.w * a1.w;
    float sd = hv.x * a2.x + hv.y * a2.y + hv.z * a2.z + hv.w * a2.w;
#pragma unroll
    for (int o = 16; o; o >>= 1) {
        ss += __shfl_xor_sync(0xFFFFFFFFu, ss, o);
        sd += __shfl_xor_sync(0xFFFFFFFFu, sd, o);
    }
    if (lane == 0) {
        d_asrc1[w] = ss;
        d_adst1[w] = sd;
        d_m1[w] = f2u(lrelu(ss + sd));   // self-loop logit seeds the segment max
    }
}

__global__ void edge_max1_k(const int* __restrict__ ei)
{
    int e = blockIdx.x * blockDim.x + threadIdx.x;
    if (e >= N_EDGES) return;
    int s = ei[e], d = ei[N_EDGES + e];
    const float4* as = (const float4*)(d_asrc1 + (size_t)s * HEADS);
    const float4* ad = (const float4*)(d_adst1 + (size_t)d * HEADS);
    float4 s0 = as[0], s1 = as[1], d0 = ad[0], d1 = ad[1];
    unsigned* mp = d_m1 + (size_t)d * HEADS;
    atomicMax(mp + 0, f2u(lrelu(s0.x + d0.x)));
    atomicMax(mp + 1, f2u(lrelu(s0.y + d0.y)));
    atomicMax(mp + 2, f2u(lrelu(s0.z + d0.z)));
    atomicMax(mp + 3, f2u(lrelu(s0.w + d0.w)));
    atomicMax(mp + 4, f2u(lrelu(s1.x + d1.x)));
    atomicMax(mp + 5, f2u(lrelu(s1.y + d1.y)));
    atomicMax(mp + 6, f2u(lrelu(s1.z + d1.z)));
    atomicMax(mp + 7, f2u(lrelu(s1.w + d1.w)));
}

__global__ void init_s1_k()
{
    int i = blockIdx.x * blockDim.x + threadIdx.x;
    if (i >= N_NODES * HEADS) return;
    float m = u2f(d_m1[i]);
    d_s1[i] = __expf(lrelu(d_asrc1[i] + d_adst1[i]) - m);   // self-loop term
}

__global__ void edge_sum1_k(const int* __restrict__ ei)
{
    int e = blockIdx.x * blockDim.x + threadIdx.x;
    if (e >= N_EDGES) return;
    int s = ei[e], d = ei[N_EDGES + e];
#pragma unroll
    for (int h = 0; h < HEADS; h++) {
        int i = d * HEADS + h;
        float v = lrelu(d_asrc1[s * HEADS + h] + d_adst1[i]);
        atomicAdd(&d_s1[i], __expf(v - u2f(d_m1[i])));
    }
}

// init agg1 with the self-loop contribution: agg1[n] = h1[n] * alpha_self(n, h)
__global__ void self_agg1_k()
{
    int t = blockIdx.x * blockDim.x + threadIdx.x;
    if (t >= N_NODES * HC / 4) return;
    int n = t >> 8;                 // 256 float4 per node
    int h = (t & 255) >> 5;         // 32 float4 per head
    int i = n * HEADS + h;
    float m = u2f(d_m1[i]);
    float al = __expf(lrelu(d_asrc1[i] + d_adst1[i]) - m) / (d_s1[i] + 1e-16f);
    float4 v = ((const float4*)d_h1)[t];
    v.x *= al; v.y *= al; v.z *= al; v.w *= al;
    ((float4*)d_agg1)[t] = v;
}

// one block per edge: 256 threads move 1024 floats (float4 each) with vector red
__global__ __launch_bounds__(256) void edge_agg1_k(const int* __restrict__ ei)
{
    __shared__ float alpha[HEADS];
    __shared__ int sh_s, sh_d;
    int e = blockIdx.x;
    if (threadIdx.x == 0) { sh_s = ei[e]; sh_d = ei[N_EDGES + e]; }
    __syncthreads();
    int s = sh_s, d = sh_d;
    if (threadIdx.x < HEADS) {
        int h = threadIdx.x;
        int i = d * HEADS + h;
        float m = u2f(d_m1[i]);
        alpha[h] = __expf(lrelu(d_asrc1[s * HEADS + h] + d_adst1[i]) - m) / (d_s1[i] + 1e-16f);
    }
    __syncthreads();
    int t = threadIdx.x;
    float4 v = *(const float4*)(d_h1 + (size_t)s * HC + t * 4);
    float al = alpha[t >> 5];
    v.x *= al; v.y *= al; v.z *= al; v.w *= al;
    red_add_v4(d_agg1 + (size_t)d * HC + t * 4, v);
}

__global__ void bias_elu1_k(const float* __restrict__ b1)
{
    int t = blockIdx.x * blockDim.x + threadIdx.x;
    if (t >= N_NODES * HC / 4) return;
    float4 v = ((const float4*)d_agg1)[t];
    const float4 b = *(const float4*)(b1 + (t & 255) * 4);
    v.x += b.x; v.y += b.y; v.z += b.z; v.w += b.w;
    v.x = v.x > 0.f ? v.x : expm1f(v.x);
    v.y = v.y > 0.f ? v.y : expm1f(v.y);
    v.z = v.z > 0.f ? v.z : expm1f(v.z);
    v.w = v.w > 0.f ? v.w : expm1f(v.w);
    ((float4*)d_agg1)[t] = v;
}

// ---------------- layer 2 ----------------
__global__ void scores2_k(const float* __restrict__ att_s, const float* __restrict__ att_d)
{
    int w = (blockIdx.x * blockDim.x + threadIdx.x) >> 5;
    int lane = threadIdx.x & 31;
    if (w >= N_NODES) return;
    const float* hp = d_h2 + (size_t)w * OUTD;
    float x0 = hp[lane], x1 = hp[lane + 32];
    float ss = x0 * att_s[lane] + x1 * att_s[lane + 32];
    float sd = x0 * att_d[lane] + x1 * att_d[lane + 32];
#pragma unroll
    for (int o = 16; o; o >>= 1) {
        ss += __shfl_xor_sync(0xFFFFFFFFu, ss, o);
        sd += __shfl_xor_sync(0xFFFFFFFFu, sd, o);
    }
    if (lane == 0) {
        d_asrc2[w] = ss;
        d_adst2[w] = sd;
        d_m2[w] = f2u(lrelu(ss + sd));
    }
}

__global__ void edge_max2_k(const int* __restrict__ ei)
{
    int e = blockIdx.x * blockDim.x + threadIdx.x;
    if (e >= N_EDGES) return;
    int s = ei[e], d = ei[N_EDGES + e];
    atomicMax(&d_m2[d], f2u(lrelu(d_asrc2[s] + d_adst2[d])));
}

__global__ void init_s2_k()
{
    int i = blockIdx.x * blockDim.x + threadIdx.x;
    if (i >= N_NODES) return;
    d_s2[i] = __expf(lrelu(d_asrc2[i] + d_adst2[i]) - u2f(d_m2[i]));
}

__global__ void edge_sum2_k(const int* __restrict__ ei)
{
    int e = blockIdx.x * blockDim.x + threadIdx.x;
    if (e >= N_EDGES) return;
    int s = ei[e], d = ei[N_EDGES + e];
    atomicAdd(&d_s2[d], __expf(lrelu(d_asrc2[s] + d_adst2[d]) - u2f(d_m2[d])));
}

__global__ void self_agg2_k(float* __restrict__ out)
{
    int t = blockIdx.x * blockDim.x + threadIdx.x;
    if (t >= N_NODES * OUTD / 4) return;
    int n = t >> 4;                 // 16 float4 per node
    float m = u2f(d_m2[n]);
    float al = __expf(lrelu(d_asrc2[n] + d_adst2[n]) - m) / (d_s2[n] + 1e-16f);
    float4 v = ((const float4*)d_h2)[t];
    v.x *= al; v.y *= al; v.z *= al; v.w *= al;
    ((float4*)out)[t] = v;
}

// 16 threads per edge
__global__ void edge_agg2_k(const int* __restrict__ ei, float* __restrict__ out)
{
    int t = blockIdx.x * blockDim.x + threadIdx.x;
    int e = t >> 4;
    if (e >= N_EDGES) return;
    int j = (t & 15) * 4;
    int s = ei[e], d = ei[N_EDGES + e];
    float m = u2f(d_m2[d]);
    float al = __expf(lrelu(d_asrc2[s] + d_adst2[d]) - m) / (d_s2[d] + 1e-16f);
    float4 v = *(const float4*)(d_h2 + (size_t)s * OUTD + j);
    v.x *= al; v.y *= al; v.z *= al; v.w *= al;
    red_add_v4(out + (size_t)d * OUTD + j, v);
}

__global__ void logsoftmax_k(float* __restrict__ out, const float* __restrict__ b2)
{
    int w = (blockIdx.x * blockDim.x + threadIdx.x) >> 5;
    int lane = threadIdx.x & 31;
    if (w >= N_NODES) return;
    float* p = out + (size_t)w * OUTD;
    float x0 = p[lane] + b2[lane];
    float x1 = p[lane + 32] + b2[lane + 32];
    float mx = fmaxf(x0, x1);
#pragma unroll
    for (int o = 16; o; o >>= 1) mx = fmaxf(mx, __shfl_xor_sync(0xFFFFFFFFu, mx, o));
    float sm = __expf(x0 - mx) + __expf(x1 - mx);
#pragma unroll
    for (int o = 16; o; o >>= 1) sm += __shfl_xor_sync(0xFFFFFFFFu, sm, o);
    float lse = mx + logf(sm);
    p[lane] = x0 - lse;
    p[lane + 32] = x1 - lse;
}

// ---------------- launch ----------------
extern "C" void kernel_launch(void* const* d_in, const int* in_sizes, int n_in,
                              void* d_out, int out_size)
{
    const float* x   = (const float*)d_in[0];
    const int*   ei  = (const int*)  d_in[1];
    const float* W1  = (const float*)d_in[2];
    const float* as1 = (const float*)d_in[3];
    const float* ad1 = (const float*)d_in[4];
    const float* b1  = (const float*)d_in[5];
    const float* W2  = (const float*)d_in[6];
    const float* as2 = (const float*)d_in[7];
    const float* ad2 = (const float*)d_in[8];
    const float* b2  = (const float*)d_in[9];
    float* out = (float*)d_out;

    float *h1p, *agg1p, *h2p;
    cudaGetSymbolAddress((void**)&h1p,  d_h1);
    cudaGetSymbolAddress((void**)&agg1p, d_agg1);
    cudaGetSymbolAddress((void**)&h2p,  d_h2);

    // ---- layer 1 ----
    {
        dim3 g(HC / 128, (N_NODES + 127) / 128);
        sgemm_n128<<<g, 256>>>(x, W1, h1p, N_NODES, HC, F_IN);
    }
    scores1_k<<<(N_NODES * HEADS * 32 + 255) / 256, 256>>>(as1, ad1);
    edge_max1_k<<<(N_EDGES + 255) / 256, 256>>>(ei);
    init_s1_k<<<(N_NODES * HEADS + 255) / 256, 256>>>();
    edge_sum1_k<<<(N_EDGES + 255) / 256, 256>>>(ei);
    self_agg1_k<<<(N_NODES * HC / 4 + 255) / 256, 256>>>();
    edge_agg1_k<<<N_EDGES, 256>>>(ei);
    bias_elu1_k<<<(N_NODES * HC / 4 + 255) / 256, 256>>>(b1);

    // ---- layer 2 ----
    sgemm_n64<<<(N_NODES + 127) / 128, 256>>>(agg1p, W2, h2p, N_NODES, HC);
    scores2_k<<<(N_NODES * 32 + 255) / 256, 256>>>(as2, ad2);
    edge_max2_k<<<(N_EDGES + 255) / 256, 256>>>(ei);
    init_s2_k<<<(N_NODES + 255) / 256, 256>>>();
    edge_sum2_k<<<(N_EDGES + 255) / 256, 256>>>(ei);
    self_agg2_k<<<(N_NODES * OUTD / 4 + 255) / 256, 256>>>(out);
    edge_agg2_k<<<(N_EDGES * 16 + 255) / 256, 256>>>(ei, out);
    logsoftmax_k<<<(N_NODES * 32 + 255) / 256, 256>>>(out, b2);
}

// round 3
// speedup vs baseline: 1.2570x; 1.2570x over previous
#include <cuda_runtime.h>
#include <cuda_bf16.h>
#include <math.h>

#define N_NODES 30000
#define F_IN    256
#define N_EDGES 300000
#define HEADS   8
#define CDIM    128
#define HC      1024
#define OUTD    64
#define NEG_SLOPE 0.2f

// ---------------- scratch ----------------
__device__ __align__(256) float d_h1  [(size_t)N_NODES * HC];
__device__ __align__(256) float d_agg1[(size_t)N_NODES * HC];
__device__ __align__(256) float d_asrc1[N_NODES * HEADS];
__device__ __align__(256) float d_adst1[N_NODES * HEADS];
__device__ __align__(256) float d_s1  [N_NODES * HEADS];
__device__ __align__(256) float d_ew1 [(size_t)N_EDGES * HEADS];
__device__ __align__(256) float d_h2  [(size_t)N_NODES * OUTD];
__device__ __align__(256) float d_asrc2[N_NODES];
__device__ __align__(256) float d_adst2[N_NODES];
__device__ __align__(256) float d_s2  [N_NODES];
__device__ __align__(256) float d_ew2 [N_EDGES];

// ---------------- helpers ----------------
__device__ __forceinline__ float lrelu(float x) { return x > 0.f ? x : NEG_SLOPE * x; }

__device__ __forceinline__ void red_add_v4(float* dst, float4 v) {
    asm volatile("red.global.add.v4.f32 [%0], {%1,%2,%3,%4};"
                 :: "l"(dst), "f"(v.x), "f"(v.y), "f"(v.z), "f"(v.w) : "memory");
}

// split two fp32 into packed bf16x2 hi and lo (residual) parts
__device__ __forceinline__ void split2(float x, float y, unsigned& h, unsigned& l) {
    __nv_bfloat16 hx = __float2bfloat16(x);
    __nv_bfloat16 hy = __float2bfloat16(y);
    float rx = x - __bfloat162float(hx);
    float ry = y - __bfloat162float(hy);
    __nv_bfloat16 lx = __float2bfloat16(rx);
    __nv_bfloat16 ly = __float2bfloat16(ry);
    h = (unsigned)__bfloat16_as_ushort(hx) | ((unsigned)__bfloat16_as_ushort(hy) << 16);
    l = (unsigned)__bfloat16_as_ushort(lx) | ((unsigned)__bfloat16_as_ushort(ly) << 16);
}

__device__ __forceinline__ void mma_bf16(float* c, const unsigned* a, unsigned b0, unsigned b1) {
    asm volatile("mma.sync.aligned.m16n8k16.row.col.f32.bf16.bf16.f32 "
                 "{%0,%1,%2,%3}, {%4,%5,%6,%7}, {%8,%9}, {%0,%1,%2,%3};\n"
                 : "+f"(c[0]), "+f"(c[1]), "+f"(c[2]), "+f"(c[3])
                 : "r"(a[0]), "r"(a[1]), "r"(a[2]), "r"(a[3]), "r"(b0), "r"(b1));
}

// ---------------- GEMM1: h1[30000,1024] = x[30000,256] @ W1 (bf16-3x mma) ----------------
__global__ __launch_bounds__(256, 1) void gemm1_mma(
    const float* __restrict__ A, const float* __restrict__ B, float* __restrict__ C, int M)
{
    __shared__ unsigned As_h[16][136], As_l[16][136];
    __shared__ unsigned Bs_h[16][136], Bs_l[16][136];
    const int tid = threadIdx.x, lane = tid & 31, wid = tid >> 5;
    const int g = lane >> 2, t = lane & 3;
    const int wm = wid >> 2, wn = wid & 3;     // 2x4 warp grid, warp tile 64x32
    const int by = blockIdx.y, bx = blockIdx.x;
    float acc[4][4][4] = {};

    const int arow = tid >> 1, akoff = (tid & 1) * 16;
    const int gArow = by * 128 + arow;
    const bool aval = gArow < M;
    const float* Ap = A + (size_t)gArow * F_IN + akoff;
    const int bk2 = tid >> 4, bcol = (tid & 15) * 4;
    const float* Bp = B + (size_t)(2 * bk2) * HC + bx * 128 + bcol;

    float4 sA[4], sB0[2], sB1[2];
#pragma unroll
    for (int i = 0; i < 4; i++)
        sA[i] = aval ? *(const float4*)(Ap + 4 * i) : make_float4(0.f, 0.f, 0.f, 0.f);
#pragma unroll
    for (int j = 0; j < 2; j++) {
        sB0[j] = *(const float4*)(Bp + 64 * j);
        sB1[j] = *(const float4*)(Bp + HC + 64 * j);
    }

    for (int kt = 0; kt < F_IN / 32; kt++) {
#pragma unroll
        for (int i = 0; i < 4; i++) {
            int k2 = (akoff >> 1) + 2 * i;
            unsigned h0, l0, h1, l1;
            split2(sA[i].x, sA[i].y, h0, l0);
            split2(sA[i].z, sA[i].w, h1, l1);
            As_h[k2][arow] = h0;     As_l[k2][arow] = l0;
            As_h[k2 + 1][arow] = h1; As_l[k2 + 1][arow] = l1;
        }
#pragma unroll
        for (int j = 0; j < 2; j++) {
            int c = bcol + 64 * j;
            unsigned h, l;
            split2(sB0[j].x, sB1[j].x, h, l); Bs_h[bk2][c] = h;     Bs_l[bk2][c] = l;
            split2(sB0[j].y, sB1[j].y, h, l); Bs_h[bk2][c + 1] = h; Bs_l[bk2][c + 1] = l;
            split2(sB0[j].z, sB1[j].z, h, l); Bs_h[bk2][c + 2] = h; Bs_l[bk2][c + 2] = l;
            split2(sB0[j].w, sB1[j].w, h, l); Bs_h[bk2][c + 3] = h; Bs_l[bk2][c + 3] = l;
        }
        __syncthreads();
        if (kt < F_IN / 32 - 1) {
            const float* Ap2 = Ap + 32 * (kt + 1);
#pragma unroll
            for (int i = 0; i < 4; i++)
                sA[i] = aval ? *(const float4*)(Ap2 + 4 * i) : make_float4(0.f, 0.f, 0.f, 0.f);
            const float* Bp2 = Bp + (size_t)32 * HC * (kt + 1);
#pragma unroll
            for (int j = 0; j < 2; j++) {
                sB0[j] = *(const float4*)(Bp2 + 64 * j);
                sB1[j] = *(const float4*)(Bp2 + HC + 64 * j);
            }
        }
#pragma unroll
        for (int s = 0; s < 2; s++) {
            unsigned ah[4][4], al[4][4];
#pragma unroll
            for (int mt = 0; mt < 4; mt++) {
                int m0 = wm * 64 + mt * 16 + g;
                ah[mt][0] = As_h[s * 8 + t][m0];         al[mt][0] = As_l[s * 8 + t][m0];
                ah[mt][1] = As_h[s * 8 + t][m0 + 8];     al[mt][1] = As_l[s * 8 + t][m0 + 8];
                ah[mt][2] = As_h[s * 8 + t + 4][m0];     al[mt][2] = As_l[s * 8 + t + 4][m0];
                ah[mt][3] = As_h[s * 8 + t + 4][m0 + 8]; al[mt][3] = As_l[s * 8 + t + 4][m0 + 8];
            }
#pragma unroll
            for (int nt = 0; nt < 4; nt++) {
                int n0 = wn * 32 + nt * 8 + g;
                unsigned bh0 = Bs_h[s * 8 + t][n0], bh1 = Bs_h[s * 8 + t + 4][n0];
                unsigned bl0 = Bs_l[s * 8 + t][n0], bl1 = Bs_l[s * 8 + t + 4][n0];
#pragma unroll
                for (int mt = 0; mt < 4; mt++) {
                    mma_bf16(acc[mt][nt], ah[mt], bh0, bh1);
                    mma_bf16(acc[mt][nt], ah[mt], bl0, bl1);
                    mma_bf16(acc[mt][nt], al[mt], bh0, bh1);
                }
            }
        }
        __syncthreads();
    }
#pragma unroll
    for (int mt = 0; mt < 4; mt++) {
        int r0 = by * 128 + wm * 64 + mt * 16 + g;
        int r1 = r0 + 8;
#pragma unroll
        for (int nt = 0; nt < 4; nt++) {
            int col = bx * 128 + wn * 32 + nt * 8 + 2 * t;
            if (r0 < M) *(float2*)(C + (size_t)r0 * HC + col) = make_float2(acc[mt][nt][0], acc[mt][nt][1]);
            if (r1 < M) *(float2*)(C + (size_t)r1 * HC + col) = make_float2(acc[mt][nt][2], acc[mt][nt][3]);
        }
    }
}

// ---------------- GEMM2: h2[30000,64] = elu(agg1 + b1) @ W2 (bf16-3x mma, fused ELU) ----------------
__global__ __launch_bounds__(256, 1) void gemm2_mma(
    const float* __restrict__ A, const float* __restrict__ B, const float* __restrict__ bias,
    float* __restrict__ C, int M)
{
    __shared__ unsigned As_h[16][136], As_l[16][136];
    __shared__ unsigned Bs_h[16][72], Bs_l[16][72];
    const int tid = threadIdx.x, lane = tid & 31, wid = tid >> 5;
    const int g = lane >> 2, t = lane & 3;
    const int wm = wid >> 1, wn = wid & 1;     // 4x2 warp grid, warp tile 32x32
    const int by = blockIdx.x;
    float acc[2][4][4] = {};

    const int arow = tid >> 1, akoff = (tid & 1) * 16;
    const int gArow = by * 128 + arow;
    const bool aval = gArow < M;
    const float* Ap = A + (size_t)gArow * HC + akoff;
    const int bk2 = tid >> 4, bcol = (tid & 15) * 4;
    const float* Bp = B + (size_t)(2 * bk2) * OUTD + bcol;

    float4 sA[4], sB0, sB1;
    {
#pragma unroll
        for (int i = 0; i < 4; i++) {
            float4 v = aval ? *(const float4*)(Ap + 4 * i) : make_float4(0.f, 0.f, 0.f, 0.f);
            float4 b = *(const float4*)(bias + akoff + 4 * i);
            v.x += b.x; v.y += b.y; v.z += b.z; v.w += b.w;
            v.x = v.x > 0.f ? v.x : expm1f(v.x);
            v.y = v.y > 0.f ? v.y : expm1f(v.y);
            v.z = v.z > 0.f ? v.z : expm1f(v.z);
            v.w = v.w > 0.f ? v.w : expm1f(v.w);
            sA[i] = v;
        }
        sB0 = *(const float4*)Bp;
        sB1 = *(const float4*)(Bp + OUTD);
    }

    for (int kt = 0; kt < HC / 32; kt++) {
#pragma unroll
        for (int i = 0; i < 4; i++) {
            int k2 = (akoff >> 1) + 2 * i;
            unsigned h0, l0, h1, l1;
            split2(sA[i].x, sA[i].y, h0, l0);
            split2(sA[i].z, sA[i].w, h1, l1);
            As_h[k2][arow] = h0;     As_l[k2][arow] = l0;
            As_h[k2 + 1][arow] = h1; As_l[k2 + 1][arow] = l1;
        }
        {
            unsigned h, l;
            split2(sB0.x, sB1.x, h, l); Bs_h[bk2][bcol] = h;     Bs_l[bk2][bcol] = l;
            split2(sB0.y, sB1.y, h, l); Bs_h[bk2][bcol + 1] = h; Bs_l[bk2][bcol + 1] = l;
            split2(sB0.z, sB1.z, h, l); Bs_h[bk2][bcol + 2] = h; Bs_l[bk2][bcol + 2] = l;
            split2(sB0.w, sB1.w, h, l); Bs_h[bk2][bcol + 3] = h; Bs_l[bk2][bcol + 3] = l;
        }
        __syncthreads();
        if (kt < HC / 32 - 1) {
            const float* Ap2 = Ap + 32 * (kt + 1);
            const float* bp2 = bias + 32 * (kt + 1) + akoff;
#pragma unroll
            for (int i = 0; i < 4; i++) {
                float4 v = aval ? *(const float4*)(Ap2 + 4 * i) : make_float4(0.f, 0.f, 0.f, 0.f);
                float4 b = *(const float4*)(bp2 + 4 * i);
                v.x += b.x; v.y += b.y; v.z += b.z; v.w += b.w;
                v.x = v.x > 0.f ? v.x : expm1f(v.x);
                v.y = v.y > 0.f ? v.y : expm1f(v.y);
                v.z = v.z > 0.f ? v.z : expm1f(v.z);
                v.w = v.w > 0.f ? v.w : expm1f(v.w);
                sA[i] = v;
            }
            const float* Bp2 = Bp + (size_t)32 * OUTD * (kt + 1);
            sB0 = *(const float4*)Bp2;
            sB1 = *(const float4*)(Bp2 + OUTD);
        }
#pragma unroll
        for (int s = 0; s < 2; s++) {
            unsigned ah[2][4], al[2][4];
#pragma unroll
            for (int mt = 0; mt < 2; mt++) {
                int m0 = wm * 32 + mt * 16 + g;
                ah[mt][0] = As_h[s * 8 + t][m0];         al[mt][0] = As_l[s * 8 + t][m0];
                ah[mt][1] = As_h[s * 8 + t][m0 + 8];     al[mt][1] = As_l[s * 8 + t][m0 + 8];
                ah[mt][2] = As_h[s * 8 + t + 4][m0];     al[mt][2] = As_l[s * 8 + t + 4][m0];
                ah[mt][3] = As_h[s * 8 + t + 4][m0 + 8]; al[mt][3] = As_l[s * 8 + t + 4][m0 + 8];
            }
#pragma unroll
            for (int nt = 0; nt < 4; nt++) {
                int n0 = wn * 32 + nt * 8 + g;
                unsigned bh0 = Bs_h[s * 8 + t][n0], bh1 = Bs_h[s * 8 + t + 4][n0];
                unsigned bl0 = Bs_l[s * 8 + t][n0], bl1 = Bs_l[s * 8 + t + 4][n0];
#pragma unroll
                for (int mt = 0; mt < 2; mt++) {
                    mma_bf16(acc[mt][nt], ah[mt], bh0, bh1);
                    mma_bf16(acc[mt][nt], ah[mt], bl0, bl1);
                    mma_bf16(acc[mt][nt], al[mt], bh0, bh1);
                }
            }
        }
        __syncthreads();
    }
#pragma unroll
    for (int mt = 0; mt < 2; mt++) {
        int r0 = by * 128 + wm * 32 + mt * 16 + g;
        int r1 = r0 + 8;
#pragma unroll
        for (int nt = 0; nt < 4; nt++) {
            int col = wn * 32 + nt * 8 + 2 * t;
            if (r0 < M) *(float2*)(C + (size_t)r0 * OUTD + col) = make_float2(acc[mt][nt][0], acc[mt][nt][1]);
            if (r1 < M) *(float2*)(C + (size_t)r1 * OUTD + col) = make_float2(acc[mt][nt][2], acc[mt][nt][3]);
        }
    }
}

// ---------------- layer-1 scores + self-loop denominator seed ----------------
__global__ void scores1_k(const float* __restrict__ att_s, const float* __restrict__ att_d)
{
    int w = (blockIdx.x * blockDim.x + threadIdx.x) >> 5;
    int lane = threadIdx.x & 31;
    if (w >= N_NODES * HEADS) return;
    int n = w / HEADS, h = w - n * HEADS;
    const float4* hp = (const float4*)(d_h1 + (size_t)n * HC + h * CDIM);
    const float4* as = (const float4*)(att_s + h * CDIM);
    const float4* ad = (const float4*)(att_d + h * CDIM);
    float4 hv = hp[lane], a1 = as[lane], a2 = ad[lane];
    float ss = hv.x * a1.x + hv.y * a1.y + hv.z * a1.z + hv.w * a1.w;
    float sd = hv.x * a2.x + hv.y * a2.y + hv.z * a2.z + hv.w * a2.w;
#pragma unroll
    for (int o = 16; o; o >>= 1) {
        ss += __shfl_xor_sync(0xFFFFFFFFu, ss, o);
        sd += __shfl_xor_sync(0xFFFFFFFFu, sd, o);
    }
    if (lane == 0) {
        d_asrc1[w] = ss;
        d_adst1[w] = sd;
        d_s1[w] = __expf(lrelu(ss + sd));   // self-loop term seeds the denominator
    }
}

// per-edge exp weights (stored) + denominator accumulation
__global__ void edge_sum1_k(const int* __restrict__ ei)
{
    int e = blockIdx.x * blockDim.x + threadIdx.x;
    if (e >= N_EDGES) return;
    int s = ei[e], d = ei[N_EDGES + e];
    float4 as0 = *(const float4*)(d_asrc1 + (size_t)s * HEADS);
    float4 as1 = *(const float4*)(d_asrc1 + (size_t)s * HEADS + 4);
    float4 ad0 = *(const float4*)(d_adst1 + (size_t)d * HEADS);
    float4 ad1 = *(const float4*)(d_adst1 + (size_t)d * HEADS + 4);
    float w[8];
    w[0] = __expf(lrelu(as0.x + ad0.x)); w[1] = __expf(lrelu(as0.y + ad0.y));
    w[2] = __expf(lrelu(as0.z + ad0.z)); w[3] = __expf(lrelu(as0.w + ad0.w));
    w[4] = __expf(lrelu(as1.x + ad1.x)); w[5] = __expf(lrelu(as1.y + ad1.y));
    w[6] = __expf(lrelu(as1.z + ad1.z)); w[7] = __expf(lrelu(as1.w + ad1.w));
    *(float4*)(d_ew1 + (size_t)e * HEADS)     = make_float4(w[0], w[1], w[2], w[3]);
    *(float4*)(d_ew1 + (size_t)e * HEADS + 4) = make_float4(w[4], w[5], w[6], w[7]);
#pragma unroll
    for (int h = 0; h < HEADS; h++) atomicAdd(&d_s1[d * HEADS + h], w[h]);
}

// init agg1 with the self-loop contribution
__global__ void self_agg1_k()
{
    int tidx = blockIdx.x * blockDim.x + threadIdx.x;
    if (tidx >= N_NODES * HC / 4) return;
    int n = tidx >> 8;
    int h = (tidx & 255) >> 5;
    int i = n * HEADS + h;
    float al = __expf(lrelu(d_asrc1[i] + d_adst1[i])) / (d_s1[i] + 1e-16f);
    float4 v = ((const float4*)d_h1)[tidx];
    v.x *= al; v.y *= al; v.z *= al; v.w *= al;
    ((float4*)d_agg1)[tidx] = v;
}

// one block per edge: gather h1[src], scale by alpha, vector red into agg1[dst]
__global__ __launch_bounds__(256) void edge_agg1_k(const int* __restrict__ ei)
{
    __shared__ float alpha[HEADS];
    __shared__ int sh_s, sh_d;
    int e = blockIdx.x;
    if (threadIdx.x == 0) { sh_s = ei[e]; sh_d = ei[N_EDGES + e]; }
    __syncthreads();
    int s = sh_s, d = sh_d;
    if (threadIdx.x < HEADS) {
        int h = threadIdx.x;
        alpha[h] = d_ew1[(size_t)e * HEADS + h] / (d_s1[d * HEADS + h] + 1e-16f);
    }
    __syncthreads();
    int tx = threadIdx.x;
    float4 v = *(const float4*)(d_h1 + (size_t)s * HC + tx * 4);
    float al = alpha[tx >> 5];
    v.x *= al; v.y *= al; v.z *= al; v.w *= al;
    red_add_v4(d_agg1 + (size_t)d * HC + tx * 4, v);
}

// ---------------- layer 2 ----------------
__global__ void scores2_k(const float* __restrict__ att_s, const float* __restrict__ att_d)
{
    int w = (blockIdx.x * blockDim.x + threadIdx.x) >> 5;
    int lane = threadIdx.x & 31;
    if (w >= N_NODES) return;
    const float* hp = d_h2 + (size_t)w * OUTD;
    float x0 = hp[lane], x1 = hp[lane + 32];
    float ss = x0 * att_s[lane] + x1 * att_s[lane + 32];
    float sd = x0 * att_d[lane] + x1 * att_d[lane + 32];
#pragma unroll
    for (int o = 16; o; o >>= 1) {
        ss += __shfl_xor_sync(0xFFFFFFFFu, ss, o);
        sd += __shfl_xor_sync(0xFFFFFFFFu, sd, o);
    }
    if (lane == 0) {
        d_asrc2[w] = ss;
        d_adst2[w] = sd;
        d_s2[w] = __expf(lrelu(ss + sd));
    }
}

__global__ void edge_sum2_k(const int* __restrict__ ei)
{
    int e = blockIdx.x * blockDim.x + threadIdx.x;
    if (e >= N_EDGES) return;
    int s = ei[e], d = ei[N_EDGES + e];
    float w = __expf(lrelu(d_asrc2[s] + d_adst2[d]));
    d_ew2[e] = w;
    atomicAdd(&d_s2[d], w);
}

__global__ void self_agg2_k(float* __restrict__ out)
{
    int tidx = blockIdx.x * blockDim.x + threadIdx.x;
    if (tidx >= N_NODES * OUTD / 4) return;
    int n = tidx >> 4;
    float al = __expf(lrelu(d_asrc2[n] + d_adst2[n])) / (d_s2[n] + 1e-16f);
    float4 v = ((const float4*)d_h2)[tidx];
    v.x *= al; v.y *= al; v.z *= al; v.w *= al;
    ((float4*)out)[tidx] = v;
}

__global__ void edge_agg2_k(const int* __restrict__ ei, float* __restrict__ out)
{
    int tidx = blockIdx.x * blockDim.x + threadIdx.x;
    int e = tidx >> 4;
    if (e >= N_EDGES) return;
    int j = (tidx & 15) * 4;
    int s = ei[e], d = ei[N_EDGES + e];
    float al = d_ew2[e] / (d_s2[d] + 1e-16f);
    float4 v = *(const float4*)(d_h2 + (size_t)s * OUTD + j);
    v.x *= al; v.y *= al; v.z *= al; v.w *= al;
    red_add_v4(out + (size_t)d * OUTD + j, v);
}

__global__ void logsoftmax_k(float* __restrict__ out, const float* __restrict__ b2)
{
    int w = (blockIdx.x * blockDim.x + threadIdx.x) >> 5;
    int lane = threadIdx.x & 31;
    if (w >= N_NODES) return;
    float* p = out + (size_t)w * OUTD;
    float x0 = p[lane] + b2[lane];
    float x1 = p[lane + 32] + b2[lane + 32];
    float mx = fmaxf(x0, x1);
#pragma unroll
    for (int o = 16; o; o >>= 1) mx = fmaxf(mx, __shfl_xor_sync(0xFFFFFFFFu, mx, o));
    float sm = __expf(x0 - mx) + __expf(x1 - mx);
#pragma unroll
    for (int o = 16; o; o >>= 1) sm += __shfl_xor_sync(0xFFFFFFFFu, sm, o);
    float lse = mx + logf(sm);
    p[lane] = x0 - lse;
    p[lane + 32] = x1 - lse;
}

// ---------------- launch ----------------
extern "C" void kernel_launch(void* const* d_in, const int* in_sizes, int n_in,
                              void* d_out, int out_size)
{
    const float* x   = (const float*)d_in[0];
    const int*   ei  = (const int*)  d_in[1];
    const float* W1  = (const float*)d_in[2];
    const float* as1 = (const float*)d_in[3];
    const float* ad1 = (const float*)d_in[4];
    const float* b1  = (const float*)d_in[5];
    const float* W2  = (const float*)d_in[6];
    const float* as2 = (const float*)d_in[7];
    const float* ad2 = (const float*)d_in[8];
    const float* b2  = (const float*)d_in[9];
    float* out = (float*)d_out;

    float *h1p, *agg1p, *h2p;
    cudaGetSymbolAddress((void**)&h1p,  d_h1);
    cudaGetSymbolAddress((void**)&agg1p, d_agg1);
    cudaGetSymbolAddress((void**)&h2p,  d_h2);

    // ---- layer 1 ----
    {
        dim3 g(HC / 128, (N_NODES + 127) / 128);
        gemm1_mma<<<g, 256>>>(x, W1, h1p, N_NODES);
    }
    scores1_k<<<(N_NODES * HEADS * 32 + 255) / 256, 256>>>(as1, ad1);
    edge_sum1_k<<<(N_EDGES + 255) / 256, 256>>>(ei);
    self_agg1_k<<<(N_NODES * HC / 4 + 255) / 256, 256>>>();
    edge_agg1_k<<<N_EDGES, 256>>>(ei);

    // ---- layer 2 (bias+ELU fused into GEMM2 A-load) ----
    gemm2_mma<<<(N_NODES + 127) / 128, 256>>>(agg1p, W2, b1, h2p, N_NODES);
    scores2_k<<<(N_NODES * 32 + 255) / 256, 256>>>(as2, ad2);
    edge_sum2_k<<<(N_EDGES + 255) / 256, 256>>>(ei);
    self_agg2_k<<<(N_NODES * OUTD / 4 + 255) / 256, 256>>>(out);
    edge_agg2_k<<<(N_EDGES * 16 + 255) / 256, 256>>>(ei, out);
    logsoftmax_k<<<(N_NODES * 32 + 255) / 256, 256>>>(out, b2);
}

// round 7
// speedup vs baseline: 2.1480x; 1.7088x over previous
#include <cuda_runtime.h>
#include <cuda_bf16.h>
#include <math.h>

#define N_NODES 30000
#define F_IN    256
#define N_EDGES 300000
#define HEADS   8
#define CDIM    128
#define HC      1024
#define OUTD    64
#define NEG_SLOPE 0.2f

// ---------------- scratch ----------------
__device__ __align__(256) float d_h1  [(size_t)N_NODES * HC];
__device__ __align__(256) float d_agg1[(size_t)N_NODES * HC];
__device__ __align__(256) float d_asrc1[N_NODES * HEADS];
__device__ __align__(256) float d_adst1[N_NODES * HEADS];
__device__ __align__(256) float d_h2  [(size_t)N_NODES * OUTD];
__device__ __align__(256) float d_asrc2[N_NODES];
__device__ __align__(256) float d_adst2[N_NODES];
__device__ __align__(256) int   d_deg   [N_NODES];
__device__ __align__(256) int   d_rowptr[N_NODES + 1];
__device__ __align__(256) int   d_cursor[N_NODES];
__device__ __align__(256) int   d_csr_src[N_EDGES];

// ---------------- helpers ----------------
__device__ __forceinline__ float lrelu(float x) { return x > 0.f ? x : NEG_SLOPE * x; }

__device__ __forceinline__ void split2(float x, float y, unsigned& h, unsigned& l) {
    __nv_bfloat16 hx = __float2bfloat16(x);
    __nv_bfloat16 hy = __float2bfloat16(y);
    float rx = x - __bfloat162float(hx);
    float ry = y - __bfloat162float(hy);
    __nv_bfloat16 lx = __float2bfloat16(rx);
    __nv_bfloat16 ly = __float2bfloat16(ry);
    h = (unsigned)__bfloat16_as_ushort(hx) | ((unsigned)__bfloat16_as_ushort(hy) << 16);
    l = (unsigned)__bfloat16_as_ushort(lx) | ((unsigned)__bfloat16_as_ushort(ly) << 16);
}

__device__ __forceinline__ void mma_bf16(float* c, const unsigned* a, unsigned b0, unsigned b1) {
    asm volatile("mma.sync.aligned.m16n8k16.row.col.f32.bf16.bf16.f32 "
                 "{%0,%1,%2,%3}, {%4,%5,%6,%7}, {%8,%9}, {%0,%1,%2,%3};\n"
                 : "+f"(c[0]), "+f"(c[1]), "+f"(c[2]), "+f"(c[3])
                 : "r"(a[0]), "r"(a[1]), "r"(a[2]), "r"(a[3]), "r"(b0), "r"(b1));
}

// ---------------- CSR build ----------------
__global__ void zero_deg_k()
{
    int i = blockIdx.x * blockDim.x + threadIdx.x;
    if (i < N_NODES) d_deg[i] = 0;
}

__global__ void hist_k(const int* __restrict__ ei)
{
    int e = blockIdx.x * blockDim.x + threadIdx.x;
    if (e >= N_EDGES) return;
    atomicAdd(&d_deg[ei[N_EDGES + e]], 1);
}

__global__ __launch_bounds__(1024) void scan_k()
{
    __shared__ int sh[1024];
    const int tid = threadIdx.x;
    int run = 0;
    for (int base = 0; base < N_NODES; base += 1024) {
        int i = base + tid;
        int v = (i < N_NODES) ? d_deg[i] : 0;
        sh[tid] = v;
        __syncthreads();
#pragma unroll
        for (int off = 1; off < 1024; off <<= 1) {
            int y = (tid >= off) ? sh[tid - off] : 0;
            __syncthreads();
            sh[tid] += y;
            __syncthreads();
        }
        int incl = sh[tid];
        int total = sh[1023];
        int excl = incl - v;
        if (i < N_NODES) {
            d_rowptr[i] = run + excl;
            d_cursor[i] = run + excl;
        }
        run += total;
        __syncthreads();
    }
    if (tid == 0) d_rowptr[N_NODES] = run;
}

__global__ void scatter_k(const int* __restrict__ ei)
{
    int e = blockIdx.x * blockDim.x + threadIdx.x;
    if (e >= N_EDGES) return;
    int s = ei[e], d = ei[N_EDGES + e];
    int p = atomicAdd(&d_cursor[d], 1);
    d_csr_src[p] = s;
}

// ---------------- GEMM1 + fused attention scores ----------------
// h1[30000,1024] = x @ W1;  asrc1/adst1[n,h] = h1[n,h,:].att  (block = 128 rows x head bx)
__global__ __launch_bounds__(256, 1) void gemm1_mma(
    const float* __restrict__ A, const float* __restrict__ B,
    const float* __restrict__ att_s, const float* __restrict__ att_d,
    float* __restrict__ C, int M)
{
    __shared__ unsigned As_h[16][136], As_l[16][136];
    __shared__ unsigned Bs_h[16][136], Bs_l[16][136];
    __shared__ float sred[4][128][2];
    const int tid = threadIdx.x, lane = tid & 31, wid = tid >> 5;
    const int g = lane >> 2, t = lane & 3;
    const int wm = wid >> 2, wn = wid & 3;     // 2x4 warps, warp tile 64x32
    const int by = blockIdx.y, bx = blockIdx.x;
    float acc[4][4][4] = {};

    const int arow = tid >> 1, akoff = (tid & 1) * 16;
    const int gArow = by * 128 + arow;
    const bool aval = gArow < M;
    const float* Ap = A + (size_t)gArow * F_IN + akoff;
    const int bk2 = tid >> 4, bcol = (tid & 15) * 4;
    const float* Bp = B + (size_t)(2 * bk2) * HC + bx * 128 + bcol;

    float4 sA[4], sB0[2], sB1[2];
#pragma unroll
    for (int i = 0; i < 4; i++)
        sA[i] = aval ? *(const float4*)(Ap + 4 * i) : make_float4(0.f, 0.f, 0.f, 0.f);
#pragma unroll
    for (int j = 0; j < 2; j++) {
        sB0[j] = *(const float4*)(Bp + 64 * j);
        sB1[j] = *(const float4*)(Bp + HC + 64 * j);
    }

    for (int kt = 0; kt < F_IN / 32; kt++) {
#pragma unroll
        for (int i = 0; i < 4; i++) {
            int k2 = (akoff >> 1) + 2 * i;
            unsigned h0, l0, h1, l1;
            split2(sA[i].x, sA[i].y, h0, l0);
            split2(sA[i].z, sA[i].w, h1, l1);
            As_h[k2][arow] = h0;     As_l[k2][arow] = l0;
            As_h[k2 + 1][arow] = h1; As_l[k2 + 1][arow] = l1;
        }
#pragma unroll
        for (int j = 0; j < 2; j++) {
            int c = bcol + 64 * j;
            unsigned h, l;
            split2(sB0[j].x, sB1[j].x, h, l); Bs_h[bk2][c] = h;     Bs_l[bk2][c] = l;
            split2(sB0[j].y, sB1[j].y, h, l); Bs_h[bk2][c + 1] = h; Bs_l[bk2][c + 1] = l;
            split2(sB0[j].z, sB1[j].z, h, l); Bs_h[bk2][c + 2] = h; Bs_l[bk2][c + 2] = l;
            split2(sB0[j].w, sB1[j].w, h, l); Bs_h[bk2][c + 3] = h; Bs_l[bk2][c + 3] = l;
        }
        __syncthreads();
        if (kt < F_IN / 32 - 1) {
            const float* Ap2 = Ap + 32 * (kt + 1);
#pragma unroll
            for (int i = 0; i < 4; i++)
                sA[i] = aval ? *(const float4*)(Ap2 + 4 * i) : make_float4(0.f, 0.f, 0.f, 0.f);
            const float* Bp2 = Bp + (size_t)32 * HC * (kt + 1);
#pragma unroll
            for (int j = 0; j < 2; j++) {
                sB0[j] = *(const float4*)(Bp2 + 64 * j);
                sB1[j] = *(const float4*)(Bp2 + HC + 64 * j);
            }
        }
#pragma unroll
        for (int s = 0; s < 2; s++) {
            unsigned ah[4][4], al[4][4];
#pragma unroll
            for (int mt = 0; mt < 4; mt++) {
                int m0 = wm * 64 + mt * 16 + g;
                ah[mt][0] = As_h[s * 8 + t][m0];         al[mt][0] = As_l[s * 8 + t][m0];
                ah[mt][1] = As_h[s * 8 + t][m0 + 8];     al[mt][1] = As_l[s * 8 + t][m0 + 8];
                ah[mt][2] = As_h[s * 8 + t + 4][m0];     al[mt][2] = As_l[s * 8 + t + 4][m0];
                ah[mt][3] = As_h[s * 8 + t + 4][m0 + 8]; al[mt][3] = As_l[s * 8 + t + 4][m0 + 8];
            }
#pragma unroll
            for (int nt = 0; nt < 4; nt++) {
                int n0 = wn * 32 + nt * 8 + g;
                unsigned bh0 = Bs_h[s * 8 + t][n0], bh1 = Bs_h[s * 8 + t + 4][n0];
                unsigned bl0 = Bs_l[s * 8 + t][n0], bl1 = Bs_l[s * 8 + t + 4][n0];
#pragma unroll
                for (int mt = 0; mt < 4; mt++) {
                    mma_bf16(acc[mt][nt], ah[mt], bh0, bh1);
                    mma_bf16(acc[mt][nt], ah[mt], bl0, bl1);
                    mma_bf16(acc[mt][nt], al[mt], bh0, bh1);
                }
            }
        }
        __syncthreads();
    }
    // store C tile
#pragma unroll
    for (int mt = 0; mt < 4; mt++) {
        int r0 = by * 128 + wm * 64 + mt * 16 + g;
        int r1 = r0 + 8;
#pragma unroll
        for (int nt = 0; nt < 4; nt++) {
            int col = bx * 128 + wn * 32 + nt * 8 + 2 * t;
            if (r0 < M) *(float2*)(C + (size_t)r0 * HC + col) = make_float2(acc[mt][nt][0], acc[mt][nt][1]);
            if (r1 < M) *(float2*)(C + (size_t)r1 * HC + col) = make_float2(acc[mt][nt][2], acc[mt][nt][3]);
        }
    }
    // fused score epilogue: ss/sd per row for head bx
    const float* as = att_s + bx * CDIM;
    const float* ad = att_d + bx * CDIM;
    float pss[4][2] = {}, psd[4][2] = {};
#pragma unroll
    for (int nt = 0; nt < 4; nt++) {
        int col = wn * 32 + nt * 8 + 2 * t;
        float a0 = as[col], a1 = as[col + 1];
        float e0 = ad[col], e1 = ad[col + 1];
#pragma unroll
        for (int mt = 0; mt < 4; mt++) {
            pss[mt][0] += acc[mt][nt][0] * a0 + acc[mt][nt][1] * a1;
            pss[mt][1] += acc[mt][nt][2] * a0 + acc[mt][nt][3] * a1;
            psd[mt][0] += acc[mt][nt][0] * e0 + acc[mt][nt][1] * e1;
            psd[mt][1] += acc[mt][nt][2] * e0 + acc[mt][nt][3] * e1;
        }
    }
#pragma unroll
    for (int o = 1; o <= 2; o <<= 1)
#pragma unroll
        for (int mt = 0; mt < 4; mt++)
#pragma unroll
            for (int rh = 0; rh < 2; rh++) {
                pss[mt][rh] += __shfl_xor_sync(0xFFFFFFFFu, pss[mt][rh], o);
                psd[mt][rh] += __shfl_xor_sync(0xFFFFFFFFu, psd[mt][rh], o);
            }
    if (t == 0) {
#pragma unroll
        for (int mt = 0; mt < 4; mt++)
#pragma unroll
            for (int rh = 0; rh < 2; rh++) {
                int rl = wm * 64 + mt * 16 + rh * 8 + g;
                sred[wn][rl][0] = pss[mt][rh];
                sred[wn][rl][1] = psd[mt][rh];
            }
    }
    __syncthreads();
    {
        int rl = tid >> 1, which = tid & 1;
        float sum = sred[0][rl][which] + sred[1][rl][which] + sred[2][rl][which] + sred[3][rl][which];
        int row = by * 128 + rl;
        if (row < M) {
            if (which) d_adst1[row * HEADS + bx] = sum;
            else       d_asrc1[row * HEADS + bx] = sum;
        }
    }
}

// ---------------- layer-1 one-pass aggregation (CSR) ----------------
// block = node, warp = head; agg1[n,h,:] = (w_self*h1[n] + sum_e w_e*h1[src_e]) / (w_self + sum w_e)
__global__ __launch_bounds__(256) void agg1_k()
{
    int n = blockIdx.x;
    int h = threadIdx.x >> 5, lane = threadIdx.x & 31;
    float adst = d_adst1[n * HEADS + h];
    float ws = __expf(lrelu(d_asrc1[n * HEADS + h] + adst));
    float4 v = *(const float4*)(d_h1 + (size_t)n * HC + h * CDIM + lane * 4);
    float4 acc = make_float4(ws * v.x, ws * v.y, ws * v.z, ws * v.w);
    float denom = ws;
    int beg = d_rowptr[n], end = d_rowptr[n + 1];
    for (int j = beg; j < end; j++) {
        int s = __ldg(&d_csr_src[j]);
        float w = __expf(lrelu(__ldg(&d_asrc1[s * HEADS + h]) + adst));
        float4 u = *(const float4*)(d_h1 + (size_t)s * HC + h * CDIM + lane * 4);
        acc.x += w * u.x; acc.y += w * u.y; acc.z += w * u.z; acc.w += w * u.w;
        denom += w;
    }
    float inv = 1.f / (denom + 1e-16f);
    acc.x *= inv; acc.y *= inv; acc.z *= inv; acc.w *= inv;
    *(float4*)(d_agg1 + (size_t)n * HC + h * CDIM + lane * 4) = acc;
}

// ---------------- GEMM2 (fused bias+ELU on A) + fused attention scores ----------------
__global__ __launch_bounds__(256, 1) void gemm2_mma(
    const float* __restrict__ A, const float* __restrict__ B, const float* __restrict__ bias,
    const float* __restrict__ att_s, const float* __restrict__ att_d,
    float* __restrict__ C, int M)
{
    __shared__ unsigned As_h[16][136], As_l[16][136];
    __shared__ unsigned Bs_h[16][72], Bs_l[16][72];
    __shared__ float sred[2][128][2];
    const int tid = threadIdx.x, lane = tid & 31, wid = tid >> 5;
    const int g = lane >> 2, t = lane & 3;
    const int wm = wid >> 1, wn = wid & 1;     // 4x2 warps, warp tile 32x32
    const int by = blockIdx.x;
    float acc[2][4][4] = {};

    const int arow = tid >> 1, akoff = (tid & 1) * 16;
    const int gArow = by * 128 + arow;
    const bool aval = gArow < M;
    const float* Ap = A + (size_t)gArow * HC + akoff;
    const int bk2 = tid >> 4, bcol = (tid & 15) * 4;
    const float* Bp = B + (size_t)(2 * bk2) * OUTD + bcol;

    float4 sA[4], sB0, sB1;
    {
#pragma unroll
        for (int i = 0; i < 4; i++) {
            float4 v = aval ? *(const float4*)(Ap + 4 * i) : make_float4(0.f, 0.f, 0.f, 0.f);
            float4 b = *(const float4*)(bias + akoff + 4 * i);
            v.x += b.x; v.y += b.y; v.z += b.z; v.w += b.w;
            v.x = v.x > 0.f ? v.x : expm1f(v.x);
            v.y = v.y > 0.f ? v.y : expm1f(v.y);
            v.z = v.z > 0.f ? v.z : expm1f(v.z);
            v.w = v.w > 0.f ? v.w : expm1f(v.w);
            sA[i] = v;
        }
        sB0 = *(const float4*)Bp;
        sB1 = *(const float4*)(Bp + OUTD);
    }

    for (int kt = 0; kt < HC / 32; kt++) {
#pragma unroll
        for (int i = 0; i < 4; i++) {
            int k2 = (akoff >> 1) + 2 * i;
            unsigned h0, l0, h1, l1;
            split2(sA[i].x, sA[i].y, h0, l0);
            split2(sA[i].z, sA[i].w, h1, l1);
            As_h[k2][arow] = h0;     As_l[k2][arow] = l0;
            As_h[k2 + 1][arow] = h1; As_l[k2 + 1][arow] = l1;
        }
        {
            unsigned h, l;
            split2(sB0.x, sB1.x, h, l); Bs_h[bk2][bcol] = h;     Bs_l[bk2][bcol] = l;
            split2(sB0.y, sB1.y, h, l); Bs_h[bk2][bcol + 1] = h; Bs_l[bk2][bcol + 1] = l;
            split2(sB0.z, sB1.z, h, l); Bs_h[bk2][bcol + 2] = h; Bs_l[bk2][bcol + 2] = l;
            split2(sB0.w, sB1.w, h, l); Bs_h[bk2][bcol + 3] = h; Bs_l[bk2][bcol + 3] = l;
        }
        __syncthreads();
        if (kt < HC / 32 - 1) {
            const float* Ap2 = Ap + 32 * (kt + 1);
            const float* bp2 = bias + 32 * (kt + 1) + akoff;
#pragma unroll
            for (int i = 0; i < 4; i++) {
                float4 v = aval ? *(const float4*)(Ap2 + 4 * i) : make_float4(0.f, 0.f, 0.f, 0.f);
                float4 b = *(const float4*)(bp2 + 4 * i);
                v.x += b.x; v.y += b.y; v.z += b.z; v.w += b.w;
                v.x = v.x > 0.f ? v.x : expm1f(v.x);
                v.y = v.y > 0.f ? v.y : expm1f(v.y);
                v.z = v.z > 0.f ? v.z : expm1f(v.z);
                v.w = v.w > 0.f ? v.w : expm1f(v.w);
                sA[i] = v;
            }
            const float* Bp2 = Bp + (size_t)32 * OUTD * (kt + 1);
            sB0 = *(const float4*)Bp2;
            sB1 = *(const float4*)(Bp2 + OUTD);
        }
#pragma unroll
        for (int s = 0; s < 2; s++) {
            unsigned ah[2][4], al[2][4];
#pragma unroll
            for (int mt = 0; mt < 2; mt++) {
                int m0 = wm * 32 + mt * 16 + g;
                ah[mt][0] = As_h[s * 8 + t][m0];         al[mt][0] = As_l[s * 8 + t][m0];
                ah[mt][1] = As_h[s * 8 + t][m0 + 8];     al[mt][1] = As_l[s * 8 + t][m0 + 8];
                ah[mt][2] = As_h[s * 8 + t + 4][m0];     al[mt][2] = As_l[s * 8 + t + 4][m0];
                ah[mt][3] = As_h[s * 8 + t + 4][m0 + 8]; al[mt][3] = As_l[s * 8 + t + 4][m0 + 8];
            }
#pragma unroll
            for (int nt = 0; nt < 4; nt++) {
                int n0 = wn * 32 + nt * 8 + g;
                unsigned bh0 = Bs_h[s * 8 + t][n0], bh1 = Bs_h[s * 8 + t + 4][n0];
                unsigned bl0 = Bs_l[s * 8 + t][n0], bl1 = Bs_l[s * 8 + t + 4][n0];
#pragma unroll
                for (int mt = 0; mt < 2; mt++) {
                    mma_bf16(acc[mt][nt], ah[mt], bh0, bh1);
                    mma_bf16(acc[mt][nt], ah[mt], bl0, bl1);
                    mma_bf16(acc[mt][nt], al[mt], bh0, bh1);
                }
            }
        }
        __syncthreads();
    }
#pragma unroll
    for (int mt = 0; mt < 2; mt++) {
        int r0 = by * 128 + wm * 32 + mt * 16 + g;
        int r1 = r0 + 8;
#pragma unroll
        for (int nt = 0; nt < 4; nt++) {
            int col = wn * 32 + nt * 8 + 2 * t;
            if (r0 < M) *(float2*)(C + (size_t)r0 * OUTD + col) = make_float2(acc[mt][nt][0], acc[mt][nt][1]);
            if (r1 < M) *(float2*)(C + (size_t)r1 * OUTD + col) = make_float2(acc[mt][nt][2], acc[mt][nt][3]);
        }
    }
    // fused score epilogue
    float pss[2][2] = {}, psd[2][2] = {};
#pragma unroll
    for (int nt = 0; nt < 4; nt++) {
        int col = wn * 32 + nt * 8 + 2 * t;
        float a0 = att_s[col], a1 = att_s[col + 1];
        float e0 = att_d[col], e1 = att_d[col + 1];
#pragma unroll
        for (int mt = 0; mt < 2; mt++) {
            pss[mt][0] += acc[mt][nt][0] * a0 + acc[mt][nt][1] * a1;
            pss[mt][1] += acc[mt][nt][2] * a0 + acc[mt][nt][3] * a1;
            psd[mt][0] += acc[mt][nt][0] * e0 + acc[mt][nt][1] * e1;
            psd[mt][1] += acc[mt][nt][2] * e0 + acc[mt][nt][3] * e1;
        }
    }
#pragma unroll
    for (int o = 1; o <= 2; o <<= 1)
#pragma unroll
        for (int mt = 0; mt < 2; mt++)
#pragma unroll
            for (int rh = 0; rh < 2; rh++) {
                pss[mt][rh] += __shfl_xor_sync(0xFFFFFFFFu, pss[mt][rh], o);
                psd[mt][rh] += __shfl_xor_sync(0xFFFFFFFFu, psd[mt][rh], o);
            }
    if (t == 0) {
#pragma unroll
        for (int mt = 0; mt < 2; mt++)
#pragma unroll
            for (int rh = 0; rh < 2; rh++) {
                int rl = wm * 32 + mt * 16 + rh * 8 + g;
                sred[wn][rl][0] = pss[mt][rh];
                sred[wn][rl][1] = psd[mt][rh];
            }
    }
    __syncthreads();
    {
        int rl = tid >> 1, which = tid & 1;
        float sum = sred[0][rl][which] + sred[1][rl][which];
        int row = by * 128 + rl;
        if (row < M) {
            if (which) d_adst2[row] = sum;
            else       d_asrc2[row] = sum;
        }
    }
}

// ---------------- layer-2 one-pass aggregation + bias + log_softmax ----------------
__global__ __launch_bounds__(256) void agg2_k(float* __restrict__ out, const float* __restrict__ b2)
{
    int n = blockIdx.x * 8 + (threadIdx.x >> 5);
    int lane = threadIdx.x & 31;
    if (n >= N_NODES) return;
    float adst = d_adst2[n];
    float ws = __expf(lrelu(d_asrc2[n] + adst));
    const float* hp = d_h2 + (size_t)n * OUTD;
    float acc0 = ws * hp[lane], acc1 = ws * hp[lane + 32];
    float denom = ws;
    int beg = d_rowptr[n], end = d_rowptr[n + 1];
    for (int j = beg; j < end; j++) {
        int s = __ldg(&d_csr_src[j]);
        float w = __expf(lrelu(__ldg(&d_asrc2[s]) + adst));
        const float* sp = d_h2 + (size_t)s * OUTD;
        acc0 += w * sp[lane];
        acc1 += w * sp[lane + 32];
        denom += w;
    }
    float inv = 1.f / (denom + 1e-16f);
    float x0 = acc0 * inv + b2[lane];
    float x1 = acc1 * inv + b2[lane + 32];
    float mx = fmaxf(x0, x1);
#pragma unroll
    for (int o = 16; o; o >>= 1) mx = fmaxf(mx, __shfl_xor_sync(0xFFFFFFFFu, mx, o));
    float sm = __expf(x0 - mx) + __expf(x1 - mx);
#pragma unroll
    for (int o = 16; o; o >>= 1) sm += __shfl_xor_sync(0xFFFFFFFFu, sm, o);
    float lse = mx + logf(sm);
    out[(size_t)n * OUTD + lane] = x0 - lse;
    out[(size_t)n * OUTD + lane + 32] = x1 - lse;
}

// ---------------- launch ----------------
extern "C" void kernel_launch(void* const* d_in, const int* in_sizes, int n_in,
                              void* d_out, int out_size)
{
    const float* x   = (const float*)d_in[0];
    const int*   ei  = (const int*)  d_in[1];
    const float* W1  = (const float*)d_in[2];
    const float* as1 = (const float*)d_in[3];
    const float* ad1 = (const float*)d_in[4];
    const float* b1  = (const float*)d_in[5];
    const float* W2  = (const float*)d_in[6];
    const float* as2 = (const float*)d_in[7];
    const float* ad2 = (const float*)d_in[8];
    const float* b2  = (const float*)d_in[9];
    float* out = (float*)d_out;

    float *h1p, *agg1p, *h2p;
    cudaGetSymbolAddress((void**)&h1p,   d_h1);
    cudaGetSymbolAddress((void**)&agg1p, d_agg1);
    cudaGetSymbolAddress((void**)&h2p,   d_h2);

    // CSR build (int work, runs before the aggregations need it)
    zero_deg_k<<<(N_NODES + 255) / 256, 256>>>();
    hist_k<<<(N_EDGES + 255) / 256, 256>>>(ei);
    scan_k<<<1, 1024>>>();
    scatter_k<<<(N_EDGES + 255) / 256, 256>>>(ei);

    // layer 1
    {
        dim3 g(HC / 128, (N_NODES + 127) / 128);
        gemm1_mma<<<g, 256>>>(x, W1, as1, ad1, h1p, N_NODES);
    }
    agg1_k<<<N_NODES, 256>>>();

    // layer 2
    gemm2_mma<<<(N_NODES + 127) / 128, 256>>>(agg1p, W2, b1, as2, ad2, h2p, N_NODES);
    agg2_k<<<(N_NODES + 7) / 8, 256>>>(out, b2);
}

// round 8
// speedup vs baseline: 2.3313x; 1.0853x over previous
#include <cuda_runtime.h>
#include <cuda_bf16.h>
#include <cuda_fp16.h>
#include <math.h>

#define N_NODES 30000
#define F_IN    256
#define N_EDGES 300000
#define HEADS   8
#define CDIM    128
#define HC      1024
#define OUTD    64
#define NEG_SLOPE 0.2f

// ---------------- scratch ----------------
__device__ __align__(256) __half d_h1h [(size_t)N_NODES * HC];   // 61.4 MB, L2-resident
__device__ __align__(256) float  d_agg1[(size_t)N_NODES * HC];   // 122.9 MB
__device__ __align__(256) float  d_asrc1[N_NODES * HEADS];
__device__ __align__(256) float  d_adst1[N_NODES * HEADS];
__device__ __align__(256) float  d_h2  [(size_t)N_NODES * OUTD];
__device__ __align__(256) float  d_asrc2[N_NODES];
__device__ __align__(256) float  d_adst2[N_NODES];
__device__ __align__(256) int    d_deg   [N_NODES];
__device__ __align__(256) int    d_rowptr[N_NODES + 1];
__device__ __align__(256) int    d_cursor[N_NODES];
__device__ __align__(256) int    d_csr_src[N_EDGES];

// ---------------- helpers ----------------
__device__ __forceinline__ float lrelu(float x) { return x > 0.f ? x : NEG_SLOPE * x; }

__device__ __forceinline__ void split2(float x, float y, unsigned& h, unsigned& l) {
    __nv_bfloat16 hx = __float2bfloat16(x);
    __nv_bfloat16 hy = __float2bfloat16(y);
    float rx = x - __bfloat162float(hx);
    float ry = y - __bfloat162float(hy);
    __nv_bfloat16 lx = __float2bfloat16(rx);
    __nv_bfloat16 ly = __float2bfloat16(ry);
    h = (unsigned)__bfloat16_as_ushort(hx) | ((unsigned)__bfloat16_as_ushort(hy) << 16);
    l = (unsigned)__bfloat16_as_ushort(lx) | ((unsigned)__bfloat16_as_ushort(ly) << 16);
}

__device__ __forceinline__ void mma_bf16(float* c, const unsigned* a, unsigned b0, unsigned b1) {
    asm volatile("mma.sync.aligned.m16n8k16.row.col.f32.bf16.bf16.f32 "
                 "{%0,%1,%2,%3}, {%4,%5,%6,%7}, {%8,%9}, {%0,%1,%2,%3};\n"
                 : "+f"(c[0]), "+f"(c[1]), "+f"(c[2]), "+f"(c[3])
                 : "r"(a[0]), "r"(a[1]), "r"(a[2]), "r"(a[3]), "r"(b0), "r"(b1));
}

// ---------------- CSR build ----------------
__global__ void zero_deg_k()
{
    int i = blockIdx.x * blockDim.x + threadIdx.x;
    if (i < N_NODES) d_deg[i] = 0;
}

__global__ void hist_k(const int* __restrict__ ei)
{
    int e = blockIdx.x * blockDim.x + threadIdx.x;
    if (e >= N_EDGES) return;
    atomicAdd(&d_deg[ei[N_EDGES + e]], 1);
}

// single-pass blocked scan: 1024 threads x 30 items
__global__ __launch_bounds__(1024) void scan_k()
{
    __shared__ int wsum[32];
    const int tid = threadIdx.x;
    const int ITEMS = (N_NODES + 1023) / 1024;   // 30
    int base = tid * ITEMS;
    int sum = 0;
#pragma unroll 4
    for (int i = 0; i < ITEMS; i++) {
        int idx = base + i;
        if (idx < N_NODES) sum += d_deg[idx];
    }
    int lane = tid & 31, wid = tid >> 5;
    int v = sum;
#pragma unroll
    for (int o = 1; o < 32; o <<= 1) {
        int y = __shfl_up_sync(0xFFFFFFFFu, v, o);
        if (lane >= o) v += y;
    }
    if (lane == 31) wsum[wid] = v;
    __syncthreads();
    if (wid == 0) {
        int w = wsum[lane];
#pragma unroll
        for (int o = 1; o < 32; o <<= 1) {
            int y = __shfl_up_sync(0xFFFFFFFFu, w, o);
            if (lane >= o) w += y;
        }
        wsum[lane] = w;
    }
    __syncthreads();
    int run = v - sum + (wid ? wsum[wid - 1] : 0);   // exclusive prefix for this thread
#pragma unroll 4
    for (int i = 0; i < ITEMS; i++) {
        int idx = base + i;
        if (idx < N_NODES) {
            d_rowptr[idx] = run;
            d_cursor[idx] = run;
            run += d_deg[idx];
        }
    }
    if (tid == 1023) d_rowptr[N_NODES] = wsum[31];
}

__global__ void scatter_k(const int* __restrict__ ei)
{
    int e = blockIdx.x * blockDim.x + threadIdx.x;
    if (e >= N_EDGES) return;
    int s = ei[e], d = ei[N_EDGES + e];
    int p = atomicAdd(&d_cursor[d], 1);
    d_csr_src[p] = s;
}

// ---------------- GEMM1 + fused attention scores, fp16 C store ----------------
__global__ __launch_bounds__(256, 1) void gemm1_mma(
    const float* __restrict__ A, const float* __restrict__ B,
    const float* __restrict__ att_s, const float* __restrict__ att_d,
    __half* __restrict__ C, int M)
{
    __shared__ unsigned As_h[16][136], As_l[16][136];
    __shared__ unsigned Bs_h[16][136], Bs_l[16][136];
    __shared__ float sred[4][128][2];
    const int tid = threadIdx.x, lane = tid & 31, wid = tid >> 5;
    const int g = lane >> 2, t = lane & 3;
    const int wm = wid >> 2, wn = wid & 3;     // 2x4 warps, warp tile 64x32
    const int by = blockIdx.y, bx = blockIdx.x;
    float acc[4][4][4] = {};

    const int arow = tid >> 1, akoff = (tid & 1) * 16;
    const int gArow = by * 128 + arow;
    const bool aval = gArow < M;
    const float* Ap = A + (size_t)gArow * F_IN + akoff;
    const int bk2 = tid >> 4, bcol = (tid & 15) * 4;
    const float* Bp = B + (size_t)(2 * bk2) * HC + bx * 128 + bcol;

    float4 sA[4], sB0[2], sB1[2];
#pragma unroll
    for (int i = 0; i < 4; i++)
        sA[i] = aval ? *(const float4*)(Ap + 4 * i) : make_float4(0.f, 0.f, 0.f, 0.f);
#pragma unroll
    for (int j = 0; j < 2; j++) {
        sB0[j] = *(const float4*)(Bp + 64 * j);
        sB1[j] = *(const float4*)(Bp + HC + 64 * j);
    }

    for (int kt = 0; kt < F_IN / 32; kt++) {
#pragma unroll
        for (int i = 0; i < 4; i++) {
            int k2 = (akoff >> 1) + 2 * i;
            unsigned h0, l0, h1, l1;
            split2(sA[i].x, sA[i].y, h0, l0);
            split2(sA[i].z, sA[i].w, h1, l1);
            As_h[k2][arow] = h0;     As_l[k2][arow] = l0;
            As_h[k2 + 1][arow] = h1; As_l[k2 + 1][arow] = l1;
        }
#pragma unroll
        for (int j = 0; j < 2; j++) {
            int c = bcol + 64 * j;
            unsigned h, l;
            split2(sB0[j].x, sB1[j].x, h, l); Bs_h[bk2][c] = h;     Bs_l[bk2][c] = l;
            split2(sB0[j].y, sB1[j].y, h, l); Bs_h[bk2][c + 1] = h; Bs_l[bk2][c + 1] = l;
            split2(sB0[j].z, sB1[j].z, h, l); Bs_h[bk2][c + 2] = h; Bs_l[bk2][c + 2] = l;
            split2(sB0[j].w, sB1[j].w, h, l); Bs_h[bk2][c + 3] = h; Bs_l[bk2][c + 3] = l;
        }
        __syncthreads();
        if (kt < F_IN / 32 - 1) {
            const float* Ap2 = Ap + 32 * (kt + 1);
#pragma unroll
            for (int i = 0; i < 4; i++)
                sA[i] = aval ? *(const float4*)(Ap2 + 4 * i) : make_float4(0.f, 0.f, 0.f, 0.f);
            const float* Bp2 = Bp + (size_t)32 * HC * (kt + 1);
#pragma unroll
            for (int j = 0; j < 2; j++) {
                sB0[j] = *(const float4*)(Bp2 + 64 * j);
                sB1[j] = *(const float4*)(Bp2 + HC + 64 * j);
            }
        }
#pragma unroll
        for (int s = 0; s < 2; s++) {
            unsigned ah[4][4], al[4][4];
#pragma unroll
            for (int mt = 0; mt < 4; mt++) {
                int m0 = wm * 64 + mt * 16 + g;
                ah[mt][0] = As_h[s * 8 + t][m0];         al[mt][0] = As_l[s * 8 + t][m0];
                ah[mt][1] = As_h[s * 8 + t][m0 + 8];     al[mt][1] = As_l[s * 8 + t][m0 + 8];
                ah[mt][2] = As_h[s * 8 + t + 4][m0];     al[mt][2] = As_l[s * 8 + t + 4][m0];
                ah[mt][3] = As_h[s * 8 + t + 4][m0 + 8]; al[mt][3] = As_l[s * 8 + t + 4][m0 + 8];
            }
#pragma unroll
            for (int nt = 0; nt < 4; nt++) {
                int n0 = wn * 32 + nt * 8 + g;
                unsigned bh0 = Bs_h[s * 8 + t][n0], bh1 = Bs_h[s * 8 + t + 4][n0];
                unsigned bl0 = Bs_l[s * 8 + t][n0], bl1 = Bs_l[s * 8 + t + 4][n0];
#pragma unroll
                for (int mt = 0; mt < 4; mt++) {
                    mma_bf16(acc[mt][nt], ah[mt], bh0, bh1);
                    mma_bf16(acc[mt][nt], ah[mt], bl0, bl1);
                    mma_bf16(acc[mt][nt], al[mt], bh0, bh1);
                }
            }
        }
        __syncthreads();
    }
    // store C tile as fp16
#pragma unroll
    for (int mt = 0; mt < 4; mt++) {
        int r0 = by * 128 + wm * 64 + mt * 16 + g;
        int r1 = r0 + 8;
#pragma unroll
        for (int nt = 0; nt < 4; nt++) {
            int col = bx * 128 + wn * 32 + nt * 8 + 2 * t;
            if (r0 < M) *(__half2*)(C + (size_t)r0 * HC + col) = __floats2half2_rn(acc[mt][nt][0], acc[mt][nt][1]);
            if (r1 < M) *(__half2*)(C + (size_t)r1 * HC + col) = __floats2half2_rn(acc[mt][nt][2], acc[mt][nt][3]);
        }
    }
    // fused score epilogue (fp32 accumulators -> exact scores)
    const float* as = att_s + bx * CDIM;
    const float* ad = att_d + bx * CDIM;
    float pss[4][2] = {}, psd[4][2] = {};
#pragma unroll
    for (int nt = 0; nt < 4; nt++) {
        int col = wn * 32 + nt * 8 + 2 * t;
        float a0 = as[col], a1 = as[col + 1];
        float e0 = ad[col], e1 = ad[col + 1];
#pragma unroll
        for (int mt = 0; mt < 4; mt++) {
            pss[mt][0] += acc[mt][nt][0] * a0 + acc[mt][nt][1] * a1;
            pss[mt][1] += acc[mt][nt][2] * a0 + acc[mt][nt][3] * a1;
            psd[mt][0] += acc[mt][nt][0] * e0 + acc[mt][nt][1] * e1;
            psd[mt][1] += acc[mt][nt][2] * e0 + acc[mt][nt][3] * e1;
        }
    }
#pragma unroll
    for (int o = 1; o <= 2; o <<= 1)
#pragma unroll
        for (int mt = 0; mt < 4; mt++)
#pragma unroll
            for (int rh = 0; rh < 2; rh++) {
                pss[mt][rh] += __shfl_xor_sync(0xFFFFFFFFu, pss[mt][rh], o);
                psd[mt][rh] += __shfl_xor_sync(0xFFFFFFFFu, psd[mt][rh], o);
            }
    if (t == 0) {
#pragma unroll
        for (int mt = 0; mt < 4; mt++)
#pragma unroll
            for (int rh = 0; rh < 2; rh++) {
                int rl = wm * 64 + mt * 16 + rh * 8 + g;
                sred[wn][rl][0] = pss[mt][rh];
                sred[wn][rl][1] = psd[mt][rh];
            }
    }
    __syncthreads();
    {
        int rl = tid >> 1, which = tid & 1;
        float sum = sred[0][rl][which] + sred[1][rl][which] + sred[2][rl][which] + sred[3][rl][which];
        int row = by * 128 + rl;
        if (row < M) {
            if (which) d_adst1[row * HEADS + bx] = sum;
            else       d_asrc1[row * HEADS + bx] = sum;
        }
    }
}

// ---------------- layer-1 one-pass aggregation (CSR, fp16 gather from L2) ----------------
__global__ __launch_bounds__(256) void agg1_k()
{
    int n = blockIdx.x;
    int h = threadIdx.x >> 5, lane = threadIdx.x & 31;
    float adst = d_adst1[n * HEADS + h];
    float ws = __expf(lrelu(d_asrc1[n * HEADS + h] + adst));
    const size_t rowoff = (size_t)h * CDIM + lane * 4;
    const __half2* hp = (const __half2*)(d_h1h + (size_t)n * HC + rowoff);
    float2 v0 = __half22float2(hp[0]);
    float2 v1 = __half22float2(hp[1]);
    float4 acc = make_float4(ws * v0.x, ws * v0.y, ws * v1.x, ws * v1.y);
    float denom = ws;
    int beg = d_rowptr[n], end = d_rowptr[n + 1];
#pragma unroll 2
    for (int j = beg; j < end; j++) {
        int s = __ldg(&d_csr_src[j]);
        float w = __expf(lrelu(__ldg(&d_asrc1[s * HEADS + h]) + adst));
        const __half2* up = (const __half2*)(d_h1h + (size_t)s * HC + rowoff);
        float2 u0 = __half22float2(up[0]);
        float2 u1 = __half22float2(up[1]);
        acc.x += w * u0.x; acc.y += w * u0.y; acc.z += w * u1.x; acc.w += w * u1.y;
        denom += w;
    }
    float inv = 1.f / (denom + 1e-16f);
    acc.x *= inv; acc.y *= inv; acc.z *= inv; acc.w *= inv;
    __stcs((float4*)(d_agg1 + (size_t)n * HC + rowoff), acc);   // streaming write: keep h1h in L2
}

// ---------------- GEMM2 (fused bias+ELU on A) + fused attention scores ----------------
__global__ __launch_bounds__(256, 1) void gemm2_mma(
    const float* __restrict__ A, const float* __restrict__ B, const float* __restrict__ bias,
    const float* __restrict__ att_s, const float* __restrict__ att_d,
    float* __restrict__ C, int M)
{
    __shared__ unsigned As_h[16][136], As_l[16][136];
    __shared__ unsigned Bs_h[16][72], Bs_l[16][72];
    __shared__ float sred[2][128][2];
    const int tid = threadIdx.x, lane = tid & 31, wid = tid >> 5;
    const int g = lane >> 2, t = lane & 3;
    const int wm = wid >> 1, wn = wid & 1;     // 4x2 warps, warp tile 32x32
    const int by = blockIdx.x;
    float acc[2][4][4] = {};

    const int arow = tid >> 1, akoff = (tid & 1) * 16;
    const int gArow = by * 128 + arow;
    const bool aval = gArow < M;
    const float* Ap = A + (size_t)gArow * HC + akoff;
    const int bk2 = tid >> 4, bcol = (tid & 15) * 4;
    const float* Bp = B + (size_t)(2 * bk2) * OUTD + bcol;

    float4 sA[4], sB0, sB1;
    {
#pragma unroll
        for (int i = 0; i < 4; i++) {
            float4 v = aval ? __ldcs((const float4*)(Ap + 4 * i)) : make_float4(0.f, 0.f, 0.f, 0.f);
            float4 b = *(const float4*)(bias + akoff + 4 * i);
            v.x += b.x; v.y += b.y; v.z += b.z; v.w += b.w;
            v.x = v.x > 0.f ? v.x : expm1f(v.x);
            v.y = v.y > 0.f ? v.y : expm1f(v.y);
            v.z = v.z > 0.f ? v.z : expm1f(v.z);
            v.w = v.w > 0.f ? v.w : expm1f(v.w);
            sA[i] = v;
        }
        sB0 = *(const float4*)Bp;
        sB1 = *(const float4*)(Bp + OUTD);
    }

    for (int kt = 0; kt < HC / 32; kt++) {
#pragma unroll
        for (int i = 0; i < 4; i++) {
            int k2 = (akoff >> 1) + 2 * i;
            unsigned h0, l0, h1, l1;
            split2(sA[i].x, sA[i].y, h0, l0);
            split2(sA[i].z, sA[i].w, h1, l1);
            As_h[k2][arow] = h0;     As_l[k2][arow] = l0;
            As_h[k2 + 1][arow] = h1; As_l[k2 + 1][arow] = l1;
        }
        {
            unsigned h, l;
            split2(sB0.x, sB1.x, h, l); Bs_h[bk2][bcol] = h;     Bs_l[bk2][bcol] = l;
            split2(sB0.y, sB1.y, h, l); Bs_h[bk2][bcol + 1] = h; Bs_l[bk2][bcol + 1] = l;
            split2(sB0.z, sB1.z, h, l); Bs_h[bk2][bcol + 2] = h; Bs_l[bk2][bcol + 2] = l;
            split2(sB0.w, sB1.w, h, l); Bs_h[bk2][bcol + 3] = h; Bs_l[bk2][bcol + 3] = l;
        }
        __syncthreads();
        if (kt < HC / 32 - 1) {
            const float* Ap2 = Ap + 32 * (kt + 1);
            const float* bp2 = bias + 32 * (kt + 1) + akoff;
#pragma unroll
            for (int i = 0; i < 4; i++) {
                float4 v = aval ? __ldcs((const float4*)(Ap2 + 4 * i)) : make_float4(0.f, 0.f, 0.f, 0.f);
                float4 b = *(const float4*)(bp2 + 4 * i);
                v.x += b.x; v.y += b.y; v.z += b.z; v.w += b.w;
                v.x = v.x > 0.f ? v.x : expm1f(v.x);
                v.y = v.y > 0.f ? v.y : expm1f(v.y);
                v.z = v.z > 0.f ? v.z : expm1f(v.z);
                v.w = v.w > 0.f ? v.w : expm1f(v.w);
                sA[i] = v;
            }
            const float* Bp2 = Bp + (size_t)32 * OUTD * (kt + 1);
            sB0 = *(const float4*)Bp2;
            sB1 = *(const float4*)(Bp2 + OUTD);
        }
#pragma unroll
        for (int s = 0; s < 2; s++) {
            unsigned ah[2][4], al[2][4];
#pragma unroll
            for (int mt = 0; mt < 2; mt++) {
                int m0 = wm * 32 + mt * 16 + g;
                ah[mt][0] = As_h[s * 8 + t][m0];         al[mt][0] = As_l[s * 8 + t][m0];
                ah[mt][1] = As_h[s * 8 + t][m0 + 8];     al[mt][1] = As_l[s * 8 + t][m0 + 8];
                ah[mt][2] = As_h[s * 8 + t + 4][m0];     al[mt][2] = As_l[s * 8 + t + 4][m0];
                ah[mt][3] = As_h[s * 8 + t + 4][m0 + 8]; al[mt][3] = As_l[s * 8 + t + 4][m0 + 8];
            }
#pragma unroll
            for (int nt = 0; nt < 4; nt++) {
                int n0 = wn * 32 + nt * 8 + g;
                unsigned bh0 = Bs_h[s * 8 + t][n0], bh1 = Bs_h[s * 8 + t + 4][n0];
                unsigned bl0 = Bs_l[s * 8 + t][n0], bl1 = Bs_l[s * 8 + t + 4][n0];
#pragma unroll
                for (int mt = 0; mt < 2; mt++) {
                    mma_bf16(acc[mt][nt], ah[mt], bh0, bh1);
                    mma_bf16(acc[mt][nt], ah[mt], bl0, bl1);
                    mma_bf16(acc[mt][nt], al[mt], bh0, bh1);
                }
            }
        }
        __syncthreads();
    }
#pragma unroll
    for (int mt = 0; mt < 2; mt++) {
        int r0 = by * 128 + wm * 32 + mt * 16 + g;
        int r1 = r0 + 8;
#pragma unroll
        for (int nt = 0; nt < 4; nt++) {
            int col = wn * 32 + nt * 8 + 2 * t;
            if (r0 < M) *(float2*)(C + (size_t)r0 * OUTD + col) = make_float2(acc[mt][nt][0], acc[mt][nt][1]);
            if (r1 < M) *(float2*)(C + (size_t)r1 * OUTD + col) = make_float2(acc[mt][nt][2], acc[mt][nt][3]);
        }
    }
    // fused score epilogue
    float pss[2][2] = {}, psd[2][2] = {};
#pragma unroll
    for (int nt = 0; nt < 4; nt++) {
        int col = wn * 32 + nt * 8 + 2 * t;
        float a0 = att_s[col], a1 = att_s[col + 1];
        float e0 = att_d[col], e1 = att_d[col + 1];
#pragma unroll
        for (int mt = 0; mt < 2; mt++) {
            pss[mt][0] += acc[mt][nt][0] * a0 + acc[mt][nt][1] * a1;
            pss[mt][1] += acc[mt][nt][2] * a0 + acc[mt][nt][3] * a1;
            psd[mt][0] += acc[mt][nt][0] * e0 + acc[mt][nt][1] * e1;
            psd[mt][1] += acc[mt][nt][2] * e0 + acc[mt][nt][3] * e1;
        }
    }
#pragma unroll
    for (int o = 1; o <= 2; o <<= 1)
#pragma unroll
        for (int mt = 0; mt < 2; mt++)
#pragma unroll
            for (int rh = 0; rh < 2; rh++) {
                pss[mt][rh] += __shfl_xor_sync(0xFFFFFFFFu, pss[mt][rh], o);
                psd[mt][rh] += __shfl_xor_sync(0xFFFFFFFFu, psd[mt][rh], o);
            }
    if (t == 0) {
#pragma unroll
        for (int mt = 0; mt < 2; mt++)
#pragma unroll
            for (int rh = 0; rh < 2; rh++) {
                int rl = wm * 32 + mt * 16 + rh * 8 + g;
                sred[wn][rl][0] = pss[mt][rh];
                sred[wn][rl][1] = psd[mt][rh];
            }
    }
    __syncthreads();
    {
        int rl = tid >> 1, which = tid & 1;
        float sum = sred[0][rl][which] + sred[1][rl][which];
        int row = by * 128 + rl;
        if (row < M) {
            if (which) d_adst2[row] = sum;
            else       d_asrc2[row] = sum;
        }
    }
}

// ---------------- layer-2 one-pass aggregation + bias + log_softmax ----------------
__global__ __launch_bounds__(256) void agg2_k(float* __restrict__ out, const float* __restrict__ b2)
{
    int n = blockIdx.x * 8 + (threadIdx.x >> 5);
    int lane = threadIdx.x & 31;
    if (n >= N_NODES) return;
    float adst = d_adst2[n];
    float ws = __expf(lrelu(d_asrc2[n] + adst));
    const float* hp = d_h2 + (size_t)n * OUTD;
    float acc0 = ws * hp[lane], acc1 = ws * hp[lane + 32];
    float denom = ws;
    int beg = d_rowptr[n], end = d_rowptr[n + 1];
    for (int j = beg; j < end; j++) {
        int s = __ldg(&d_csr_src[j]);
        float w = __expf(lrelu(__ldg(&d_asrc2[s]) + adst));
        const float* sp = d_h2 + (size_t)s * OUTD;
        acc0 += w * sp[lane];
        acc1 += w * sp[lane + 32];
        denom += w;
    }
    float inv = 1.f / (denom + 1e-16f);
    float x0 = acc0 * inv + b2[lane];
    float x1 = acc1 * inv + b2[lane + 32];
    float mx = fmaxf(x0, x1);
#pragma unroll
    for (int o = 16; o; o >>= 1) mx = fmaxf(mx, __shfl_xor_sync(0xFFFFFFFFu, mx, o));
    float sm = __expf(x0 - mx) + __expf(x1 - mx);
#pragma unroll
    for (int o = 16; o; o >>= 1) sm += __shfl_xor_sync(0xFFFFFFFFu, sm, o);
    float lse = mx + logf(sm);
    out[(size_t)n * OUTD + lane] = x0 - lse;
    out[(size_t)n * OUTD + lane + 32] = x1 - lse;
}

// ---------------- launch ----------------
extern "C" void kernel_launch(void* const* d_in, const int* in_sizes, int n_in,
                              void* d_out, int out_size)
{
    const float* x   = (const float*)d_in[0];
    const int*   ei  = (const int*)  d_in[1];
    const float* W1  = (const float*)d_in[2];
    const float* as1 = (const float*)d_in[3];
    const float* ad1 = (const float*)d_in[4];
    const float* b1  = (const float*)d_in[5];
    const float* W2  = (const float*)d_in[6];
    const float* as2 = (const float*)d_in[7];
    const float* ad2 = (const float*)d_in[8];
    const float* b2  = (const float*)d_in[9];
    float* out = (float*)d_out;

    __half* h1p;
    float *agg1p, *h2p;
    cudaGetSymbolAddress((void**)&h1p,   d_h1h);
    cudaGetSymbolAddress((void**)&agg1p, d_agg1);
    cudaGetSymbolAddress((void**)&h2p,   d_h2);

    // CSR build
    zero_deg_k<<<(N_NODES + 255) / 256, 256>>>();
    hist_k<<<(N_EDGES + 255) / 256, 256>>>(ei);
    scan_k<<<1, 1024>>>();
    scatter_k<<<(N_EDGES + 255) / 256, 256>>>(ei);

    // layer 1
    {
        dim3 g(HC / 128, (N_NODES + 127) / 128);
        gemm1_mma<<<g, 256>>>(x, W1, as1, ad1, h1p, N_NODES);
    }
    agg1_k<<<N_NODES, 256>>>();

    // layer 2
    gemm2_mma<<<(N_NODES + 127) / 128, 256>>>(agg1p, W2, b1, as2, ad2, h2p, N_NODES);
    agg2_k<<<(N_NODES + 7) / 8, 256>>>(out, b2);
}

// round 9
// speedup vs baseline: 2.3699x; 1.0166x over previous
#include <cuda_runtime.h>
#include <cuda_bf16.h>
#include <cuda_fp16.h>
#include <math.h>

#define N_NODES 30000
#define F_IN    256
#define N_EDGES 300000
#define HEADS   8
#define CDIM    128
#define HC      1024
#define OUTD    64
#define NEG_SLOPE 0.2f

// ---------------- scratch ----------------
__device__ __align__(256) __half d_h1h [(size_t)N_NODES * HC];   // 61.4 MB, L2-resident
__device__ __align__(256) float  d_agg1[(size_t)N_NODES * HC];   // 122.9 MB
__device__ __align__(256) float  d_asrc1[N_NODES * HEADS];
__device__ __align__(256) float  d_adst1[N_NODES * HEADS];
__device__ __align__(256) float  d_h2  [(size_t)N_NODES * OUTD];
__device__ __align__(256) float  d_asrc2[N_NODES];
__device__ __align__(256) float  d_adst2[N_NODES];
__device__ __align__(256) int    d_deg   [N_NODES];
__device__ __align__(256) int    d_rowptr[N_NODES + 1];
__device__ __align__(256) int    d_cursor[N_NODES];
__device__ __align__(256) int    d_csr_src[N_EDGES];

// ---------------- helpers ----------------
__device__ __forceinline__ float lrelu(float x) { return x > 0.f ? x : NEG_SLOPE * x; }

__device__ __forceinline__ void split2(float x, float y, unsigned& h, unsigned& l) {
    __nv_bfloat16 hx = __float2bfloat16(x);
    __nv_bfloat16 hy = __float2bfloat16(y);
    float rx = x - __bfloat162float(hx);
    float ry = y - __bfloat162float(hy);
    __nv_bfloat16 lx = __float2bfloat16(rx);
    __nv_bfloat16 ly = __float2bfloat16(ry);
    h = (unsigned)__bfloat16_as_ushort(hx) | ((unsigned)__bfloat16_as_ushort(hy) << 16);
    l = (unsigned)__bfloat16_as_ushort(lx) | ((unsigned)__bfloat16_as_ushort(ly) << 16);
}

__device__ __forceinline__ void mma_bf16(float* c, const unsigned* a, unsigned b0, unsigned b1) {
    asm volatile("mma.sync.aligned.m16n8k16.row.col.f32.bf16.bf16.f32 "
                 "{%0,%1,%2,%3}, {%4,%5,%6,%7}, {%8,%9}, {%0,%1,%2,%3};\n"
                 : "+f"(c[0]), "+f"(c[1]), "+f"(c[2]), "+f"(c[3])
                 : "r"(a[0]), "r"(a[1]), "r"(a[2]), "r"(a[3]), "r"(b0), "r"(b1));
}

// accumulate one fp16 feature vector (4 halves at base) scaled by w
__device__ __forceinline__ void acc_h4(float4& acc, const __half* base, float w) {
    uint2 raw = *(const uint2*)base;
    __half2 p0 = *reinterpret_cast<const __half2*>(&raw.x);
    __half2 p1 = *reinterpret_cast<const __half2*>(&raw.y);
    float2 u0 = __half22float2(p0), u1 = __half22float2(p1);
    acc.x += w * u0.x; acc.y += w * u0.y; acc.z += w * u1.x; acc.w += w * u1.y;
}

// ---------------- CSR build ----------------
__global__ void zero_deg_k()
{
    int i = blockIdx.x * blockDim.x + threadIdx.x;
    if (i < N_NODES) d_deg[i] = 0;
}

__global__ void hist_k(const int* __restrict__ ei)
{
    int e = blockIdx.x * blockDim.x + threadIdx.x;
    if (e >= N_EDGES) return;
    atomicAdd(&d_deg[ei[N_EDGES + e]], 1);
}

// single-pass blocked scan: 1024 threads x 30 items
__global__ __launch_bounds__(1024) void scan_k()
{
    __shared__ int wsum[32];
    const int tid = threadIdx.x;
    const int ITEMS = (N_NODES + 1023) / 1024;   // 30
    int base = tid * ITEMS;
    int sum = 0;
#pragma unroll 4
    for (int i = 0; i < ITEMS; i++) {
        int idx = base + i;
        if (idx < N_NODES) sum += d_deg[idx];
    }
    int lane = tid & 31, wid = tid >> 5;
    int v = sum;
#pragma unroll
    for (int o = 1; o < 32; o <<= 1) {
        int y = __shfl_up_sync(0xFFFFFFFFu, v, o);
        if (lane >= o) v += y;
    }
    if (lane == 31) wsum[wid] = v;
    __syncthreads();
    if (wid == 0) {
        int w = wsum[lane];
#pragma unroll
        for (int o = 1; o < 32; o <<= 1) {
            int y = __shfl_up_sync(0xFFFFFFFFu, w, o);
            if (lane >= o) w += y;
        }
        wsum[lane] = w;
    }
    __syncthreads();
    int run = v - sum + (wid ? wsum[wid - 1] : 0);
#pragma unroll 4
    for (int i = 0; i < ITEMS; i++) {
        int idx = base + i;
        if (idx < N_NODES) {
            d_rowptr[idx] = run;
            d_cursor[idx] = run;
            run += d_deg[idx];
        }
    }
    if (tid == 1023) d_rowptr[N_NODES] = wsum[31];
}

__global__ void scatter_k(const int* __restrict__ ei)
{
    int e = blockIdx.x * blockDim.x + threadIdx.x;
    if (e >= N_EDGES) return;
    int s = ei[e], d = ei[N_EDGES + e];
    int p = atomicAdd(&d_cursor[d], 1);
    d_csr_src[p] = s;
}

// ---------------- GEMM1 + fused attention scores, fp16 C store ----------------
__global__ __launch_bounds__(256, 1) void gemm1_mma(
    const float* __restrict__ A, const float* __restrict__ B,
    const float* __restrict__ att_s, const float* __restrict__ att_d,
    __half* __restrict__ C, int M)
{
    __shared__ unsigned As_h[16][136], As_l[16][136];
    __shared__ unsigned Bs_h[16][136], Bs_l[16][136];
    __shared__ float sred[4][128][2];
    const int tid = threadIdx.x, lane = tid & 31, wid = tid >> 5;
    const int g = lane >> 2, t = lane & 3;
    const int wm = wid >> 2, wn = wid & 3;     // 2x4 warps, warp tile 64x32
    const int by = blockIdx.y, bx = blockIdx.x;
    float acc[4][4][4] = {};

    const int arow = tid >> 1, akoff = (tid & 1) * 16;
    const int gArow = by * 128 + arow;
    const bool aval = gArow < M;
    const float* Ap = A + (size_t)gArow * F_IN + akoff;
    const int bk2 = tid >> 4, bcol = (tid & 15) * 4;
    const float* Bp = B + (size_t)(2 * bk2) * HC + bx * 128 + bcol;

    float4 sA[4], sB0[2], sB1[2];
#pragma unroll
    for (int i = 0; i < 4; i++)
        sA[i] = aval ? *(const float4*)(Ap + 4 * i) : make_float4(0.f, 0.f, 0.f, 0.f);
#pragma unroll
    for (int j = 0; j < 2; j++) {
        sB0[j] = *(const float4*)(Bp + 64 * j);
        sB1[j] = *(const float4*)(Bp + HC + 64 * j);
    }

    for (int kt = 0; kt < F_IN / 32; kt++) {
#pragma unroll
        for (int i = 0; i < 4; i++) {
            int k2 = (akoff >> 1) + 2 * i;
            unsigned h0, l0, h1, l1;
            split2(sA[i].x, sA[i].y, h0, l0);
            split2(sA[i].z, sA[i].w, h1, l1);
            As_h[k2][arow] = h0;     As_l[k2][arow] = l0;
            As_h[k2 + 1][arow] = h1; As_l[k2 + 1][arow] = l1;
        }
#pragma unroll
        for (int j = 0; j < 2; j++) {
            int c = bcol + 64 * j;
            unsigned h, l;
            split2(sB0[j].x, sB1[j].x, h, l); Bs_h[bk2][c] = h;     Bs_l[bk2][c] = l;
            split2(sB0[j].y, sB1[j].y, h, l); Bs_h[bk2][c + 1] = h; Bs_l[bk2][c + 1] = l;
            split2(sB0[j].z, sB1[j].z, h, l); Bs_h[bk2][c + 2] = h; Bs_l[bk2][c + 2] = l;
            split2(sB0[j].w, sB1[j].w, h, l); Bs_h[bk2][c + 3] = h; Bs_l[bk2][c + 3] = l;
        }
        __syncthreads();
        if (kt < F_IN / 32 - 1) {
            const float* Ap2 = Ap + 32 * (kt + 1);
#pragma unroll
            for (int i = 0; i < 4; i++)
                sA[i] = aval ? *(const float4*)(Ap2 + 4 * i) : make_float4(0.f, 0.f, 0.f, 0.f);
            const float* Bp2 = Bp + (size_t)32 * HC * (kt + 1);
#pragma unroll
            for (int j = 0; j < 2; j++) {
                sB0[j] = *(const float4*)(Bp2 + 64 * j);
                sB1[j] = *(const float4*)(Bp2 + HC + 64 * j);
            }
        }
#pragma unroll
        for (int s = 0; s < 2; s++) {
            unsigned ah[4][4], al[4][4];
#pragma unroll
            for (int mt = 0; mt < 4; mt++) {
                int m0 = wm * 64 + mt * 16 + g;
                ah[mt][0] = As_h[s * 8 + t][m0];         al[mt][0] = As_l[s * 8 + t][m0];
                ah[mt][1] = As_h[s * 8 + t][m0 + 8];     al[mt][1] = As_l[s * 8 + t][m0 + 8];
                ah[mt][2] = As_h[s * 8 + t + 4][m0];     al[mt][2] = As_l[s * 8 + t + 4][m0];
                ah[mt][3] = As_h[s * 8 + t + 4][m0 + 8]; al[mt][3] = As_l[s * 8 + t + 4][m0 + 8];
            }
#pragma unroll
            for (int nt = 0; nt < 4; nt++) {
                int n0 = wn * 32 + nt * 8 + g;
                unsigned bh0 = Bs_h[s * 8 + t][n0], bh1 = Bs_h[s * 8 + t + 4][n0];
                unsigned bl0 = Bs_l[s * 8 + t][n0], bl1 = Bs_l[s * 8 + t + 4][n0];
#pragma unroll
                for (int mt = 0; mt < 4; mt++) {
                    mma_bf16(acc[mt][nt], ah[mt], bh0, bh1);
                    mma_bf16(acc[mt][nt], ah[mt], bl0, bl1);
                    mma_bf16(acc[mt][nt], al[mt], bh0, bh1);
                }
            }
        }
        __syncthreads();
    }
    // store C tile as fp16
#pragma unroll
    for (int mt = 0; mt < 4; mt++) {
        int r0 = by * 128 + wm * 64 + mt * 16 + g;
        int r1 = r0 + 8;
#pragma unroll
        for (int nt = 0; nt < 4; nt++) {
            int col = bx * 128 + wn * 32 + nt * 8 + 2 * t;
            if (r0 < M) *(__half2*)(C + (size_t)r0 * HC + col) = __floats2half2_rn(acc[mt][nt][0], acc[mt][nt][1]);
            if (r1 < M) *(__half2*)(C + (size_t)r1 * HC + col) = __floats2half2_rn(acc[mt][nt][2], acc[mt][nt][3]);
        }
    }
    // fused score epilogue (fp32 accumulators -> exact scores)
    const float* as = att_s + bx * CDIM;
    const float* ad = att_d + bx * CDIM;
    float pss[4][2] = {}, psd[4][2] = {};
#pragma unroll
    for (int nt = 0; nt < 4; nt++) {
        int col = wn * 32 + nt * 8 + 2 * t;
        float a0 = as[col], a1 = as[col + 1];
        float e0 = ad[col], e1 = ad[col + 1];
#pragma unroll
        for (int mt = 0; mt < 4; mt++) {
            pss[mt][0] += acc[mt][nt][0] * a0 + acc[mt][nt][1] * a1;
            pss[mt][1] += acc[mt][nt][2] * a0 + acc[mt][nt][3] * a1;
            psd[mt][0] += acc[mt][nt][0] * e0 + acc[mt][nt][1] * e1;
            psd[mt][1] += acc[mt][nt][2] * e0 + acc[mt][nt][3] * e1;
        }
    }
#pragma unroll
    for (int o = 1; o <= 2; o <<= 1)
#pragma unroll
        for (int mt = 0; mt < 4; mt++)
#pragma unroll
            for (int rh = 0; rh < 2; rh++) {
                pss[mt][rh] += __shfl_xor_sync(0xFFFFFFFFu, pss[mt][rh], o);
                psd[mt][rh] += __shfl_xor_sync(0xFFFFFFFFu, psd[mt][rh], o);
            }
    if (t == 0) {
#pragma unroll
        for (int mt = 0; mt < 4; mt++)
#pragma unroll
            for (int rh = 0; rh < 2; rh++) {
                int rl = wm * 64 + mt * 16 + rh * 8 + g;
                sred[wn][rl][0] = pss[mt][rh];
                sred[wn][rl][1] = psd[mt][rh];
            }
    }
    __syncthreads();
    {
        int rl = tid >> 1, which = tid & 1;
        float sum = sred[0][rl][which] + sred[1][rl][which] + sred[2][rl][which] + sred[3][rl][which];
        int row = by * 128 + rl;
        if (row < M) {
            if (which) d_adst1[row * HEADS + bx] = sum;
            else       d_asrc1[row * HEADS + bx] = sum;
        }
    }
}

// ---------------- layer-1 one-pass aggregation (CSR, staged indices+weights, MLP-4 gather) ----------------
__global__ __launch_bounds__(256) void agg1_k()
{
    __shared__ int   s_src[32];
    __shared__ float s_w[HEADS][32];
    const int n = blockIdx.x;
    const int h = threadIdx.x >> 5, lane = threadIdx.x & 31;
    const float adst = d_adst1[n * HEADS + h];
    const float ws = __expf(lrelu(d_asrc1[n * HEADS + h] + adst));
    const size_t rowoff = (size_t)h * CDIM + lane * 4;

    float4 acc = make_float4(0.f, 0.f, 0.f, 0.f);
    acc_h4(acc, d_h1h + (size_t)n * HC + rowoff, ws);
    float denom = ws;

    const int beg = d_rowptr[n], end = d_rowptr[n + 1];
    for (int c0 = beg; c0 < end; c0 += 32) {
        const int m = min(32, end - c0);
        if (h == 0 && lane < m) s_src[lane] = d_csr_src[c0 + lane];
        __syncthreads();
        if (lane < m)
            s_w[h][lane] = __expf(lrelu(__ldg(&d_asrc1[s_src[lane] * HEADS + h]) + adst));
        __syncwarp();
        int jm = m & ~3;
        for (int j = 0; j < jm; j += 4) {
            int s0 = s_src[j], s1 = s_src[j + 1], s2 = s_src[j + 2], s3 = s_src[j + 3];
            float w0 = s_w[h][j], w1 = s_w[h][j + 1], w2 = s_w[h][j + 2], w3 = s_w[h][j + 3];
            const __half* p0 = d_h1h + (size_t)s0 * HC + rowoff;
            const __half* p1 = d_h1h + (size_t)s1 * HC + rowoff;
            const __half* p2 = d_h1h + (size_t)s2 * HC + rowoff;
            const __half* p3 = d_h1h + (size_t)s3 * HC + rowoff;
            uint2 r0 = *(const uint2*)p0;
            uint2 r1 = *(const uint2*)p1;
            uint2 r2 = *(const uint2*)p2;
            uint2 r3 = *(const uint2*)p3;
            float2 a0 = __half22float2(*reinterpret_cast<const __half2*>(&r0.x));
            float2 b0 = __half22float2(*reinterpret_cast<const __half2*>(&r0.y));
            float2 a1 = __half22float2(*reinterpret_cast<const __half2*>(&r1.x));
            float2 b1 = __half22float2(*reinterpret_cast<const __half2*>(&r1.y));
            float2 a2 = __half22float2(*reinterpret_cast<const __half2*>(&r2.x));
            float2 b2 = __half22float2(*reinterpret_cast<const __half2*>(&r2.y));
            float2 a3 = __half22float2(*reinterpret_cast<const __half2*>(&r3.x));
            float2 b3 = __half22float2(*reinterpret_cast<const __half2*>(&r3.y));
            acc.x += w0 * a0.x + w1 * a1.x + w2 * a2.x + w3 * a3.x;
            acc.y += w0 * a0.y + w1 * a1.y + w2 * a2.y + w3 * a3.y;
            acc.z += w0 * b0.x + w1 * b1.x + w2 * b2.x + w3 * b3.x;
            acc.w += w0 * b0.y + w1 * b1.y + w2 * b2.y + w3 * b3.y;
            denom += w0 + w1 + w2 + w3;
        }
        for (int j = jm; j < m; j++) {
            float w = s_w[h][j];
            acc_h4(acc, d_h1h + (size_t)s_src[j] * HC + rowoff, w);
            denom += w;
        }
        __syncthreads();   // protect s_src before next chunk overwrite
    }
    float inv = 1.f / (denom + 1e-16f);
    acc.x *= inv; acc.y *= inv; acc.z *= inv; acc.w *= inv;
    __stcs((float4*)(d_agg1 + (size_t)n * HC + rowoff), acc);
}

// ---------------- GEMM2 (fused bias+ELU on A) + fused attention scores ----------------
__global__ __launch_bounds__(256, 1) void gemm2_mma(
    const float* __restrict__ A, const float* __restrict__ B, const float* __restrict__ bias,
    const float* __restrict__ att_s, const float* __restrict__ att_d,
    float* __restrict__ C, int M)
{
    __shared__ unsigned As_h[16][136], As_l[16][136];
    __shared__ unsigned Bs_h[16][72], Bs_l[16][72];
    __shared__ float sred[2][128][2];
    const int tid = threadIdx.x, lane = tid & 31, wid = tid >> 5;
    const int g = lane >> 2, t = lane & 3;
    const int wm = wid >> 1, wn = wid & 1;     // 4x2 warps, warp tile 32x32
    const int by = blockIdx.x;
    float acc[2][4][4] = {};

    const int arow = tid >> 1, akoff = (tid & 1) * 16;
    const int gArow = by * 128 + arow;
    const bool aval = gArow < M;
    const float* Ap = A + (size_t)gArow * HC + akoff;
    const int bk2 = tid >> 4, bcol = (tid & 15) * 4;
    const float* Bp = B + (size_t)(2 * bk2) * OUTD + bcol;

    float4 sA[4], sB0, sB1;
    {
#pragma unroll
        for (int i = 0; i < 4; i++) {
            float4 v = aval ? __ldcs((const float4*)(Ap + 4 * i)) : make_float4(0.f, 0.f, 0.f, 0.f);
            float4 b = *(const float4*)(bias + akoff + 4 * i);
            v.x += b.x; v.y += b.y; v.z += b.z; v.w += b.w;
            v.x = v.x > 0.f ? v.x : expm1f(v.x);
            v.y = v.y > 0.f ? v.y : expm1f(v.y);
            v.z = v.z > 0.f ? v.z : expm1f(v.z);
            v.w = v.w > 0.f ? v.w : expm1f(v.w);
            sA[i] = v;
        }
        sB0 = *(const float4*)Bp;
        sB1 = *(const float4*)(Bp + OUTD);
    }

    for (int kt = 0; kt < HC / 32; kt++) {
#pragma unroll
        for (int i = 0; i < 4; i++) {
            int k2 = (akoff >> 1) + 2 * i;
            unsigned h0, l0, h1, l1;
            split2(sA[i].x, sA[i].y, h0, l0);
            split2(sA[i].z, sA[i].w, h1, l1);
            As_h[k2][arow] = h0;     As_l[k2][arow] = l0;
            As_h[k2 + 1][arow] = h1; As_l[k2 + 1][arow] = l1;
        }
        {
            unsigned h, l;
            split2(sB0.x, sB1.x, h, l); Bs_h[bk2][bcol] = h;     Bs_l[bk2][bcol] = l;
            split2(sB0.y, sB1.y, h, l); Bs_h[bk2][bcol + 1] = h; Bs_l[bk2][bcol + 1] = l;
            split2(sB0.z, sB1.z, h, l); Bs_h[bk2][bcol + 2] = h; Bs_l[bk2][bcol + 2] = l;
            split2(sB0.w, sB1.w, h, l); Bs_h[bk2][bcol + 3] = h; Bs_l[bk2][bcol + 3] = l;
        }
        __syncthreads();
        if (kt < HC / 32 - 1) {
            const float* Ap2 = Ap + 32 * (kt + 1);
            const float* bp2 = bias + 32 * (kt + 1) + akoff;
#pragma unroll
            for (int i = 0; i < 4; i++) {
                float4 v = aval ? __ldcs((const float4*)(Ap2 + 4 * i)) : make_float4(0.f, 0.f, 0.f, 0.f);
                float4 b = *(const float4*)(bp2 + 4 * i);
                v.x += b.x; v.y += b.y; v.z += b.z; v.w += b.w;
                v.x = v.x > 0.f ? v.x : expm1f(v.x);
                v.y = v.y > 0.f ? v.y : expm1f(v.y);
                v.z = v.z > 0.f ? v.z : expm1f(v.z);
                v.w = v.w > 0.f ? v.w : expm1f(v.w);
                sA[i] = v;
            }
            const float* Bp2 = Bp + (size_t)32 * OUTD * (kt + 1);
            sB0 = *(const float4*)Bp2;
            sB1 = *(const float4*)(Bp2 + OUTD);
        }
#pragma unroll
        for (int s = 0; s < 2; s++) {
            unsigned ah[2][4], al[2][4];
#pragma unroll
            for (int mt = 0; mt < 2; mt++) {
                int m0 = wm * 32 + mt * 16 + g;
                ah[mt][0] = As_h[s * 8 + t][m0];         al[mt][0] = As_l[s * 8 + t][m0];
                ah[mt][1] = As_h[s * 8 + t][m0 + 8];     al[mt][1] = As_l[s * 8 + t][m0 + 8];
                ah[mt][2] = As_h[s * 8 + t + 4][m0];     al[mt][2] = As_l[s * 8 + t + 4][m0];
                ah[mt][3] = As_h[s * 8 + t + 4][m0 + 8]; al[mt][3] = As_l[s * 8 + t + 4][m0 + 8];
            }
#pragma unroll
            for (int nt = 0; nt < 4; nt++) {
                int n0 = wn * 32 + nt * 8 + g;
                unsigned bh0 = Bs_h[s * 8 + t][n0], bh1 = Bs_h[s * 8 + t + 4][n0];
                unsigned bl0 = Bs_l[s * 8 + t][n0], bl1 = Bs_l[s * 8 + t + 4][n0];
#pragma unroll
                for (int mt = 0; mt < 2; mt++) {
                    mma_bf16(acc[mt][nt], ah[mt], bh0, bh1);
                    mma_bf16(acc[mt][nt], ah[mt], bl0, bl1);
                    mma_bf16(acc[mt][nt], al[mt], bh0, bh1);
                }
            }
        }
        __syncthreads();
    }
#pragma unroll
    for (int mt = 0; mt < 2; mt++) {
        int r0 = by * 128 + wm * 32 + mt * 16 + g;
        int r1 = r0 + 8;
#pragma unroll
        for (int nt = 0; nt < 4; nt++) {
            int col = wn * 32 + nt * 8 + 2 * t;
            if (r0 < M) *(float2*)(C + (size_t)r0 * OUTD + col) = make_float2(acc[mt][nt][0], acc[mt][nt][1]);
            if (r1 < M) *(float2*)(C + (size_t)r1 * OUTD + col) = make_float2(acc[mt][nt][2], acc[mt][nt][3]);
        }
    }
    // fused score epilogue
    float pss[2][2] = {}, psd[2][2] = {};
#pragma unroll
    for (int nt = 0; nt < 4; nt++) {
        int col = wn * 32 + nt * 8 + 2 * t;
        float a0 = att_s[col], a1 = att_s[col + 1];
        float e0 = att_d[col], e1 = att_d[col + 1];
#pragma unroll
        for (int mt = 0; mt < 2; mt++) {
            pss[mt][0] += acc[mt][nt][0] * a0 + acc[mt][nt][1] * a1;
            pss[mt][1] += acc[mt][nt][2] * a0 + acc[mt][nt][3] * a1;
            psd[mt][0] += acc[mt][nt][0] * e0 + acc[mt][nt][1] * e1;
            psd[mt][1] += acc[mt][nt][2] * e0 + acc[mt][nt][3] * e1;
        }
    }
#pragma unroll
    for (int o = 1; o <= 2; o <<= 1)
#pragma unroll
        for (int mt = 0; mt < 2; mt++)
#pragma unroll
            for (int rh = 0; rh < 2; rh++) {
                pss[mt][rh] += __shfl_xor_sync(0xFFFFFFFFu, pss[mt][rh], o);
                psd[mt][rh] += __shfl_xor_sync(0xFFFFFFFFu, psd[mt][rh], o);
            }
    if (t == 0) {
#pragma unroll
        for (int mt = 0; mt < 2; mt++)
#pragma unroll
            for (int rh = 0; rh < 2; rh++) {
                int rl = wm * 32 + mt * 16 + rh * 8 + g;
                sred[wn][rl][0] = pss[mt][rh];
                sred[wn][rl][1] = psd[mt][rh];
            }
    }
    __syncthreads();
    {
        int rl = tid >> 1, which = tid & 1;
        float sum = sred[0][rl][which] + sred[1][rl][which];
        int row = by * 128 + rl;
        if (row < M) {
            if (which) d_adst2[row] = sum;
            else       d_asrc2[row] = sum;
        }
    }
}

// ---------------- layer-2 one-pass aggregation + bias + log_softmax (MLP-4) ----------------
__global__ __launch_bounds__(256) void agg2_k(float* __restrict__ out, const float* __restrict__ b2)
{
    int n = blockIdx.x * 8 + (threadIdx.x >> 5);
    int lane = threadIdx.x & 31;
    if (n >= N_NODES) return;
    float adst = d_adst2[n];
    float ws = __expf(lrelu(d_asrc2[n] + adst));
    const float* hp = d_h2 + (size_t)n * OUTD;
    float acc0 = ws * hp[lane], acc1 = ws * hp[lane + 32];
    float denom = ws;
    const int beg = d_rowptr[n], end = d_rowptr[n + 1];
    int j = beg;
    for (; j + 4 <= end; j += 4) {
        int s0 = __ldg(&d_csr_src[j]);
        int s1 = __ldg(&d_csr_src[j + 1]);
        int s2 = __ldg(&d_csr_src[j + 2]);
        int s3 = __ldg(&d_csr_src[j + 3]);
        float w0 = __expf(lrelu(__ldg(&d_asrc2[s0]) + adst));
        float w1 = __expf(lrelu(__ldg(&d_asrc2[s1]) + adst));
        float w2 = __expf(lrelu(__ldg(&d_asrc2[s2]) + adst));
        float w3 = __expf(lrelu(__ldg(&d_asrc2[s3]) + adst));
        const float* p0 = d_h2 + (size_t)s0 * OUTD;
        const float* p1 = d_h2 + (size_t)s1 * OUTD;
        const float* p2 = d_h2 + (size_t)s2 * OUTD;
        const float* p3 = d_h2 + (size_t)s3 * OUTD;
        float f00 = p0[lane], f01 = p0[lane + 32];
        float f10 = p1[lane], f11 = p1[lane + 32];
        float f20 = p2[lane], f21 = p2[lane + 32];
        float f30 = p3[lane], f31 = p3[lane + 32];
        acc0 += w0 * f00 + w1 * f10 + w2 * f20 + w3 * f30;
        acc1 += w0 * f01 + w1 * f11 + w2 * f21 + w3 * f31;
        denom += w0 + w1 + w2 + w3;
    }
    for (; j < end; j++) {
        int s = __ldg(&d_csr_src[j]);
        float w = __expf(lrelu(__ldg(&d_asrc2[s]) + adst));
        const float* sp = d_h2 + (size_t)s * OUTD;
        acc0 += w * sp[lane];
        acc1 += w * sp[lane + 32];
        denom += w;
    }
    float inv = 1.f / (denom + 1e-16f);
    float x0 = acc0 * inv + b2[lane];
    float x1 = acc1 * inv + b2[lane + 32];
    float mx = fmaxf(x0, x1);
#pragma unroll
    for (int o = 16; o; o >>= 1) mx = fmaxf(mx, __shfl_xor_sync(0xFFFFFFFFu, mx, o));
    float sm = __expf(x0 - mx) + __expf(x1 - mx);
#pragma unroll
    for (int o = 16; o; o >>= 1) sm += __shfl_xor_sync(0xFFFFFFFFu, sm, o);
    float lse = mx + logf(sm);
    out[(size_t)n * OUTD + lane] = x0 - lse;
    out[(size_t)n * OUTD + lane + 32] = x1 - lse;
}

// ---------------- launch ----------------
extern "C" void kernel_launch(void* const* d_in, const int* in_sizes, int n_in,
                              void* d_out, int out_size)
{
    const float* x   = (const float*)d_in[0];
    const int*   ei  = (const int*)  d_in[1];
    const float* W1  = (const float*)d_in[2];
    const float* as1 = (const float*)d_in[3];
    const float* ad1 = (const float*)d_in[4];
    const float* b1  = (const float*)d_in[5];
    const float* W2  = (const float*)d_in[6];
    const float* as2 = (const float*)d_in[7];
    const float* ad2 = (const float*)d_in[8];
    const float* b2  = (const float*)d_in[9];
    float* out = (float*)d_out;

    __half* h1p;
    float *agg1p, *h2p;
    cudaGetSymbolAddress((void**)&h1p,   d_h1h);
    cudaGetSymbolAddress((void**)&agg1p, d_agg1);
    cudaGetSymbolAddress((void**)&h2p,   d_h2);

    // CSR build
    zero_deg_k<<<(N_NODES + 255) / 256, 256>>>();
    hist_k<<<(N_EDGES + 255) / 256, 256>>>(ei);
    scan_k<<<1, 1024>>>();
    scatter_k<<<(N_EDGES + 255) / 256, 256>>>(ei);

    // layer 1
    {
        dim3 g(HC / 128, (N_NODES + 127) / 128);
        gemm1_mma<<<g, 256>>>(x, W1, as1, ad1, h1p, N_NODES);
    }
    agg1_k<<<N_NODES, 256>>>();

    // layer 2
    gemm2_mma<<<(N_NODES + 127) / 128, 256>>>(agg1p, W2, b1, as2, ad2, h2p, N_NODES);
    agg2_k<<<(N_NODES + 7) / 8, 256>>>(out, b2);
}

// round 10
// speedup vs baseline: 2.4449x; 1.0317x over previous
#include <cuda_runtime.h>
#include <cuda_bf16.h>
#include <cuda_fp16.h>
#include <math.h>

#define N_NODES 30000
#define F_IN    256
#define N_EDGES 300000
#define HEADS   8
#define CDIM    128
#define HC      1024
#define OUTD    64
#define NEG_SLOPE 0.2f

// ---------------- scratch ----------------
__device__ __align__(256) __half d_h1h  [(size_t)N_NODES * HC];  // 61.4 MB
__device__ __align__(256) __half d_agg1h[(size_t)N_NODES * HC];  // 61.4 MB (post bias+ELU)
__device__ __align__(256) float  d_asrc1[N_NODES * HEADS];
__device__ __align__(256) float  d_adst1[N_NODES * HEADS];
__device__ __align__(256) float  d_h2  [(size_t)N_NODES * OUTD];
__device__ __align__(256) float  d_asrc2[N_NODES];
__device__ __align__(256) float  d_adst2[N_NODES];
__device__ __align__(256) int    d_deg   [N_NODES];
__device__ __align__(256) int    d_rowptr[N_NODES + 1];
__device__ __align__(256) int    d_cursor[N_NODES];
__device__ __align__(256) int    d_csr_src[N_EDGES];

// ---------------- helpers ----------------
__device__ __forceinline__ float lrelu(float x) { return x > 0.f ? x : NEG_SLOPE * x; }

__device__ __forceinline__ void split2(float x, float y, unsigned& h, unsigned& l) {
    __nv_bfloat16 hx = __float2bfloat16(x);
    __nv_bfloat16 hy = __float2bfloat16(y);
    float rx = x - __bfloat162float(hx);
    float ry = y - __bfloat162float(hy);
    __nv_bfloat16 lx = __float2bfloat16(rx);
    __nv_bfloat16 ly = __float2bfloat16(ry);
    h = (unsigned)__bfloat16_as_ushort(hx) | ((unsigned)__bfloat16_as_ushort(hy) << 16);
    l = (unsigned)__bfloat16_as_ushort(lx) | ((unsigned)__bfloat16_as_ushort(ly) << 16);
}

__device__ __forceinline__ void mma_bf16(float* c, const unsigned* a, unsigned b0, unsigned b1) {
    asm volatile("mma.sync.aligned.m16n8k16.row.col.f32.bf16.bf16.f32 "
                 "{%0,%1,%2,%3}, {%4,%5,%6,%7}, {%8,%9}, {%0,%1,%2,%3};\n"
                 : "+f"(c[0]), "+f"(c[1]), "+f"(c[2]), "+f"(c[3])
                 : "r"(a[0]), "r"(a[1]), "r"(a[2]), "r"(a[3]), "r"(b0), "r"(b1));
}

__device__ __forceinline__ void acc_h4(float4& acc, const __half* base, float w) {
    uint2 raw = *(const uint2*)base;
    float2 u0 = __half22float2(*reinterpret_cast<const __half2*>(&raw.x));
    float2 u1 = __half22float2(*reinterpret_cast<const __half2*>(&raw.y));
    acc.x += w * u0.x; acc.y += w * u0.y; acc.z += w * u1.x; acc.w += w * u1.y;
}

// ---------------- CSR build ----------------
__global__ void zero_deg_k()
{
    int i = blockIdx.x * blockDim.x + threadIdx.x;
    if (i < N_NODES) d_deg[i] = 0;
}

__global__ void hist_k(const int* __restrict__ ei)
{
    int e = blockIdx.x * blockDim.x + threadIdx.x;
    if (e >= N_EDGES) return;
    atomicAdd(&d_deg[ei[N_EDGES + e]], 1);
}

__global__ __launch_bounds__(1024) void scan_k()
{
    __shared__ int wsum[32];
    const int tid = threadIdx.x;
    const int ITEMS = (N_NODES + 1023) / 1024;   // 30
    int base = tid * ITEMS;
    int sum = 0;
#pragma unroll 4
    for (int i = 0; i < ITEMS; i++) {
        int idx = base + i;
        if (idx < N_NODES) sum += d_deg[idx];
    }
    int lane = tid & 31, wid = tid >> 5;
    int v = sum;
#pragma unroll
    for (int o = 1; o < 32; o <<= 1) {
        int y = __shfl_up_sync(0xFFFFFFFFu, v, o);
        if (lane >= o) v += y;
    }
    if (lane == 31) wsum[wid] = v;
    __syncthreads();
    if (wid == 0) {
        int w = wsum[lane];
#pragma unroll
        for (int o = 1; o < 32; o <<= 1) {
            int y = __shfl_up_sync(0xFFFFFFFFu, w, o);
            if (lane >= o) w += y;
        }
        wsum[lane] = w;
    }
    __syncthreads();
    int run = v - sum + (wid ? wsum[wid - 1] : 0);
#pragma unroll 4
    for (int i = 0; i < ITEMS; i++) {
        int idx = base + i;
        if (idx < N_NODES) {
            d_rowptr[idx] = run;
            d_cursor[idx] = run;
            run += d_deg[idx];
        }
    }
    if (tid == 1023) d_rowptr[N_NODES] = wsum[31];
}

__global__ void scatter_k(const int* __restrict__ ei)
{
    int e = blockIdx.x * blockDim.x + threadIdx.x;
    if (e >= N_EDGES) return;
    int s = ei[e], d = ei[N_EDGES + e];
    int p = atomicAdd(&d_cursor[d], 1);
    d_csr_src[p] = s;
}

// ---------------- GEMM1 + fused attention scores, fp16 C store ----------------
__global__ __launch_bounds__(256, 1) void gemm1_mma(
    const float* __restrict__ A, const float* __restrict__ B,
    const float* __restrict__ att_s, const float* __restrict__ att_d,
    __half* __restrict__ C, int M)
{
    __shared__ unsigned As_h[16][136], As_l[16][136];
    __shared__ unsigned Bs_h[16][136], Bs_l[16][136];
    __shared__ float sred[4][128][2];
    const int tid = threadIdx.x, lane = tid & 31, wid = tid >> 5;
    const int g = lane >> 2, t = lane & 3;
    const int wm = wid >> 2, wn = wid & 3;     // 2x4 warps, warp tile 64x32
    const int by = blockIdx.y, bx = blockIdx.x;
    float acc[4][4][4] = {};

    const int arow = tid >> 1, akoff = (tid & 1) * 16;
    const int gArow = by * 128 + arow;
    const bool aval = gArow < M;
    const float* Ap = A + (size_t)gArow * F_IN + akoff;
    const int bk2 = tid >> 4, bcol = (tid & 15) * 4;
    const float* Bp = B + (size_t)(2 * bk2) * HC + bx * 128 + bcol;

    float4 sA[4], sB0[2], sB1[2];
#pragma unroll
    for (int i = 0; i < 4; i++)
        sA[i] = aval ? *(const float4*)(Ap + 4 * i) : make_float4(0.f, 0.f, 0.f, 0.f);
#pragma unroll
    for (int j = 0; j < 2; j++) {
        sB0[j] = *(const float4*)(Bp + 64 * j);
        sB1[j] = *(const float4*)(Bp + HC + 64 * j);
    }

    for (int kt = 0; kt < F_IN / 32; kt++) {
#pragma unroll
        for (int i = 0; i < 4; i++) {
            int k2 = (akoff >> 1) + 2 * i;
            unsigned h0, l0, h1, l1;
            split2(sA[i].x, sA[i].y, h0, l0);
            split2(sA[i].z, sA[i].w, h1, l1);
            As_h[k2][arow] = h0;     As_l[k2][arow] = l0;
            As_h[k2 + 1][arow] = h1; As_l[k2 + 1][arow] = l1;
        }
#pragma unroll
        for (int j = 0; j < 2; j++) {
            int c = bcol + 64 * j;
            unsigned h, l;
            split2(sB0[j].x, sB1[j].x, h, l); Bs_h[bk2][c] = h;     Bs_l[bk2][c] = l;
            split2(sB0[j].y, sB1[j].y, h, l); Bs_h[bk2][c + 1] = h; Bs_l[bk2][c + 1] = l;
            split2(sB0[j].z, sB1[j].z, h, l); Bs_h[bk2][c + 2] = h; Bs_l[bk2][c + 2] = l;
            split2(sB0[j].w, sB1[j].w, h, l); Bs_h[bk2][c + 3] = h; Bs_l[bk2][c + 3] = l;
        }
        __syncthreads();
        if (kt < F_IN / 32 - 1) {
            const float* Ap2 = Ap + 32 * (kt + 1);
#pragma unroll
            for (int i = 0; i < 4; i++)
                sA[i] = aval ? *(const float4*)(Ap2 + 4 * i) : make_float4(0.f, 0.f, 0.f, 0.f);
            const float* Bp2 = Bp + (size_t)32 * HC * (kt + 1);
#pragma unroll
            for (int j = 0; j < 2; j++) {
                sB0[j] = *(const float4*)(Bp2 + 64 * j);
                sB1[j] = *(const float4*)(Bp2 + HC + 64 * j);
            }
        }
#pragma unroll
        for (int s = 0; s < 2; s++) {
            unsigned ah[4][4], al[4][4];
#pragma unroll
            for (int mt = 0; mt < 4; mt++) {
                int m0 = wm * 64 + mt * 16 + g;
                ah[mt][0] = As_h[s * 8 + t][m0];         al[mt][0] = As_l[s * 8 + t][m0];
                ah[mt][1] = As_h[s * 8 + t][m0 + 8];     al[mt][1] = As_l[s * 8 + t][m0 + 8];
                ah[mt][2] = As_h[s * 8 + t + 4][m0];     al[mt][2] = As_l[s * 8 + t + 4][m0];
                ah[mt][3] = As_h[s * 8 + t + 4][m0 + 8]; al[mt][3] = As_l[s * 8 + t + 4][m0 + 8];
            }
#pragma unroll
            for (int nt = 0; nt < 4; nt++) {
                int n0 = wn * 32 + nt * 8 + g;
                unsigned bh0 = Bs_h[s * 8 + t][n0], bh1 = Bs_h[s * 8 + t + 4][n0];
                unsigned bl0 = Bs_l[s * 8 + t][n0], bl1 = Bs_l[s * 8 + t + 4][n0];
#pragma unroll
                for (int mt = 0; mt < 4; mt++) {
                    mma_bf16(acc[mt][nt], ah[mt], bh0, bh1);
                    mma_bf16(acc[mt][nt], ah[mt], bl0, bl1);
                    mma_bf16(acc[mt][nt], al[mt], bh0, bh1);
                }
            }
        }
        __syncthreads();
    }
    // store C tile as fp16
#pragma unroll
    for (int mt = 0; mt < 4; mt++) {
        int r0 = by * 128 + wm * 64 + mt * 16 + g;
        int r1 = r0 + 8;
#pragma unroll
        for (int nt = 0; nt < 4; nt++) {
            int col = bx * 128 + wn * 32 + nt * 8 + 2 * t;
            if (r0 < M) *(__half2*)(C + (size_t)r0 * HC + col) = __floats2half2_rn(acc[mt][nt][0], acc[mt][nt][1]);
            if (r1 < M) *(__half2*)(C + (size_t)r1 * HC + col) = __floats2half2_rn(acc[mt][nt][2], acc[mt][nt][3]);
        }
    }
    // fused score epilogue (fp32 accumulators -> exact scores)
    const float* as = att_s + bx * CDIM;
    const float* ad = att_d + bx * CDIM;
    float pss[4][2] = {}, psd[4][2] = {};
#pragma unroll
    for (int nt = 0; nt < 4; nt++) {
        int col = wn * 32 + nt * 8 + 2 * t;
        float a0 = as[col], a1 = as[col + 1];
        float e0 = ad[col], e1 = ad[col + 1];
#pragma unroll
        for (int mt = 0; mt < 4; mt++) {
            pss[mt][0] += acc[mt][nt][0] * a0 + acc[mt][nt][1] * a1;
            pss[mt][1] += acc[mt][nt][2] * a0 + acc[mt][nt][3] * a1;
            psd[mt][0] += acc[mt][nt][0] * e0 + acc[mt][nt][1] * e1;
            psd[mt][1] += acc[mt][nt][2] * e0 + acc[mt][nt][3] * e1;
        }
    }
#pragma unroll
    for (int o = 1; o <= 2; o <<= 1)
#pragma unroll
        for (int mt = 0; mt < 4; mt++)
#pragma unroll
            for (int rh = 0; rh < 2; rh++) {
                pss[mt][rh] += __shfl_xor_sync(0xFFFFFFFFu, pss[mt][rh], o);
                psd[mt][rh] += __shfl_xor_sync(0xFFFFFFFFu, psd[mt][rh], o);
            }
    if (t == 0) {
#pragma unroll
        for (int mt = 0; mt < 4; mt++)
#pragma unroll
            for (int rh = 0; rh < 2; rh++) {
                int rl = wm * 64 + mt * 16 + rh * 8 + g;
                sred[wn][rl][0] = pss[mt][rh];
                sred[wn][rl][1] = psd[mt][rh];
            }
    }
    __syncthreads();
    {
        int rl = tid >> 1, which = tid & 1;
        float sum = sred[0][rl][which] + sred[1][rl][which] + sred[2][rl][which] + sred[3][rl][which];
        int row = by * 128 + rl;
        if (row < M) {
            if (which) d_adst1[row * HEADS + bx] = sum;
            else       d_asrc1[row * HEADS + bx] = sum;
        }
    }
}

// ---------------- layer-1 aggregation: one pass per 4-head group (30.7 MB L2-resident working set)
// block = node (128 threads = 4 warps), warp = head h0+w; fused bias+ELU, fp16 output
__global__ __launch_bounds__(128) void agg1_k(const float* __restrict__ b1, int h0)
{
    __shared__ int   s_src[32];
    __shared__ float s_w[4][32];
    const int n = blockIdx.x;
    const int hw = threadIdx.x >> 5, lane = threadIdx.x & 31;
    const int h = h0 + hw;
    const float adst = d_adst1[n * HEADS + h];
    const float ws = __expf(lrelu(d_asrc1[n * HEADS + h] + adst));
    const size_t rowoff = (size_t)h * CDIM + lane * 4;

    float4 acc = make_float4(0.f, 0.f, 0.f, 0.f);
    acc_h4(acc, d_h1h + (size_t)n * HC + rowoff, ws);
    float denom = ws;

    const int beg = d_rowptr[n], end = d_rowptr[n + 1];
    for (int c0 = beg; c0 < end; c0 += 32) {
        const int m = min(32, end - c0);
        if (hw == 0 && lane < m) s_src[lane] = d_csr_src[c0 + lane];
        __syncthreads();
        if (lane < m)
            s_w[hw][lane] = __expf(lrelu(__ldg(&d_asrc1[s_src[lane] * HEADS + h]) + adst));
        __syncwarp();
        int jm = m & ~3;
        for (int j = 0; j < jm; j += 4) {
            int s0 = s_src[j], s1 = s_src[j + 1], s2 = s_src[j + 2], s3 = s_src[j + 3];
            float w0 = s_w[hw][j], w1 = s_w[hw][j + 1], w2 = s_w[hw][j + 2], w3 = s_w[hw][j + 3];
            uint2 r0 = *(const uint2*)(d_h1h + (size_t)s0 * HC + rowoff);
            uint2 r1 = *(const uint2*)(d_h1h + (size_t)s1 * HC + rowoff);
            uint2 r2 = *(const uint2*)(d_h1h + (size_t)s2 * HC + rowoff);
            uint2 r3 = *(const uint2*)(d_h1h + (size_t)s3 * HC + rowoff);
            float2 a0 = __half22float2(*reinterpret_cast<const __half2*>(&r0.x));
            float2 b0 = __half22float2(*reinterpret_cast<const __half2*>(&r0.y));
            float2 a1 = __half22float2(*reinterpret_cast<const __half2*>(&r1.x));
            float2 b1v = __half22float2(*reinterpret_cast<const __half2*>(&r1.y));
            float2 a2 = __half22float2(*reinterpret_cast<const __half2*>(&r2.x));
            float2 b2v = __half22float2(*reinterpret_cast<const __half2*>(&r2.y));
            float2 a3 = __half22float2(*reinterpret_cast<const __half2*>(&r3.x));
            float2 b3v = __half22float2(*reinterpret_cast<const __half2*>(&r3.y));
            acc.x += w0 * a0.x + w1 * a1.x + w2 * a2.x + w3 * a3.x;
            acc.y += w0 * a0.y + w1 * a1.y + w2 * a2.y + w3 * a3.y;
            acc.z += w0 * b0.x + w1 * b1v.x + w2 * b2v.x + w3 * b3v.x;
            acc.w += w0 * b0.y + w1 * b1v.y + w2 * b2v.y + w3 * b3v.y;
            denom += w0 + w1 + w2 + w3;
        }
        for (int j = jm; j < m; j++) {
            float w = s_w[hw][j];
            acc_h4(acc, d_h1h + (size_t)s_src[j] * HC + rowoff, w);
            denom += w;
        }
        __syncthreads();
    }
    float inv = 1.f / (denom + 1e-16f);
    float4 bv = *(const float4*)(b1 + rowoff);
    float4 r;
    r.x = acc.x * inv + bv.x;
    r.y = acc.y * inv + bv.y;
    r.z = acc.z * inv + bv.z;
    r.w = acc.w * inv + bv.w;
    r.x = r.x > 0.f ? r.x : expm1f(r.x);
    r.y = r.y > 0.f ? r.y : expm1f(r.y);
    r.z = r.z > 0.f ? r.z : expm1f(r.z);
    r.w = r.w > 0.f ? r.w : expm1f(r.w);
    __half2 o0 = __floats2half2_rn(r.x, r.y);
    __half2 o1 = __floats2half2_rn(r.z, r.w);
    unsigned long long pack = (unsigned long long)*reinterpret_cast<unsigned*>(&o0)
                            | ((unsigned long long)*reinterpret_cast<unsigned*>(&o1) << 32);
    __stcs((unsigned long long*)(d_agg1h + (size_t)n * HC + rowoff), pack);
}

// ---------------- GEMM2 (fp16 A, already bias+ELU'd) + fused attention scores ----------------
__global__ __launch_bounds__(256, 1) void gemm2_mma(
    const __half* __restrict__ A, const float* __restrict__ B,
    const float* __restrict__ att_s, const float* __restrict__ att_d,
    float* __restrict__ C, int M)
{
    __shared__ unsigned As_h[16][136], As_l[16][136];
    __shared__ unsigned Bs_h[16][72], Bs_l[16][72];
    __shared__ float sred[2][128][2];
    const int tid = threadIdx.x, lane = tid & 31, wid = tid >> 5;
    const int g = lane >> 2, t = lane & 3;
    const int wm = wid >> 1, wn = wid & 1;     // 4x2 warps, warp tile 32x32
    const int by = blockIdx.x;
    float acc[2][4][4] = {};

    const int arow = tid >> 1, akoff = (tid & 1) * 16;
    const int gArow = by * 128 + arow;
    const bool aval = gArow < M;
    const __half* Ap = A + (size_t)gArow * HC + akoff;
    const int bk2 = tid >> 4, bcol = (tid & 15) * 4;
    const float* Bp = B + (size_t)(2 * bk2) * OUTD + bcol;

    float4 sA[4], sB0, sB1;
    {
#pragma unroll
        for (int i = 0; i < 4; i++) {
            if (aval) {
                uint2 raw = __ldcs((const uint2*)(Ap + 4 * i));
                float2 f0 = __half22float2(*reinterpret_cast<const __half2*>(&raw.x));
                float2 f1 = __half22float2(*reinterpret_cast<const __half2*>(&raw.y));
                sA[i] = make_float4(f0.x, f0.y, f1.x, f1.y);
            } else sA[i] = make_float4(0.f, 0.f, 0.f, 0.f);
        }
        sB0 = *(const float4*)Bp;
        sB1 = *(const float4*)(Bp + OUTD);
    }

    for (int kt = 0; kt < HC / 32; kt++) {
#pragma unroll
        for (int i = 0; i < 4; i++) {
            int k2 = (akoff >> 1) + 2 * i;
            unsigned h0, l0, h1, l1;
            split2(sA[i].x, sA[i].y, h0, l0);
            split2(sA[i].z, sA[i].w, h1, l1);
            As_h[k2][arow] = h0;     As_l[k2][arow] = l0;
            As_h[k2 + 1][arow] = h1; As_l[k2 + 1][arow] = l1;
        }
        {
            unsigned h, l;
            split2(sB0.x, sB1.x, h, l); Bs_h[bk2][bcol] = h;     Bs_l[bk2][bcol] = l;
            split2(sB0.y, sB1.y, h, l); Bs_h[bk2][bcol + 1] = h; Bs_l[bk2][bcol + 1] = l;
            split2(sB0.z, sB1.z, h, l); Bs_h[bk2][bcol + 2] = h; Bs_l[bk2][bcol + 2] = l;
            split2(sB0.w, sB1.w, h, l); Bs_h[bk2][bcol + 3] = h; Bs_l[bk2][bcol + 3] = l;
        }
        __syncthreads();
        if (kt < HC / 32 - 1) {
            const __half* Ap2 = Ap + 32 * (kt + 1);
#pragma unroll
            for (int i = 0; i < 4; i++) {
                if (aval) {
                    uint2 raw = __ldcs((const uint2*)(Ap2 + 4 * i));
                    float2 f0 = __half22float2(*reinterpret_cast<const __half2*>(&raw.x));
                    float2 f1 = __half22float2(*reinterpret_cast<const __half2*>(&raw.y));
                    sA[i] = make_float4(f0.x, f0.y, f1.x, f1.y);
                } else sA[i] = make_float4(0.f, 0.f, 0.f, 0.f);
            }
            const float* Bp2 = Bp + (size_t)32 * OUTD * (kt + 1);
            sB0 = *(const float4*)Bp2;
            sB1 = *(const float4*)(Bp2 + OUTD);
        }
#pragma unroll
        for (int s = 0; s < 2; s++) {
            unsigned ah[2][4], al[2][4];
#pragma unroll
            for (int mt = 0; mt < 2; mt++) {
                int m0 = wm * 32 + mt * 16 + g;
                ah[mt][0] = As_h[s * 8 + t][m0];         al[mt][0] = As_l[s * 8 + t][m0];
                ah[mt][1] = As_h[s * 8 + t][m0 + 8];     al[mt][1] = As_l[s * 8 + t][m0 + 8];
                ah[mt][2] = As_h[s * 8 + t + 4][m0];     al[mt][2] = As_l[s * 8 + t + 4][m0];
                ah[mt][3] = As_h[s * 8 + t + 4][m0 + 8]; al[mt][3] = As_l[s * 8 + t + 4][m0 + 8];
            }
#pragma unroll
            for (int nt = 0; nt < 4; nt++) {
                int n0 = wn * 32 + nt * 8 + g;
                unsigned bh0 = Bs_h[s * 8 + t][n0], bh1 = Bs_h[s * 8 + t + 4][n0];
                unsigned bl0 = Bs_l[s * 8 + t][n0], bl1 = Bs_l[s * 8 + t + 4][n0];
#pragma unroll
                for (int mt = 0; mt < 2; mt++) {
                    mma_bf16(acc[mt][nt], ah[mt], bh0, bh1);
                    mma_bf16(acc[mt][nt], ah[mt], bl0, bl1);
                    mma_bf16(acc[mt][nt], al[mt], bh0, bh1);
                }
            }
        }
        __syncthreads();
    }
#pragma unroll
    for (int mt = 0; mt < 2; mt++) {
        int r0 = by * 128 + wm * 32 + mt * 16 + g;
        int r1 = r0 + 8;
#pragma unroll
        for (int nt = 0; nt < 4; nt++) {
            int col = wn * 32 + nt * 8 + 2 * t;
            if (r0 < M) *(float2*)(C + (size_t)r0 * OUTD + col) = make_float2(acc[mt][nt][0], acc[mt][nt][1]);
            if (r1 < M) *(float2*)(C + (size_t)r1 * OUTD + col) = make_float2(acc[mt][nt][2], acc[mt][nt][3]);
        }
    }
    // fused score epilogue
    float pss[2][2] = {}, psd[2][2] = {};
#pragma unroll
    for (int nt = 0; nt < 4; nt++) {
        int col = wn * 32 + nt * 8 + 2 * t;
        float a0 = att_s[col], a1 = att_s[col + 1];
        float e0 = att_d[col], e1 = att_d[col + 1];
#pragma unroll
        for (int mt = 0; mt < 2; mt++) {
            pss[mt][0] += acc[mt][nt][0] * a0 + acc[mt][nt][1] * a1;
            pss[mt][1] += acc[mt][nt][2] * a0 + acc[mt][nt][3] * a1;
            psd[mt][0] += acc[mt][nt][0] * e0 + acc[mt][nt][1] * e1;
            psd[mt][1] += acc[mt][nt][2] * e0 + acc[mt][nt][3] * e1;
        }
    }
#pragma unroll
    for (int o = 1; o <= 2; o <<= 1)
#pragma unroll
        for (int mt = 0; mt < 2; mt++)
#pragma unroll
            for (int rh = 0; rh < 2; rh++) {
                pss[mt][rh] += __shfl_xor_sync(0xFFFFFFFFu, pss[mt][rh], o);
                psd[mt][rh] += __shfl_xor_sync(0xFFFFFFFFu, psd[mt][rh], o);
            }
    if (t == 0) {
#pragma unroll
        for (int mt = 0; mt < 2; mt++)
#pragma unroll
            for (int rh = 0; rh < 2; rh++) {
                int rl = wm * 32 + mt * 16 + rh * 8 + g;
                sred[wn][rl][0] = pss[mt][rh];
                sred[wn][rl][1] = psd[mt][rh];
            }
    }
    __syncthreads();
    {
        int rl = tid >> 1, which = tid & 1;
        float sum = sred[0][rl][which] + sred[1][rl][which];
        int row = by * 128 + rl;
        if (row < M) {
            if (which) d_adst2[row] = sum;
            else       d_asrc2[row] = sum;
        }
    }
}

// ---------------- layer-2 one-pass aggregation + bias + log_softmax (MLP-4) ----------------
__global__ __launch_bounds__(256) void agg2_k(float* __restrict__ out, const float* __restrict__ b2)
{
    int n = blockIdx.x * 8 + (threadIdx.x >> 5);
    int lane = threadIdx.x & 31;
    if (n >= N_NODES) return;
    float adst = d_adst2[n];
    float ws = __expf(lrelu(d_asrc2[n] + adst));
    const float* hp = d_h2 + (size_t)n * OUTD;
    float acc0 = ws * hp[lane], acc1 = ws * hp[lane + 32];
    float denom = ws;
    const int beg = d_rowptr[n], end = d_rowptr[n + 1];
    int j = beg;
    for (; j + 4 <= end; j += 4) {
        int s0 = __ldg(&d_csr_src[j]);
        int s1 = __ldg(&d_csr_src[j + 1]);
        int s2 = __ldg(&d_csr_src[j + 2]);
        int s3 = __ldg(&d_csr_src[j + 3]);
        float w0 = __expf(lrelu(__ldg(&d_asrc2[s0]) + adst));
        float w1 = __expf(lrelu(__ldg(&d_asrc2[s1]) + adst));
        float w2 = __expf(lrelu(__ldg(&d_asrc2[s2]) + adst));
        float w3 = __expf(lrelu(__ldg(&d_asrc2[s3]) + adst));
        const float* p0 = d_h2 + (size_t)s0 * OUTD;
        const float* p1 = d_h2 + (size_t)s1 * OUTD;
        const float* p2 = d_h2 + (size_t)s2 * OUTD;
        const float* p3 = d_h2 + (size_t)s3 * OUTD;
        float f00 = p0[lane], f01 = p0[lane + 32];
        float f10 = p1[lane], f11 = p1[lane + 32];
        float f20 = p2[lane], f21 = p2[lane + 32];
        float f30 = p3[lane], f31 = p3[lane + 32];
        acc0 += w0 * f00 + w1 * f10 + w2 * f20 + w3 * f30;
        acc1 += w0 * f01 + w1 * f11 + w2 * f21 + w3 * f31;
        denom += w0 + w1 + w2 + w3;
    }
    for (; j < end; j++) {
        int s = __ldg(&d_csr_src[j]);
        float w = __expf(lrelu(__ldg(&d_asrc2[s]) + adst));
        const float* sp = d_h2 + (size_t)s * OUTD;
        acc0 += w * sp[lane];
        acc1 += w * sp[lane + 32];
        denom += w;
    }
    float inv = 1.f / (denom + 1e-16f);
    float x0 = acc0 * inv + b2[lane];
    float x1 = acc1 * inv + b2[lane + 32];
    float mx = fmaxf(x0, x1);
#pragma unroll
    for (int o = 16; o; o >>= 1) mx = fmaxf(mx, __shfl_xor_sync(0xFFFFFFFFu, mx, o));
    float sm = __expf(x0 - mx) + __expf(x1 - mx);
#pragma unroll
    for (int o = 16; o; o >>= 1) sm += __shfl_xor_sync(0xFFFFFFFFu, sm, o);
    float lse = mx + logf(sm);
    out[(size_t)n * OUTD + lane] = x0 - lse;
    out[(size_t)n * OUTD + lane + 32] = x1 - lse;
}

// ---------------- launch ----------------
extern "C" void kernel_launch(void* const* d_in, const int* in_sizes, int n_in,
                              void* d_out, int out_size)
{
    const float* x   = (const float*)d_in[0];
    const int*   ei  = (const int*)  d_in[1];
    const float* W1  = (const float*)d_in[2];
    const float* as1 = (const float*)d_in[3];
    const float* ad1 = (const float*)d_in[4];
    const float* b1  = (const float*)d_in[5];
    const float* W2  = (const float*)d_in[6];
    const float* as2 = (const float*)d_in[7];
    const float* ad2 = (const float*)d_in[8];
    const float* b2  = (const float*)d_in[9];
    float* out = (float*)d_out;

    __half *h1p, *agg1hp;
    float *h2p;
    cudaGetSymbolAddress((void**)&h1p,    d_h1h);
    cudaGetSymbolAddress((void**)&agg1hp, d_agg1h);
    cudaGetSymbolAddress((void**)&h2p,    d_h2);

    // CSR build
    zero_deg_k<<<(N_NODES + 255) / 256, 256>>>();
    hist_k<<<(N_EDGES + 255) / 256, 256>>>(ei);
    scan_k<<<1, 1024>>>();
    scatter_k<<<(N_EDGES + 255) / 256, 256>>>(ei);

    // layer 1
    {
        dim3 g(HC / 128, (N_NODES + 127) / 128);
        gemm1_mma<<<g, 256>>>(x, W1, as1, ad1, h1p, N_NODES);
    }
    // two serialized head-group passes: 30.7 MB working set each (L2-resident)
    agg1_k<<<N_NODES, 128>>>(b1, 0);
    agg1_k<<<N_NODES, 128>>>(b1, 4);

    // layer 2
    gemm2_mma<<<(N_NODES + 127) / 128, 256>>>(agg1hp, W2, as2, ad2, h2p, N_NODES);
    agg2_k<<<(N_NODES + 7) / 8, 256>>>(out, b2);
}

// round 11
// speedup vs baseline: 2.9421x; 1.2033x over previous
#include <cuda_runtime.h>
#include <cuda_bf16.h>
#include <cuda_fp16.h>
#include <math.h>

#define N_NODES 30000
#define F_IN    256
#define N_EDGES 300000
#define HEADS   8
#define CDIM    128
#define HC      1024
#define OUTD    64
#define NEG_SLOPE 0.2f

// ---------------- scratch ----------------
__device__ __align__(256) __half d_h1h  [(size_t)N_NODES * HC];  // 61.4 MB
__device__ __align__(256) __half d_agg1h[(size_t)N_NODES * HC];  // 61.4 MB (post bias+ELU)
__device__ __align__(256) float  d_asrc1[N_NODES * HEADS];
__device__ __align__(256) float  d_adst1[N_NODES * HEADS];
__device__ __align__(256) float  d_h2  [(size_t)N_NODES * OUTD];
__device__ __align__(256) float  d_asrc2[N_NODES];
__device__ __align__(256) float  d_adst2[N_NODES];
__device__ __align__(256) int    d_deg   [N_NODES];
__device__ __align__(256) int    d_rowptr[N_NODES + 1];
__device__ __align__(256) int    d_cursor[N_NODES];
__device__ __align__(256) int    d_csr_src[N_EDGES];

// ---------------- helpers ----------------
__device__ __forceinline__ float lrelu(float x) { return x > 0.f ? x : NEG_SLOPE * x; }

// pack two floats to fp16x2
__device__ __forceinline__ unsigned packh2(float x, float y) {
    __half2 p = __floats2half2_rn(x, y);
    return *reinterpret_cast<unsigned*>(&p);
}

// split two fp32 into fp16x2 hi and fp16x2 lo (residual): hi+lo captures ~22 mantissa bits
__device__ __forceinline__ void split2h(float x, float y, unsigned& h, unsigned& l) {
    __half hx = __float2half_rn(x);
    __half hy = __float2half_rn(y);
    float rx = x - __half2float(hx);
    float ry = y - __half2float(hy);
    __half lx = __float2half_rn(rx);
    __half ly = __float2half_rn(ry);
    h = (unsigned)__half_as_ushort(hx) | ((unsigned)__half_as_ushort(hy) << 16);
    l = (unsigned)__half_as_ushort(lx) | ((unsigned)__half_as_ushort(ly) << 16);
}

__device__ __forceinline__ void mma_f16(float* c, const unsigned* a, unsigned b0, unsigned b1) {
    asm volatile("mma.sync.aligned.m16n8k16.row.col.f32.f16.f16.f32 "
                 "{%0,%1,%2,%3}, {%4,%5,%6,%7}, {%8,%9}, {%0,%1,%2,%3};\n"
                 : "+f"(c[0]), "+f"(c[1]), "+f"(c[2]), "+f"(c[3])
                 : "r"(a[0]), "r"(a[1]), "r"(a[2]), "r"(a[3]), "r"(b0), "r"(b1));
}

__device__ __forceinline__ void acc_h4(float4& acc, const __half* base, float w) {
    uint2 raw = *(const uint2*)base;
    float2 u0 = __half22float2(*reinterpret_cast<const __half2*>(&raw.x));
    float2 u1 = __half22float2(*reinterpret_cast<const __half2*>(&raw.y));
    acc.x += w * u0.x; acc.y += w * u0.y; acc.z += w * u1.x; acc.w += w * u1.y;
}

// ---------------- CSR build ----------------
__global__ void zero_deg_k()
{
    int i = blockIdx.x * blockDim.x + threadIdx.x;
    if (i < N_NODES) d_deg[i] = 0;
}

__global__ void hist_k(const int* __restrict__ ei)
{
    int e = blockIdx.x * blockDim.x + threadIdx.x;
    if (e >= N_EDGES) return;
    atomicAdd(&d_deg[ei[N_EDGES + e]], 1);
}

__global__ __launch_bounds__(1024) void scan_k()
{
    __shared__ int wsum[32];
    const int tid = threadIdx.x;
    const int ITEMS = (N_NODES + 1023) / 1024;   // 30
    int base = tid * ITEMS;
    int sum = 0;
#pragma unroll 4
    for (int i = 0; i < ITEMS; i++) {
        int idx = base + i;
        if (idx < N_NODES) sum += d_deg[idx];
    }
    int lane = tid & 31, wid = tid >> 5;
    int v = sum;
#pragma unroll
    for (int o = 1; o < 32; o <<= 1) {
        int y = __shfl_up_sync(0xFFFFFFFFu, v, o);
        if (lane >= o) v += y;
    }
    if (lane == 31) wsum[wid] = v;
    __syncthreads();
    if (wid == 0) {
        int w = wsum[lane];
#pragma unroll
        for (int o = 1; o < 32; o <<= 1) {
            int y = __shfl_up_sync(0xFFFFFFFFu, w, o);
            if (lane >= o) w += y;
        }
        wsum[lane] = w;
    }
    __syncthreads();
    int run = v - sum + (wid ? wsum[wid - 1] : 0);
#pragma unroll 4
    for (int i = 0; i < ITEMS; i++) {
        int idx = base + i;
        if (idx < N_NODES) {
            d_rowptr[idx] = run;
            d_cursor[idx] = run;
            run += d_deg[idx];
        }
    }
    if (tid == 1023) d_rowptr[N_NODES] = wsum[31];
}

__global__ void scatter_k(const int* __restrict__ ei)
{
    int e = blockIdx.x * blockDim.x + threadIdx.x;
    if (e >= N_EDGES) return;
    int s = ei[e], d = ei[N_EDGES + e];
    int p = atomicAdd(&d_cursor[d], 1);
    d_csr_src[p] = s;
}

// ---------------- GEMM1 (A fp16, B fp16 hi+lo, 2-term mma) + fused scores, fp16 C ----------------
__global__ __launch_bounds__(256, 1) void gemm1_mma(
    const float* __restrict__ A, const float* __restrict__ B,
    const float* __restrict__ att_s, const float* __restrict__ att_d,
    __half* __restrict__ C, int M)
{
    __shared__ unsigned As_f[16][136];
    __shared__ unsigned Bs_h[16][136], Bs_l[16][136];
    __shared__ float sred[4][128][2];
    const int tid = threadIdx.x, lane = tid & 31, wid = tid >> 5;
    const int g = lane >> 2, t = lane & 3;
    const int wm = wid >> 2, wn = wid & 3;     // 2x4 warps, warp tile 64x32
    const int by = blockIdx.y, bx = blockIdx.x;
    float acc[4][4][4] = {};

    const int arow = tid >> 1, akoff = (tid & 1) * 16;
    const int gArow = by * 128 + arow;
    const bool aval = gArow < M;
    const float* Ap = A + (size_t)gArow * F_IN + akoff;
    const int bk2 = tid >> 4, bcol = (tid & 15) * 4;
    const float* Bp = B + (size_t)(2 * bk2) * HC + bx * 128 + bcol;

    float4 sA[4], sB0[2], sB1[2];
#pragma unroll
    for (int i = 0; i < 4; i++)
        sA[i] = aval ? *(const float4*)(Ap + 4 * i) : make_float4(0.f, 0.f, 0.f, 0.f);
#pragma unroll
    for (int j = 0; j < 2; j++) {
        sB0[j] = *(const float4*)(Bp + 64 * j);
        sB1[j] = *(const float4*)(Bp + HC + 64 * j);
    }

    for (int kt = 0; kt < F_IN / 32; kt++) {
#pragma unroll
        for (int i = 0; i < 4; i++) {
            int k2 = (akoff >> 1) + 2 * i;
            As_f[k2][arow]     = packh2(sA[i].x, sA[i].y);
            As_f[k2 + 1][arow] = packh2(sA[i].z, sA[i].w);
        }
#pragma unroll
        for (int j = 0; j < 2; j++) {
            int c = bcol + 64 * j;
            unsigned h, l;
            split2h(sB0[j].x, sB1[j].x, h, l); Bs_h[bk2][c] = h;     Bs_l[bk2][c] = l;
            split2h(sB0[j].y, sB1[j].y, h, l); Bs_h[bk2][c + 1] = h; Bs_l[bk2][c + 1] = l;
            split2h(sB0[j].z, sB1[j].z, h, l); Bs_h[bk2][c + 2] = h; Bs_l[bk2][c + 2] = l;
            split2h(sB0[j].w, sB1[j].w, h, l); Bs_h[bk2][c + 3] = h; Bs_l[bk2][c + 3] = l;
        }
        __syncthreads();
        if (kt < F_IN / 32 - 1) {
            const float* Ap2 = Ap + 32 * (kt + 1);
#pragma unroll
            for (int i = 0; i < 4; i++)
                sA[i] = aval ? *(const float4*)(Ap2 + 4 * i) : make_float4(0.f, 0.f, 0.f, 0.f);
            const float* Bp2 = Bp + (size_t)32 * HC * (kt + 1);
#pragma unroll
            for (int j = 0; j < 2; j++) {
                sB0[j] = *(const float4*)(Bp2 + 64 * j);
                sB1[j] = *(const float4*)(Bp2 + HC + 64 * j);
            }
        }
#pragma unroll
        for (int s = 0; s < 2; s++) {
            unsigned ah[4][4];
#pragma unroll
            for (int mt = 0; mt < 4; mt++) {
                int m0 = wm * 64 + mt * 16 + g;
                ah[mt][0] = As_f[s * 8 + t][m0];
                ah[mt][1] = As_f[s * 8 + t][m0 + 8];
                ah[mt][2] = As_f[s * 8 + t + 4][m0];
                ah[mt][3] = As_f[s * 8 + t + 4][m0 + 8];
            }
#pragma unroll
            for (int nt = 0; nt < 4; nt++) {
                int n0 = wn * 32 + nt * 8 + g;
                unsigned bh0 = Bs_h[s * 8 + t][n0], bh1 = Bs_h[s * 8 + t + 4][n0];
                unsigned bl0 = Bs_l[s * 8 + t][n0], bl1 = Bs_l[s * 8 + t + 4][n0];
#pragma unroll
                for (int mt = 0; mt < 4; mt++) {
                    mma_f16(acc[mt][nt], ah[mt], bh0, bh1);
                    mma_f16(acc[mt][nt], ah[mt], bl0, bl1);
                }
            }
        }
        __syncthreads();
    }
    // store C tile as fp16
#pragma unroll
    for (int mt = 0; mt < 4; mt++) {
        int r0 = by * 128 + wm * 64 + mt * 16 + g;
        int r1 = r0 + 8;
#pragma unroll
        for (int nt = 0; nt < 4; nt++) {
            int col = bx * 128 + wn * 32 + nt * 8 + 2 * t;
            if (r0 < M) *(__half2*)(C + (size_t)r0 * HC + col) = __floats2half2_rn(acc[mt][nt][0], acc[mt][nt][1]);
            if (r1 < M) *(__half2*)(C + (size_t)r1 * HC + col) = __floats2half2_rn(acc[mt][nt][2], acc[mt][nt][3]);
        }
    }
    // fused score epilogue (fp32 accumulators)
    const float* as = att_s + bx * CDIM;
    const float* ad = att_d + bx * CDIM;
    float pss[4][2] = {}, psd[4][2] = {};
#pragma unroll
    for (int nt = 0; nt < 4; nt++) {
        int col = wn * 32 + nt * 8 + 2 * t;
        float a0 = as[col], a1 = as[col + 1];
        float e0 = ad[col], e1 = ad[col + 1];
#pragma unroll
        for (int mt = 0; mt < 4; mt++) {
            pss[mt][0] += acc[mt][nt][0] * a0 + acc[mt][nt][1] * a1;
            pss[mt][1] += acc[mt][nt][2] * a0 + acc[mt][nt][3] * a1;
            psd[mt][0] += acc[mt][nt][0] * e0 + acc[mt][nt][1] * e1;
            psd[mt][1] += acc[mt][nt][2] * e0 + acc[mt][nt][3] * e1;
        }
    }
#pragma unroll
    for (int o = 1; o <= 2; o <<= 1)
#pragma unroll
        for (int mt = 0; mt < 4; mt++)
#pragma unroll
            for (int rh = 0; rh < 2; rh++) {
                pss[mt][rh] += __shfl_xor_sync(0xFFFFFFFFu, pss[mt][rh], o);
                psd[mt][rh] += __shfl_xor_sync(0xFFFFFFFFu, psd[mt][rh], o);
            }
    if (t == 0) {
#pragma unroll
        for (int mt = 0; mt < 4; mt++)
#pragma unroll
            for (int rh = 0; rh < 2; rh++) {
                int rl = wm * 64 + mt * 16 + rh * 8 + g;
                sred[wn][rl][0] = pss[mt][rh];
                sred[wn][rl][1] = psd[mt][rh];
            }
    }
    __syncthreads();
    {
        int rl = tid >> 1, which = tid & 1;
        float sum = sred[0][rl][which] + sred[1][rl][which] + sred[2][rl][which] + sred[3][rl][which];
        int row = by * 128 + rl;
        if (row < M) {
            if (which) d_adst1[row * HEADS + bx] = sum;
            else       d_asrc1[row * HEADS + bx] = sum;
        }
    }
}

// ---------------- layer-1 aggregation: one pass per 4-head group, fused bias+ELU, fp16 out ----------------
__global__ __launch_bounds__(128) void agg1_k(const float* __restrict__ b1, int h0)
{
    __shared__ int   s_src[32];
    __shared__ float s_w[4][32];
    const int n = blockIdx.x;
    const int hw = threadIdx.x >> 5, lane = threadIdx.x & 31;
    const int h = h0 + hw;
    const float adst = d_adst1[n * HEADS + h];
    const float ws = __expf(lrelu(d_asrc1[n * HEADS + h] + adst));
    const size_t rowoff = (size_t)h * CDIM + lane * 4;

    float4 acc = make_float4(0.f, 0.f, 0.f, 0.f);
    acc_h4(acc, d_h1h + (size_t)n * HC + rowoff, ws);
    float denom = ws;

    const int beg = d_rowptr[n], end = d_rowptr[n + 1];
    for (int c0 = beg; c0 < end; c0 += 32) {
        const int m = min(32, end - c0);
        if (hw == 0 && lane < m) s_src[lane] = d_csr_src[c0 + lane];
        __syncthreads();
        if (lane < m)
            s_w[hw][lane] = __expf(lrelu(__ldg(&d_asrc1[s_src[lane] * HEADS + h]) + adst));
        __syncwarp();
        int jm = m & ~3;
        for (int j = 0; j < jm; j += 4) {
            int s0 = s_src[j], s1 = s_src[j + 1], s2 = s_src[j + 2], s3 = s_src[j + 3];
            float w0 = s_w[hw][j], w1 = s_w[hw][j + 1], w2 = s_w[hw][j + 2], w3 = s_w[hw][j + 3];
            uint2 r0 = *(const uint2*)(d_h1h + (size_t)s0 * HC + rowoff);
            uint2 r1 = *(const uint2*)(d_h1h + (size_t)s1 * HC + rowoff);
            uint2 r2 = *(const uint2*)(d_h1h + (size_t)s2 * HC + rowoff);
            uint2 r3 = *(const uint2*)(d_h1h + (size_t)s3 * HC + rowoff);
            float2 a0 = __half22float2(*reinterpret_cast<const __half2*>(&r0.x));
            float2 b0 = __half22float2(*reinterpret_cast<const __half2*>(&r0.y));
            float2 a1 = __half22float2(*reinterpret_cast<const __half2*>(&r1.x));
            float2 b1v = __half22float2(*reinterpret_cast<const __half2*>(&r1.y));
            float2 a2 = __half22float2(*reinterpret_cast<const __half2*>(&r2.x));
            float2 b2v = __half22float2(*reinterpret_cast<const __half2*>(&r2.y));
            float2 a3 = __half22float2(*reinterpret_cast<const __half2*>(&r3.x));
            float2 b3v = __half22float2(*reinterpret_cast<const __half2*>(&r3.y));
            acc.x += w0 * a0.x + w1 * a1.x + w2 * a2.x + w3 * a3.x;
            acc.y += w0 * a0.y + w1 * a1.y + w2 * a2.y + w3 * a3.y;
            acc.z += w0 * b0.x + w1 * b1v.x + w2 * b2v.x + w3 * b3v.x;
            acc.w += w0 * b0.y + w1 * b1v.y + w2 * b2v.y + w3 * b3v.y;
            denom += w0 + w1 + w2 + w3;
        }
        for (int j = jm; j < m; j++) {
            float w = s_w[hw][j];
            acc_h4(acc, d_h1h + (size_t)s_src[j] * HC + rowoff, w);
            denom += w;
        }
        __syncthreads();
    }
    float inv = 1.f / (denom + 1e-16f);
    float4 bv = *(const float4*)(b1 + rowoff);
    float4 r;
    r.x = acc.x * inv + bv.x;
    r.y = acc.y * inv + bv.y;
    r.z = acc.z * inv + bv.z;
    r.w = acc.w * inv + bv.w;
    r.x = r.x > 0.f ? r.x : expm1f(r.x);
    r.y = r.y > 0.f ? r.y : expm1f(r.y);
    r.z = r.z > 0.f ? r.z : expm1f(r.z);
    r.w = r.w > 0.f ? r.w : expm1f(r.w);
    __half2 o0 = __floats2half2_rn(r.x, r.y);
    __half2 o1 = __floats2half2_rn(r.z, r.w);
    unsigned long long pack = (unsigned long long)*reinterpret_cast<unsigned*>(&o0)
                            | ((unsigned long long)*reinterpret_cast<unsigned*>(&o1) << 32);
    __stcs((unsigned long long*)(d_agg1h + (size_t)n * HC + rowoff), pack);
}

// ---------------- GEMM2 (fp16 A direct, B fp16 hi+lo, 2-term mma) + fused scores ----------------
__global__ __launch_bounds__(256, 1) void gemm2_mma(
    const __half* __restrict__ A, const float* __restrict__ B,
    const float* __restrict__ att_s, const float* __restrict__ att_d,
    float* __restrict__ C, int M)
{
    __shared__ unsigned As_f[16][136];
    __shared__ unsigned Bs_h[16][72], Bs_l[16][72];
    __shared__ float sred[2][128][2];
    const int tid = threadIdx.x, lane = tid & 31, wid = tid >> 5;
    const int g = lane >> 2, t = lane & 3;
    const int wm = wid >> 1, wn = wid & 1;     // 4x2 warps, warp tile 32x32
    const int by = blockIdx.x;
    float acc[2][4][4] = {};

    const int arow = tid >> 1, akoff = (tid & 1) * 16;
    const int gArow = by * 128 + arow;
    const bool aval = gArow < M;
    const __half* Ap = A + (size_t)gArow * HC + akoff;
    const int bk2 = tid >> 4, bcol = (tid & 15) * 4;
    const float* Bp = B + (size_t)(2 * bk2) * OUTD + bcol;

    uint2 sA[4];
    float4 sB0, sB1;
    {
#pragma unroll
        for (int i = 0; i < 4; i++)
            sA[i] = aval ? __ldcs((const uint2*)(Ap + 4 * i)) : make_uint2(0u, 0u);
        sB0 = *(const float4*)Bp;
        sB1 = *(const float4*)(Bp + OUTD);
    }

    for (int kt = 0; kt < HC / 32; kt++) {
#pragma unroll
        for (int i = 0; i < 4; i++) {
            int k2 = (akoff >> 1) + 2 * i;
            As_f[k2][arow]     = sA[i].x;
            As_f[k2 + 1][arow] = sA[i].y;
        }
        {
            unsigned h, l;
            split2h(sB0.x, sB1.x, h, l); Bs_h[bk2][bcol] = h;     Bs_l[bk2][bcol] = l;
            split2h(sB0.y, sB1.y, h, l); Bs_h[bk2][bcol + 1] = h; Bs_l[bk2][bcol + 1] = l;
            split2h(sB0.z, sB1.z, h, l); Bs_h[bk2][bcol + 2] = h; Bs_l[bk2][bcol + 2] = l;
            split2h(sB0.w, sB1.w, h, l); Bs_h[bk2][bcol + 3] = h; Bs_l[bk2][bcol + 3] = l;
        }
        __syncthreads();
        if (kt < HC / 32 - 1) {
            const __half* Ap2 = Ap + 32 * (kt + 1);
#pragma unroll
            for (int i = 0; i < 4; i++)
                sA[i] = aval ? __ldcs((const uint2*)(Ap2 + 4 * i)) : make_uint2(0u, 0u);
            const float* Bp2 = Bp + (size_t)32 * OUTD * (kt + 1);
            sB0 = *(const float4*)Bp2;
            sB1 = *(const float4*)(Bp2 + OUTD);
        }
#pragma unroll
        for (int s = 0; s < 2; s++) {
            unsigned ah[2][4];
#pragma unroll
            for (int mt = 0; mt < 2; mt++) {
                int m0 = wm * 32 + mt * 16 + g;
                ah[mt][0] = As_f[s * 8 + t][m0];
                ah[mt][1] = As_f[s * 8 + t][m0 + 8];
                ah[mt][2] = As_f[s * 8 + t + 4][m0];
                ah[mt][3] = As_f[s * 8 + t + 4][m0 + 8];
            }
#pragma unroll
            for (int nt = 0; nt < 4; nt++) {
                int n0 = wn * 32 + nt * 8 + g;
                unsigned bh0 = Bs_h[s * 8 + t][n0], bh1 = Bs_h[s * 8 + t + 4][n0];
                unsigned bl0 = Bs_l[s * 8 + t][n0], bl1 = Bs_l[s * 8 + t + 4][n0];
#pragma unroll
                for (int mt = 0; mt < 2; mt++) {
                    mma_f16(acc[mt][nt], ah[mt], bh0, bh1);
                    mma_f16(acc[mt][nt], ah[mt], bl0, bl1);
                }
            }
        }
        __syncthreads();
    }
#pragma unroll
    for (int mt = 0; mt < 2; mt++) {
        int r0 = by * 128 + wm * 32 + mt * 16 + g;
        int r1 = r0 + 8;
#pragma unroll
        for (int nt = 0; nt < 4; nt++) {
            int col = wn * 32 + nt * 8 + 2 * t;
            if (r0 < M) *(float2*)(C + (size_t)r0 * OUTD + col) = make_float2(acc[mt][nt][0], acc[mt][nt][1]);
            if (r1 < M) *(float2*)(C + (size_t)r1 * OUTD + col) = make_float2(acc[mt][nt][2], acc[mt][nt][3]);
        }
    }
    // fused score epilogue
    float pss[2][2] = {}, psd[2][2] = {};
#pragma unroll
    for (int nt = 0; nt < 4; nt++) {
        int col = wn * 32 + nt * 8 + 2 * t;
        float a0 = att_s[col], a1 = att_s[col + 1];
        float e0 = att_d[col], e1 = att_d[col + 1];
#pragma unroll
        for (int mt = 0; mt < 2; mt++) {
            pss[mt][0] += acc[mt][nt][0] * a0 + acc[mt][nt][1] * a1;
            pss[mt][1] += acc[mt][nt][2] * a0 + acc[mt][nt][3] * a1;
            psd[mt][0] += acc[mt][nt][0] * e0 + acc[mt][nt][1] * e1;
            psd[mt][1] += acc[mt][nt][2] * e0 + acc[mt][nt][3] * e1;
        }
    }
#pragma unroll
    for (int o = 1; o <= 2; o <<= 1)
#pragma unroll
        for (int mt = 0; mt < 2; mt++)
#pragma unroll
            for (int rh = 0; rh < 2; rh++) {
                pss[mt][rh] += __shfl_xor_sync(0xFFFFFFFFu, pss[mt][rh], o);
                psd[mt][rh] += __shfl_xor_sync(0xFFFFFFFFu, psd[mt][rh], o);
            }
    if (t == 0) {
#pragma unroll
        for (int mt = 0; mt < 2; mt++)
#pragma unroll
            for (int rh = 0; rh < 2; rh++) {
                int rl = wm * 32 + mt * 16 + rh * 8 + g;
                sred[wn][rl][0] = pss[mt][rh];
                sred[wn][rl][1] = psd[mt][rh];
            }
    }
    __syncthreads();
    {
        int rl = tid >> 1, which = tid & 1;
        float sum = sred[0][rl][which] + sred[1][rl][which];
        int row = by * 128 + rl;
        if (row < M) {
            if (which) d_adst2[row] = sum;
            else       d_asrc2[row] = sum;
        }
    }
}

// ---------------- layer-2 one-pass aggregation + bias + log_softmax (MLP-4) ----------------
__global__ __launch_bounds__(256) void agg2_k(float* __restrict__ out, const float* __restrict__ b2)
{
    int n = blockIdx.x * 8 + (threadIdx.x >> 5);
    int lane = threadIdx.x & 31;
    if (n >= N_NODES) return;
    float adst = d_adst2[n];
    float ws = __expf(lrelu(d_asrc2[n] + adst));
    const float* hp = d_h2 + (size_t)n * OUTD;
    float acc0 = ws * hp[lane], acc1 = ws * hp[lane + 32];
    float denom = ws;
    const int beg = d_rowptr[n], end = d_rowptr[n + 1];
    int j = beg;
    for (; j + 4 <= end; j += 4) {
        int s0 = __ldg(&d_csr_src[j]);
        int s1 = __ldg(&d_csr_src[j + 1]);
        int s2 = __ldg(&d_csr_src[j + 2]);
        int s3 = __ldg(&d_csr_src[j + 3]);
        float w0 = __expf(lrelu(__ldg(&d_asrc2[s0]) + adst));
        float w1 = __expf(lrelu(__ldg(&d_asrc2[s1]) + adst));
        float w2 = __expf(lrelu(__ldg(&d_asrc2[s2]) + adst));
        float w3 = __expf(lrelu(__ldg(&d_asrc2[s3]) + adst));
        const float* p0 = d_h2 + (size_t)s0 * OUTD;
        const float* p1 = d_h2 + (size_t)s1 * OUTD;
        const float* p2 = d_h2 + (size_t)s2 * OUTD;
        const float* p3 = d_h2 + (size_t)s3 * OUTD;
        float f00 = p0[lane], f01 = p0[lane + 32];
        float f10 = p1[lane], f11 = p1[lane + 32];
        float f20 = p2[lane], f21 = p2[lane + 32];
        float f30 = p3[lane], f31 = p3[lane + 32];
        acc0 += w0 * f00 + w1 * f10 + w2 * f20 + w3 * f30;
        acc1 += w0 * f01 + w1 * f11 + w2 * f21 + w3 * f31;
        denom += w0 + w1 + w2 + w3;
    }
    for (; j < end; j++) {
        int s = __ldg(&d_csr_src[j]);
        float w = __expf(lrelu(__ldg(&d_asrc2[s]) + adst));
        const float* sp = d_h2 + (size_t)s * OUTD;
        acc0 += w * sp[lane];
        acc1 += w * sp[lane + 32];
        denom += w;
    }
    float inv = 1.f / (denom + 1e-16f);
    float x0 = acc0 * inv + b2[lane];
    float x1 = acc1 * inv + b2[lane + 32];
    float mx = fmaxf(x0, x1);
#pragma unroll
    for (int o = 16; o; o >>= 1) mx = fmaxf(mx, __shfl_xor_sync(0xFFFFFFFFu, mx, o));
    float sm = __expf(x0 - mx) + __expf(x1 - mx);
#pragma unroll
    for (int o = 16; o; o >>= 1) sm += __shfl_xor_sync(0xFFFFFFFFu, sm, o);
    float lse = mx + logf(sm);
    out[(size_t)n * OUTD + lane] = x0 - lse;
    out[(size_t)n * OUTD + lane + 32] = x1 - lse;
}

// ---------------- launch ----------------
extern "C" void kernel_launch(void* const* d_in, const int* in_sizes, int n_in,
                              void* d_out, int out_size)
{
    const float* x   = (const float*)d_in[0];
    const int*   ei  = (const int*)  d_in[1];
    const float* W1  = (const float*)d_in[2];
    const float* as1 = (const float*)d_in[3];
    const float* ad1 = (const float*)d_in[4];
    const float* b1  = (const float*)d_in[5];
    const float* W2  = (const float*)d_in[6];
    const float* as2 = (const float*)d_in[7];
    const float* ad2 = (const float*)d_in[8];
    const float* b2  = (const float*)d_in[9];
    float* out = (float*)d_out;

    __half *h1p, *agg1hp;
    float *h2p;
    cudaGetSymbolAddress((void**)&h1p,    d_h1h);
    cudaGetSymbolAddress((void**)&agg1hp, d_agg1h);
    cudaGetSymbolAddress((void**)&h2p,    d_h2);

    // CSR build; gemm1 moved into profile slot #4 (no dependency on scatter)
    zero_deg_k<<<(N_NODES + 255) / 256, 256>>>();
    hist_k<<<(N_EDGES + 255) / 256, 256>>>(ei);
    scan_k<<<1, 1024>>>();
    {
        dim3 g(HC / 128, (N_NODES + 127) / 128);
        gemm1_mma<<<g, 256>>>(x, W1, as1, ad1, h1p, N_NODES);
    }
    scatter_k<<<(N_EDGES + 255) / 256, 256>>>(ei);

    // layer-1 aggregation: two serialized head-group passes (30.7 MB L2-resident each)
    agg1_k<<<N_NODES, 128>>>(b1, 0);
    agg1_k<<<N_NODES, 128>>>(b1, 4);

    // layer 2
    gemm2_mma<<<(N_NODES + 127) / 128, 256>>>(agg1hp, W2, as2, ad2, h2p, N_NODES);
    agg2_k<<<(N_NODES + 7) / 8, 256>>>(out, b2);
}

// round 12
// speedup vs baseline: 3.4286x; 1.1654x over previous
#include <cuda_runtime.h>
#include <cuda_bf16.h>
#include <cuda_fp16.h>
#include <math.h>

#define N_NODES 30000
#define F_IN    256
#define N_EDGES 300000
#define HEADS   8
#define CDIM    128
#define HC      1024
#define OUTD    64
#define NEG_SLOPE 0.2f

// ---------------- scratch ----------------
__device__ __align__(256) __half d_h1h  [(size_t)N_NODES * HC];  // 61.4 MB
__device__ __align__(256) __half d_agg1h[(size_t)N_NODES * HC];  // 61.4 MB
__device__ __align__(256) __half d_xh   [(size_t)N_NODES * F_IN]; // 15.4 MB (x in fp16)
__device__ __align__(256) __half d_w1h  [F_IN * HC];              // W1 hi fp16
__device__ __align__(256) __half d_w1l  [F_IN * HC];              // W1 lo fp16
__device__ __align__(256) float  d_asrc1[N_NODES * HEADS];
__device__ __align__(256) float  d_adst1[N_NODES * HEADS];
__device__ __align__(256) float  d_h2  [(size_t)N_NODES * OUTD];
__device__ __align__(256) float  d_asrc2[N_NODES];
__device__ __align__(256) float  d_adst2[N_NODES];
__device__ __align__(256) int    d_deg   [N_NODES];
__device__ __align__(256) int    d_rowptr[N_NODES + 1];
__device__ __align__(256) int    d_cursor[N_NODES];
__device__ __align__(256) int    d_csr_src[N_EDGES];

// ---------------- helpers ----------------
__device__ __forceinline__ float lrelu(float x) { return x > 0.f ? x : NEG_SLOPE * x; }

__device__ __forceinline__ unsigned smem_u32(const void* p) {
    unsigned a;
    asm("{ .reg .u64 t; cvta.to.shared.u64 t, %1; cvt.u32.u64 %0, t; }" : "=r"(a) : "l"(p));
    return a;
}

__device__ __forceinline__ void split2h(float x, float y, unsigned& h, unsigned& l) {
    __half hx = __float2half_rn(x);
    __half hy = __float2half_rn(y);
    float rx = x - __half2float(hx);
    float ry = y - __half2float(hy);
    __half lx = __float2half_rn(rx);
    __half ly = __float2half_rn(ry);
    h = (unsigned)__half_as_ushort(hx) | ((unsigned)__half_as_ushort(hy) << 16);
    l = (unsigned)__half_as_ushort(lx) | ((unsigned)__half_as_ushort(ly) << 16);
}

__device__ __forceinline__ void mma_f16(float* c, const unsigned* a, unsigned b0, unsigned b1) {
    asm volatile("mma.sync.aligned.m16n8k16.row.col.f32.f16.f16.f32 "
                 "{%0,%1,%2,%3}, {%4,%5,%6,%7}, {%8,%9}, {%0,%1,%2,%3};\n"
                 : "+f"(c[0]), "+f"(c[1]), "+f"(c[2]), "+f"(c[3])
                 : "r"(a[0]), "r"(a[1]), "r"(a[2]), "r"(a[3]), "r"(b0), "r"(b1));
}

__device__ __forceinline__ void ldsm_x4(unsigned& r0, unsigned& r1, unsigned& r2, unsigned& r3, unsigned a) {
    asm volatile("ldmatrix.sync.aligned.m8n8.x4.shared.b16 {%0,%1,%2,%3}, [%4];"
                 : "=r"(r0), "=r"(r1), "=r"(r2), "=r"(r3) : "r"(a));
}
__device__ __forceinline__ void ldsm_x4_t(unsigned& r0, unsigned& r1, unsigned& r2, unsigned& r3, unsigned a) {
    asm volatile("ldmatrix.sync.aligned.m8n8.x4.trans.shared.b16 {%0,%1,%2,%3}, [%4];"
                 : "=r"(r0), "=r"(r1), "=r"(r2), "=r"(r3) : "r"(a));
}

#define CPA16(dst, src, sz) \
    asm volatile("cp.async.cg.shared.global [%0], [%1], 16, %2;\n" :: "r"(dst), "l"(src), "r"(sz))

__device__ __forceinline__ void acc_h4(float4& acc, const __half* base, float w) {
    uint2 raw = *(const uint2*)base;
    float2 u0 = __half22float2(*reinterpret_cast<const __half2*>(&raw.x));
    float2 u1 = __half22float2(*reinterpret_cast<const __half2*>(&raw.y));
    acc.x += w * u0.x; acc.y += w * u0.y; acc.z += w * u1.x; acc.w += w * u1.y;
}

// ---------------- conversion kernels ----------------
__global__ void convx_k(const float* __restrict__ x)
{
    int i = blockIdx.x * 256 + threadIdx.x;
    if (i >= N_NODES * F_IN / 4) return;
    float4 v = ((const float4*)x)[i];
    __half2 h0 = __floats2half2_rn(v.x, v.y), h1 = __floats2half2_rn(v.z, v.w);
    uint2 o;
    o.x = *reinterpret_cast<unsigned*>(&h0);
    o.y = *reinterpret_cast<unsigned*>(&h1);
    ((uint2*)d_xh)[i] = o;
}

__global__ void convw1_k(const float* __restrict__ W)
{
    int i = blockIdx.x * 256 + threadIdx.x;
    if (i >= F_IN * HC / 2) return;
    float2 v = ((const float2*)W)[i];
    unsigned h, l;
    split2h(v.x, v.y, h, l);
    ((unsigned*)d_w1h)[i] = h;
    ((unsigned*)d_w1l)[i] = l;
}

// ---------------- CSR build ----------------
__global__ void zero_deg_k()
{
    int i = blockIdx.x * blockDim.x + threadIdx.x;
    if (i < N_NODES) d_deg[i] = 0;
}

__global__ void hist_k(const int* __restrict__ ei)
{
    int e = blockIdx.x * blockDim.x + threadIdx.x;
    if (e >= N_EDGES) return;
    atomicAdd(&d_deg[ei[N_EDGES + e]], 1);
}

__global__ __launch_bounds__(1024) void scan_k()
{
    __shared__ int wsum[32];
    const int tid = threadIdx.x;
    const int ITEMS = (N_NODES + 1023) / 1024;   // 30
    int base = tid * ITEMS;
    int sum = 0;
#pragma unroll 4
    for (int i = 0; i < ITEMS; i++) {
        int idx = base + i;
        if (idx < N_NODES) sum += d_deg[idx];
    }
    int lane = tid & 31, wid = tid >> 5;
    int v = sum;
#pragma unroll
    for (int o = 1; o < 32; o <<= 1) {
        int y = __shfl_up_sync(0xFFFFFFFFu, v, o);
        if (lane >= o) v += y;
    }
    if (lane == 31) wsum[wid] = v;
    __syncthreads();
    if (wid == 0) {
        int w = wsum[lane];
#pragma unroll
        for (int o = 1; o < 32; o <<= 1) {
            int y = __shfl_up_sync(0xFFFFFFFFu, w, o);
            if (lane >= o) w += y;
        }
        wsum[lane] = w;
    }
    __syncthreads();
    int run = v - sum + (wid ? wsum[wid - 1] : 0);
#pragma unroll 4
    for (int i = 0; i < ITEMS; i++) {
        int idx = base + i;
        if (idx < N_NODES) {
            d_rowptr[idx] = run;
            d_cursor[idx] = run;
            run += d_deg[idx];
        }
    }
    if (tid == 1023) d_rowptr[N_NODES] = wsum[31];
}

__global__ void scatter_k(const int* __restrict__ ei)
{
    int e = blockIdx.x * blockDim.x + threadIdx.x;
    if (e >= N_EDGES) return;
    int s = ei[e], d = ei[N_EDGES + e];
    int p = atomicAdd(&d_cursor[d], 1);
    d_csr_src[p] = s;
}

// ---------------- GEMM1: preconverted fp16 A/B(hi,lo), cp.async 2-stage, ldmatrix, 2 CTA/SM ----
// smem stage layout: [A: 128 rows x 40 halves = 10240 B][Bh: 32 x 136 halves = 8704 B][Bl: 8704 B]
#define G1_STAGE 27648
#define G1_BH    10240
#define G1_BL    18944

__global__ __launch_bounds__(256, 2) void gemm1_mma(
    const __half* __restrict__ Ax, const __half* __restrict__ Bh16, const __half* __restrict__ Bl16,
    const float* __restrict__ att_s, const float* __restrict__ att_d,
    __half* __restrict__ C, int M)
{
    extern __shared__ char dsm[];
    const unsigned sbase = smem_u32(dsm);
    const int tid = threadIdx.x, lane = tid & 31, wid = tid >> 5;
    const int g = lane >> 2, t = lane & 3;
    const int wm = wid >> 2, wn = wid & 3;     // 2x4 warps, warp tile 64x32
    const int by = blockIdx.y, bx = blockIdx.x;
    const int gRow0 = by * 128;
    float acc[4][4][4] = {};

    // loader indices (2 x 16B chunks per thread per tile)
    const int ar0 = tid >> 2, ar1 = (tid + 256) >> 2, acc4 = (tid & 3);
    const int br0 = tid >> 4, br1 = (tid + 256) >> 4, bcc = (tid & 15);

    // ldmatrix per-lane offsets (bytes, all 16B-aligned)
    const unsigned aLane = (unsigned)((wm * 64 + (lane & 15)) * 80 + ((lane & 16) ? 16 : 0));
    const unsigned bLane = (unsigned)((lane & 15) * 272 + wn * 64 + ((lane & 16) ? 16 : 0));

    auto issue = [&](int kt, int st) {
        unsigned sb = sbase + st * G1_STAGE;
        {
            long r = gRow0 + ar0;
            CPA16(sb + ar0 * 80 + acc4 * 16, Ax + (size_t)r * F_IN + kt * 32 + acc4 * 8, (r < M) ? 16 : 0);
            r = gRow0 + ar1;
            CPA16(sb + ar1 * 80 + acc4 * 16, Ax + (size_t)r * F_IN + kt * 32 + acc4 * 8, (r < M) ? 16 : 0);
        }
        CPA16(sb + G1_BH + br0 * 272 + bcc * 16, Bh16 + (size_t)(kt * 32 + br0) * HC + bx * 128 + bcc * 8, 16);
        CPA16(sb + G1_BL + br0 * 272 + bcc * 16, Bl16 + (size_t)(kt * 32 + br0) * HC + bx * 128 + bcc * 8, 16);
        CPA16(sb + G1_BH + br1 * 272 + bcc * 16, Bh16 + (size_t)(kt * 32 + br1) * HC + bx * 128 + bcc * 8, 16);
        CPA16(sb + G1_BL + br1 * 272 + bcc * 16, Bl16 + (size_t)(kt * 32 + br1) * HC + bx * 128 + bcc * 8, 16);
        asm volatile("cp.async.commit_group;\n" ::: "memory");
    };

    issue(0, 0);
    for (int kt = 0; kt < F_IN / 32; kt++) {
        if (kt < F_IN / 32 - 1) {
            issue(kt + 1, (kt + 1) & 1);
            asm volatile("cp.async.wait_group 1;\n" ::: "memory");
        } else {
            asm volatile("cp.async.wait_group 0;\n" ::: "memory");
        }
        __syncthreads();
        unsigned sb = sbase + (kt & 1) * G1_STAGE;
#pragma unroll
        for (int s = 0; s < 2; s++) {
            unsigned ah[4][4];
#pragma unroll
            for (int mt = 0; mt < 4; mt++)
                ldsm_x4(ah[mt][0], ah[mt][1], ah[mt][2], ah[mt][3],
                        sb + aLane + mt * 1280 + s * 32);
#pragma unroll
            for (int p = 0; p < 2; p++) {
                unsigned h0, h1, h2, h3, l0, l1, l2, l3;
                ldsm_x4_t(h0, h1, h2, h3, sb + G1_BH + bLane + s * 4352 + p * 32);
                ldsm_x4_t(l0, l1, l2, l3, sb + G1_BL + bLane + s * 4352 + p * 32);
#pragma unroll
                for (int mt = 0; mt < 4; mt++) {
                    mma_f16(acc[mt][p * 2],     ah[mt], h0, h1);
                    mma_f16(acc[mt][p * 2],     ah[mt], l0, l1);
                    mma_f16(acc[mt][p * 2 + 1], ah[mt], h2, h3);
                    mma_f16(acc[mt][p * 2 + 1], ah[mt], l2, l3);
                }
            }
        }
        __syncthreads();
    }
    // store C tile as fp16
#pragma unroll
    for (int mt = 0; mt < 4; mt++) {
        int r0 = gRow0 + wm * 64 + mt * 16 + g;
        int r1 = r0 + 8;
#pragma unroll
        for (int nt = 0; nt < 4; nt++) {
            int col = bx * 128 + wn * 32 + nt * 8 + 2 * t;
            if (r0 < M) *(__half2*)(C + (size_t)r0 * HC + col) = __floats2half2_rn(acc[mt][nt][0], acc[mt][nt][1]);
            if (r1 < M) *(__half2*)(C + (size_t)r1 * HC + col) = __floats2half2_rn(acc[mt][nt][2], acc[mt][nt][3]);
        }
    }
    // fused score epilogue (sred aliases stage smem; safe after trailing barrier)
    float* sred = reinterpret_cast<float*>(dsm);   // [4][128][2]
    const float* as = att_s + bx * CDIM;
    const float* ad = att_d + bx * CDIM;
    float pss[4][2] = {}, psd[4][2] = {};
#pragma unroll
    for (int nt = 0; nt < 4; nt++) {
        int col = wn * 32 + nt * 8 + 2 * t;
        float a0 = as[col], a1 = as[col + 1];
        float e0 = ad[col], e1 = ad[col + 1];
#pragma unroll
        for (int mt = 0; mt < 4; mt++) {
            pss[mt][0] += acc[mt][nt][0] * a0 + acc[mt][nt][1] * a1;
            pss[mt][1] += acc[mt][nt][2] * a0 + acc[mt][nt][3] * a1;
            psd[mt][0] += acc[mt][nt][0] * e0 + acc[mt][nt][1] * e1;
            psd[mt][1] += acc[mt][nt][2] * e0 + acc[mt][nt][3] * e1;
        }
    }
#pragma unroll
    for (int o = 1; o <= 2; o <<= 1)
#pragma unroll
        for (int mt = 0; mt < 4; mt++)
#pragma unroll
            for (int rh = 0; rh < 2; rh++) {
                pss[mt][rh] += __shfl_xor_sync(0xFFFFFFFFu, pss[mt][rh], o);
                psd[mt][rh] += __shfl_xor_sync(0xFFFFFFFFu, psd[mt][rh], o);
            }
    if (t == 0) {
#pragma unroll
        for (int mt = 0; mt < 4; mt++)
#pragma unroll
            for (int rh = 0; rh < 2; rh++) {
                int rl = wm * 64 + mt * 16 + rh * 8 + g;
                sred[(wn * 128 + rl) * 2 + 0] = pss[mt][rh];
                sred[(wn * 128 + rl) * 2 + 1] = psd[mt][rh];
            }
    }
    __syncthreads();
    {
        int rl = tid >> 1, which = tid & 1;
        float sum = sred[(0 * 128 + rl) * 2 + which] + sred[(1 * 128 + rl) * 2 + which]
                  + sred[(2 * 128 + rl) * 2 + which] + sred[(3 * 128 + rl) * 2 + which];
        int row = gRow0 + rl;
        if (row < M) {
            if (which) d_adst1[row * HEADS + bx] = sum;
            else       d_asrc1[row * HEADS + bx] = sum;
        }
    }
}

// ---------------- layer-1 aggregation: per 4-head group, fused bias+ELU, fp16 out ----------------
__global__ __launch_bounds__(128) void agg1_k(const float* __restrict__ b1, int h0)
{
    __shared__ int   s_src[32];
    __shared__ float s_w[4][32];
    const int n = blockIdx.x;
    const int hw = threadIdx.x >> 5, lane = threadIdx.x & 31;
    const int h = h0 + hw;
    const float adst = d_adst1[n * HEADS + h];
    const float ws = __expf(lrelu(d_asrc1[n * HEADS + h] + adst));
    const size_t rowoff = (size_t)h * CDIM + lane * 4;

    float4 acc = make_float4(0.f, 0.f, 0.f, 0.f);
    acc_h4(acc, d_h1h + (size_t)n * HC + rowoff, ws);
    float denom = ws;

    const int beg = d_rowptr[n], end = d_rowptr[n + 1];
    for (int c0 = beg; c0 < end; c0 += 32) {
        const int m = min(32, end - c0);
        if (hw == 0 && lane < m) s_src[lane] = d_csr_src[c0 + lane];
        __syncthreads();
        if (lane < m)
            s_w[hw][lane] = __expf(lrelu(__ldg(&d_asrc1[s_src[lane] * HEADS + h]) + adst));
        __syncwarp();
        int jm = m & ~3;
        for (int j = 0; j < jm; j += 4) {
            int s0 = s_src[j], s1 = s_src[j + 1], s2 = s_src[j + 2], s3 = s_src[j + 3];
            float w0 = s_w[hw][j], w1 = s_w[hw][j + 1], w2 = s_w[hw][j + 2], w3 = s_w[hw][j + 3];
            uint2 r0 = *(const uint2*)(d_h1h + (size_t)s0 * HC + rowoff);
            uint2 r1 = *(const uint2*)(d_h1h + (size_t)s1 * HC + rowoff);
            uint2 r2 = *(const uint2*)(d_h1h + (size_t)s2 * HC + rowoff);
            uint2 r3 = *(const uint2*)(d_h1h + (size_t)s3 * HC + rowoff);
            float2 a0 = __half22float2(*reinterpret_cast<const __half2*>(&r0.x));
            float2 b0 = __half22float2(*reinterpret_cast<const __half2*>(&r0.y));
            float2 a1 = __half22float2(*reinterpret_cast<const __half2*>(&r1.x));
            float2 b1v = __half22float2(*reinterpret_cast<const __half2*>(&r1.y));
            float2 a2 = __half22float2(*reinterpret_cast<const __half2*>(&r2.x));
            float2 b2v = __half22float2(*reinterpret_cast<const __half2*>(&r2.y));
            float2 a3 = __half22float2(*reinterpret_cast<const __half2*>(&r3.x));
            float2 b3v = __half22float2(*reinterpret_cast<const __half2*>(&r3.y));
            acc.x += w0 * a0.x + w1 * a1.x + w2 * a2.x + w3 * a3.x;
            acc.y += w0 * a0.y + w1 * a1.y + w2 * a2.y + w3 * a3.y;
            acc.z += w0 * b0.x + w1 * b1v.x + w2 * b2v.x + w3 * b3v.x;
            acc.w += w0 * b0.y + w1 * b1v.y + w2 * b2v.y + w3 * b3v.y;
            denom += w0 + w1 + w2 + w3;
        }
        for (int j = jm; j < m; j++) {
            float w = s_w[hw][j];
            acc_h4(acc, d_h1h + (size_t)s_src[j] * HC + rowoff, w);
            denom += w;
        }
        __syncthreads();
    }
    float inv = 1.f / (denom + 1e-16f);
    float4 bv = *(const float4*)(b1 + rowoff);
    float4 r;
    r.x = acc.x * inv + bv.x;
    r.y = acc.y * inv + bv.y;
    r.z = acc.z * inv + bv.z;
    r.w = acc.w * inv + bv.w;
    r.x = r.x > 0.f ? r.x : expm1f(r.x);
    r.y = r.y > 0.f ? r.y : expm1f(r.y);
    r.z = r.z > 0.f ? r.z : expm1f(r.z);
    r.w = r.w > 0.f ? r.w : expm1f(r.w);
    __half2 o0 = __floats2half2_rn(r.x, r.y);
    __half2 o1 = __floats2half2_rn(r.z, r.w);
    unsigned long long pack = (unsigned long long)*reinterpret_cast<unsigned*>(&o0)
                            | ((unsigned long long)*reinterpret_cast<unsigned*>(&o1) << 32);
    __stcs((unsigned long long*)(d_agg1h + (size_t)n * HC + rowoff), pack);
}

// ---------------- GEMM2 (fp16 A direct, B fp16 hi+lo, 2-term mma) + fused scores ----------------
__global__ __launch_bounds__(256, 1) void gemm2_mma(
    const __half* __restrict__ A, const float* __restrict__ B,
    const float* __restrict__ att_s, const float* __restrict__ att_d,
    float* __restrict__ C, int M)
{
    __shared__ unsigned As_f[16][136];
    __shared__ unsigned Bs_h[16][72], Bs_l[16][72];
    __shared__ float sred[2][128][2];
    const int tid = threadIdx.x, lane = tid & 31, wid = tid >> 5;
    const int g = lane >> 2, t = lane & 3;
    const int wm = wid >> 1, wn = wid & 1;     // 4x2 warps, warp tile 32x32
    const int by = blockIdx.x;
    float acc[2][4][4] = {};

    const int arow = tid >> 1, akoff = (tid & 1) * 16;
    const int gArow = by * 128 + arow;
    const bool aval = gArow < M;
    const __half* Ap = A + (size_t)gArow * HC + akoff;
    const int bk2 = tid >> 4, bcol = (tid & 15) * 4;
    const float* Bp = B + (size_t)(2 * bk2) * OUTD + bcol;

    uint2 sA[4];
    float4 sB0, sB1;
    {
#pragma unroll
        for (int i = 0; i < 4; i++)
            sA[i] = aval ? __ldcs((const uint2*)(Ap + 4 * i)) : make_uint2(0u, 0u);
        sB0 = *(const float4*)Bp;
        sB1 = *(const float4*)(Bp + OUTD);
    }

    for (int kt = 0; kt < HC / 32; kt++) {
#pragma unroll
        for (int i = 0; i < 4; i++) {
            int k2 = (akoff >> 1) + 2 * i;
            As_f[k2][arow]     = sA[i].x;
            As_f[k2 + 1][arow] = sA[i].y;
        }
        {
            unsigned h, l;
            split2h(sB0.x, sB1.x, h, l); Bs_h[bk2][bcol] = h;     Bs_l[bk2][bcol] = l;
            split2h(sB0.y, sB1.y, h, l); Bs_h[bk2][bcol + 1] = h; Bs_l[bk2][bcol + 1] = l;
            split2h(sB0.z, sB1.z, h, l); Bs_h[bk2][bcol + 2] = h; Bs_l[bk2][bcol + 2] = l;
            split2h(sB0.w, sB1.w, h, l); Bs_h[bk2][bcol + 3] = h; Bs_l[bk2][bcol + 3] = l;
        }
        __syncthreads();
        if (kt < HC / 32 - 1) {
            const __half* Ap2 = Ap + 32 * (kt + 1);
#pragma unroll
            for (int i = 0; i < 4; i++)
                sA[i] = aval ? __ldcs((const uint2*)(Ap2 + 4 * i)) : make_uint2(0u, 0u);
            const float* Bp2 = Bp + (size_t)32 * OUTD * (kt + 1);
            sB0 = *(const float4*)Bp2;
            sB1 = *(const float4*)(Bp2 + OUTD);
        }
#pragma unroll
        for (int s = 0; s < 2; s++) {
            unsigned ah[2][4];
#pragma unroll
            for (int mt = 0; mt < 2; mt++) {
                int m0 = wm * 32 + mt * 16 + g;
                ah[mt][0] = As_f[s * 8 + t][m0];
                ah[mt][1] = As_f[s * 8 + t][m0 + 8];
                ah[mt][2] = As_f[s * 8 + t + 4][m0];
                ah[mt][3] = As_f[s * 8 + t + 4][m0 + 8];
            }
#pragma unroll
            for (int nt = 0; nt < 4; nt++) {
                int n0 = wn * 32 + nt * 8 + g;
                unsigned bh0 = Bs_h[s * 8 + t][n0], bh1 = Bs_h[s * 8 + t + 4][n0];
                unsigned bl0 = Bs_l[s * 8 + t][n0], bl1 = Bs_l[s * 8 + t + 4][n0];
#pragma unroll
                for (int mt = 0; mt < 2; mt++) {
                    mma_f16(acc[mt][nt], ah[mt], bh0, bh1);
                    mma_f16(acc[mt][nt], ah[mt], bl0, bl1);
                }
            }
        }
        __syncthreads();
    }
#pragma unroll
    for (int mt = 0; mt < 2; mt++) {
        int r0 = by * 128 + wm * 32 + mt * 16 + g;
        int r1 = r0 + 8;
#pragma unroll
        for (int nt = 0; nt < 4; nt++) {
            int col = wn * 32 + nt * 8 + 2 * t;
            if (r0 < M) *(float2*)(C + (size_t)r0 * OUTD + col) = make_float2(acc[mt][nt][0], acc[mt][nt][1]);
            if (r1 < M) *(float2*)(C + (size_t)r1 * OUTD + col) = make_float2(acc[mt][nt][2], acc[mt][nt][3]);
        }
    }
    // fused score epilogue
    float pss[2][2] = {}, psd[2][2] = {};
#pragma unroll
    for (int nt = 0; nt < 4; nt++) {
        int col = wn * 32 + nt * 8 + 2 * t;
        float a0 = att_s[col], a1 = att_s[col + 1];
        float e0 = att_d[col], e1 = att_d[col + 1];
#pragma unroll
        for (int mt = 0; mt < 2; mt++) {
            pss[mt][0] += acc[mt][nt][0] * a0 + acc[mt][nt][1] * a1;
            pss[mt][1] += acc[mt][nt][2] * a0 + acc[mt][nt][3] * a1;
            psd[mt][0] += acc[mt][nt][0] * e0 + acc[mt][nt][1] * e1;
            psd[mt][1] += acc[mt][nt][2] * e0 + acc[mt][nt][3] * e1;
        }
    }
#pragma unroll
    for (int o = 1; o <= 2; o <<= 1)
#pragma unroll
        for (int mt = 0; mt < 2; mt++)
#pragma unroll
            for (int rh = 0; rh < 2; rh++) {
                pss[mt][rh] += __shfl_xor_sync(0xFFFFFFFFu, pss[mt][rh], o);
                psd[mt][rh] += __shfl_xor_sync(0xFFFFFFFFu, psd[mt][rh], o);
            }
    if (t == 0) {
#pragma unroll
        for (int mt = 0; mt < 2; mt++)
#pragma unroll
            for (int rh = 0; rh < 2; rh++) {
                int rl = wm * 32 + mt * 16 + rh * 8 + g;
                sred[wn][rl][0] = pss[mt][rh];
                sred[wn][rl][1] = psd[mt][rh];
            }
    }
    __syncthreads();
    {
        int rl = tid >> 1, which = tid & 1;
        float sum = sred[0][rl][which] + sred[1][rl][which];
        int row = by * 128 + rl;
        if (row < M) {
            if (which) d_adst2[row] = sum;
            else       d_asrc2[row] = sum;
        }
    }
}

// ---------------- layer-2 one-pass aggregation + bias + log_softmax (MLP-4) ----------------
__global__ __launch_bounds__(256) void agg2_k(float* __restrict__ out, const float* __restrict__ b2)
{
    int n = blockIdx.x * 8 + (threadIdx.x >> 5);
    int lane = threadIdx.x & 31;
    if (n >= N_NODES) return;
    float adst = d_adst2[n];
    float ws = __expf(lrelu(d_asrc2[n] + adst));
    const float* hp = d_h2 + (size_t)n * OUTD;
    float acc0 = ws * hp[lane], acc1 = ws * hp[lane + 32];
    float denom = ws;
    const int beg = d_rowptr[n], end = d_rowptr[n + 1];
    int j = beg;
    for (; j + 4 <= end; j += 4) {
        int s0 = __ldg(&d_csr_src[j]);
        int s1 = __ldg(&d_csr_src[j + 1]);
        int s2 = __ldg(&d_csr_src[j + 2]);
        int s3 = __ldg(&d_csr_src[j + 3]);
        float w0 = __expf(lrelu(__ldg(&d_asrc2[s0]) + adst));
        float w1 = __expf(lrelu(__ldg(&d_asrc2[s1]) + adst));
        float w2 = __expf(lrelu(__ldg(&d_asrc2[s2]) + adst));
        float w3 = __expf(lrelu(__ldg(&d_asrc2[s3]) + adst));
        const float* p0 = d_h2 + (size_t)s0 * OUTD;
        const float* p1 = d_h2 + (size_t)s1 * OUTD;
        const float* p2 = d_h2 + (size_t)s2 * OUTD;
        const float* p3 = d_h2 + (size_t)s3 * OUTD;
        float f00 = p0[lane], f01 = p0[lane + 32];
        float f10 = p1[lane], f11 = p1[lane + 32];
        float f20 = p2[lane], f21 = p2[lane + 32];
        float f30 = p3[lane], f31 = p3[lane + 32];
        acc0 += w0 * f00 + w1 * f10 + w2 * f20 + w3 * f30;
        acc1 += w0 * f01 + w1 * f11 + w2 * f21 + w3 * f31;
        denom += w0 + w1 + w2 + w3;
    }
    for (; j < end; j++) {
        int s = __ldg(&d_csr_src[j]);
        float w = __expf(lrelu(__ldg(&d_asrc2[s]) + adst));
        const float* sp = d_h2 + (size_t)s * OUTD;
        acc0 += w * sp[lane];
        acc1 += w * sp[lane + 32];
        denom += w;
    }
    float inv = 1.f / (denom + 1e-16f);
    float x0 = acc0 * inv + b2[lane];
    float x1 = acc1 * inv + b2[lane + 32];
    float mx = fmaxf(x0, x1);
#pragma unroll
    for (int o = 16; o; o >>= 1) mx = fmaxf(mx, __shfl_xor_sync(0xFFFFFFFFu, mx, o));
    float sm = __expf(x0 - mx) + __expf(x1 - mx);
#pragma unroll
    for (int o = 16; o; o >>= 1) sm += __shfl_xor_sync(0xFFFFFFFFu, sm, o);
    float lse = mx + logf(sm);
    out[(size_t)n * OUTD + lane] = x0 - lse;
    out[(size_t)n * OUTD + lane + 32] = x1 - lse;
}

// ---------------- launch ----------------
extern "C" void kernel_launch(void* const* d_in, const int* in_sizes, int n_in,
                              void* d_out, int out_size)
{
    const float* x   = (const float*)d_in[0];
    const int*   ei  = (const int*)  d_in[1];
    const float* W1  = (const float*)d_in[2];
    const float* as1 = (const float*)d_in[3];
    const float* ad1 = (const float*)d_in[4];
    const float* b1  = (const float*)d_in[5];
    const float* W2  = (const float*)d_in[6];
    const float* as2 = (const float*)d_in[7];
    const float* ad2 = (const float*)d_in[8];
    const float* b2  = (const float*)d_in[9];
    float* out = (float*)d_out;

    __half *h1p, *agg1hp, *xhp, *w1hp, *w1lp;
    float *h2p;
    cudaGetSymbolAddress((void**)&h1p,    d_h1h);
    cudaGetSymbolAddress((void**)&agg1hp, d_agg1h);
    cudaGetSymbolAddress((void**)&xhp,    d_xh);
    cudaGetSymbolAddress((void**)&w1hp,   d_w1h);
    cudaGetSymbolAddress((void**)&w1lp,   d_w1l);
    cudaGetSymbolAddress((void**)&h2p,    d_h2);

    cudaFuncSetAttribute(gemm1_mma, cudaFuncAttributeMaxDynamicSharedMemorySize, 2 * G1_STAGE);

    // launch order keeps gemm1 in the profiled slot (#4)
    zero_deg_k<<<(N_NODES + 255) / 256, 256>>>();
    convx_k<<<(N_NODES * F_IN / 4 + 255) / 256, 256>>>(x);
    convw1_k<<<(F_IN * HC / 2 + 255) / 256, 256>>>(W1);
    {
        dim3 g(HC / 128, (N_NODES + 127) / 128);
        gemm1_mma<<<g, 256, 2 * G1_STAGE>>>(xhp, w1hp, w1lp, as1, ad1, h1p, N_NODES);
    }
    hist_k<<<(N_EDGES + 255) / 256, 256>>>(ei);
    scan_k<<<1, 1024>>>();
    scatter_k<<<(N_EDGES + 255) / 256, 256>>>(ei);

    // layer-1 aggregation: two serialized head-group passes (30.7 MB L2-resident each)
    agg1_k<<<N_NODES, 128>>>(b1, 0);
    agg1_k<<<N_NODES, 128>>>(b1, 4);

    // layer 2
    gemm2_mma<<<(N_NODES + 127) / 128, 256>>>(agg1hp, W2, as2, ad2, h2p, N_NODES);
    agg2_k<<<(N_NODES + 7) / 8, 256>>>(out, b2);
}

// round 13
// speedup vs baseline: 3.8370x; 1.1191x over previous
#include <cuda_runtime.h>
#include <cuda_bf16.h>
#include <cuda_fp16.h>
#include <math.h>

#define N_NODES 30000
#define F_IN    256
#define N_EDGES 300000
#define HEADS   8
#define CDIM    128
#define HC      1024
#define OUTD    64
#define NEG_SLOPE 0.2f

// ---------------- scratch ----------------
__device__ __align__(256) __half d_h1h  [(size_t)N_NODES * HC];  // 61.4 MB
__device__ __align__(256) __half d_agg1h[(size_t)N_NODES * HC];  // 61.4 MB
__device__ __align__(256) __half d_xh   [(size_t)N_NODES * F_IN]; // 15.4 MB
__device__ __align__(256) __half d_w1h  [F_IN * HC];              // W1 fp16
__device__ __align__(256) float  d_asrc1[N_NODES * HEADS];
__device__ __align__(256) float  d_adst1[N_NODES * HEADS];
__device__ __align__(256) float  d_h2  [(size_t)N_NODES * OUTD];
__device__ __align__(256) float  d_asrc2[N_NODES];
__device__ __align__(256) float  d_adst2[N_NODES];
__device__ __align__(256) int    d_deg   [N_NODES];
__device__ __align__(256) int    d_rowptr[N_NODES + 1];
__device__ __align__(256) int    d_cursor[N_NODES];
__device__ __align__(256) int    d_csr_src[N_EDGES];

// ---------------- helpers ----------------
__device__ __forceinline__ float lrelu(float x) { return x > 0.f ? x : NEG_SLOPE * x; }

__device__ __forceinline__ unsigned smem_u32(const void* p) {
    unsigned a;
    asm("{ .reg .u64 t; cvta.to.shared.u64 t, %1; cvt.u32.u64 %0, t; }" : "=r"(a) : "l"(p));
    return a;
}

__device__ __forceinline__ void split2h(float x, float y, unsigned& h, unsigned& l) {
    __half hx = __float2half_rn(x);
    __half hy = __float2half_rn(y);
    float rx = x - __half2float(hx);
    float ry = y - __half2float(hy);
    __half lx = __float2half_rn(rx);
    __half ly = __float2half_rn(ry);
    h = (unsigned)__half_as_ushort(hx) | ((unsigned)__half_as_ushort(hy) << 16);
    l = (unsigned)__half_as_ushort(lx) | ((unsigned)__half_as_ushort(ly) << 16);
}

__device__ __forceinline__ void mma_f16(float* c, const unsigned* a, unsigned b0, unsigned b1) {
    asm volatile("mma.sync.aligned.m16n8k16.row.col.f32.f16.f16.f32 "
                 "{%0,%1,%2,%3}, {%4,%5,%6,%7}, {%8,%9}, {%0,%1,%2,%3};\n"
                 : "+f"(c[0]), "+f"(c[1]), "+f"(c[2]), "+f"(c[3])
                 : "r"(a[0]), "r"(a[1]), "r"(a[2]), "r"(a[3]), "r"(b0), "r"(b1));
}

__device__ __forceinline__ void ldsm_x4(unsigned& r0, unsigned& r1, unsigned& r2, unsigned& r3, unsigned a) {
    asm volatile("ldmatrix.sync.aligned.m8n8.x4.shared.b16 {%0,%1,%2,%3}, [%4];"
                 : "=r"(r0), "=r"(r1), "=r"(r2), "=r"(r3) : "r"(a));
}
__device__ __forceinline__ void ldsm_x4_t(unsigned& r0, unsigned& r1, unsigned& r2, unsigned& r3, unsigned a) {
    asm volatile("ldmatrix.sync.aligned.m8n8.x4.trans.shared.b16 {%0,%1,%2,%3}, [%4];"
                 : "=r"(r0), "=r"(r1), "=r"(r2), "=r"(r3) : "r"(a));
}

#define CPA16(dst, src, sz) \
    asm volatile("cp.async.cg.shared.global [%0], [%1], 16, %2;\n" :: "r"(dst), "l"(src), "r"(sz))

__device__ __forceinline__ void acc_h4(float4& acc, const __half* base, float w) {
    uint2 raw = *(const uint2*)base;
    float2 u0 = __half22float2(*reinterpret_cast<const __half2*>(&raw.x));
    float2 u1 = __half22float2(*reinterpret_cast<const __half2*>(&raw.y));
    acc.x += w * u0.x; acc.y += w * u0.y; acc.z += w * u1.x; acc.w += w * u1.y;
}

// ---------------- conversion kernels ----------------
__global__ void convx_k(const float* __restrict__ x)
{
    int i = blockIdx.x * 256 + threadIdx.x;
    if (i >= N_NODES * F_IN / 4) return;
    float4 v = ((const float4*)x)[i];
    __half2 h0 = __floats2half2_rn(v.x, v.y), h1 = __floats2half2_rn(v.z, v.w);
    uint2 o;
    o.x = *reinterpret_cast<unsigned*>(&h0);
    o.y = *reinterpret_cast<unsigned*>(&h1);
    ((uint2*)d_xh)[i] = o;
}

__global__ void convw1_k(const float* __restrict__ W)
{
    int i = blockIdx.x * 256 + threadIdx.x;
    if (i >= F_IN * HC / 4) return;
    float4 v = ((const float4*)W)[i];
    __half2 h0 = __floats2half2_rn(v.x, v.y), h1 = __floats2half2_rn(v.z, v.w);
    uint2 o;
    o.x = *reinterpret_cast<unsigned*>(&h0);
    o.y = *reinterpret_cast<unsigned*>(&h1);
    ((uint2*)d_w1h)[i] = o;
}

// ---------------- CSR build ----------------
__global__ void zero_deg_k()
{
    int i = blockIdx.x * blockDim.x + threadIdx.x;
    if (i < N_NODES) d_deg[i] = 0;
}

__global__ void hist_k(const int* __restrict__ ei)
{
    int e = blockIdx.x * blockDim.x + threadIdx.x;
    if (e >= N_EDGES) return;
    atomicAdd(&d_deg[ei[N_EDGES + e]], 1);
}

__global__ __launch_bounds__(1024) void scan_k()
{
    __shared__ int wsum[32];
    const int tid = threadIdx.x;
    const int ITEMS = (N_NODES + 1023) / 1024;   // 30
    int base = tid * ITEMS;
    int sum = 0;
#pragma unroll 4
    for (int i = 0; i < ITEMS; i++) {
        int idx = base + i;
        if (idx < N_NODES) sum += d_deg[idx];
    }
    int lane = tid & 31, wid = tid >> 5;
    int v = sum;
#pragma unroll
    for (int o = 1; o < 32; o <<= 1) {
        int y = __shfl_up_sync(0xFFFFFFFFu, v, o);
        if (lane >= o) v += y;
    }
    if (lane == 31) wsum[wid] = v;
    __syncthreads();
    if (wid == 0) {
        int w = wsum[lane];
#pragma unroll
        for (int o = 1; o < 32; o <<= 1) {
            int y = __shfl_up_sync(0xFFFFFFFFu, w, o);
            if (lane >= o) w += y;
        }
        wsum[lane] = w;
    }
    __syncthreads();
    int run = v - sum + (wid ? wsum[wid - 1] : 0);
#pragma unroll 4
    for (int i = 0; i < ITEMS; i++) {
        int idx = base + i;
        if (idx < N_NODES) {
            d_rowptr[idx] = run;
            d_cursor[idx] = run;
            run += d_deg[idx];
        }
    }
    if (tid == 1023) d_rowptr[N_NODES] = wsum[31];
}

__global__ void scatter_k(const int* __restrict__ ei)
{
    int e = blockIdx.x * blockDim.x + threadIdx.x;
    if (e >= N_EDGES) return;
    int s = ei[e], d = ei[N_EDGES + e];
    int p = atomicAdd(&d_cursor[d], 1);
    d_csr_src[p] = s;
}

// ---------------- GEMM1: fp16 A, fp16 B (single-term), cp.async 2-stage, ldmatrix ----------------
// smem stage layout: [A: 128 rows x 40 halves = 10240 B][B: 32 rows x 136 halves = 8704 B]
#define G1_BH    10240
#define G1_STAGE 18944

__global__ __launch_bounds__(256, 2) void gemm1_mma(
    const __half* __restrict__ Ax, const __half* __restrict__ Bh16,
    const float* __restrict__ att_s, const float* __restrict__ att_d,
    __half* __restrict__ C, int M)
{
    extern __shared__ char dsm[];
    const unsigned sbase = smem_u32(dsm);
    const int tid = threadIdx.x, lane = tid & 31, wid = tid >> 5;
    const int g = lane >> 2, t = lane & 3;
    const int wm = wid >> 2, wn = wid & 3;     // 2x4 warps, warp tile 64x32
    const int by = blockIdx.y, bx = blockIdx.x;
    const int gRow0 = by * 128;
    float acc[4][4][4] = {};

    const int ar0 = tid >> 2, ar1 = (tid + 256) >> 2, acc4 = (tid & 3);
    const int br0 = tid >> 4, br1 = (tid + 256) >> 4, bcc = (tid & 15);

    const unsigned aLane = (unsigned)((wm * 64 + (lane & 15)) * 80 + ((lane & 16) ? 16 : 0));
    const unsigned bLane = (unsigned)((lane & 15) * 272 + wn * 64 + ((lane & 16) ? 16 : 0));

    auto issue = [&](int kt, int st) {
        unsigned sb = sbase + st * G1_STAGE;
        {
            long r = gRow0 + ar0;
            CPA16(sb + ar0 * 80 + acc4 * 16, Ax + (size_t)r * F_IN + kt * 32 + acc4 * 8, (r < M) ? 16 : 0);
            r = gRow0 + ar1;
            CPA16(sb + ar1 * 80 + acc4 * 16, Ax + (size_t)r * F_IN + kt * 32 + acc4 * 8, (r < M) ? 16 : 0);
        }
        CPA16(sb + G1_BH + br0 * 272 + bcc * 16, Bh16 + (size_t)(kt * 32 + br0) * HC + bx * 128 + bcc * 8, 16);
        CPA16(sb + G1_BH + br1 * 272 + bcc * 16, Bh16 + (size_t)(kt * 32 + br1) * HC + bx * 128 + bcc * 8, 16);
        asm volatile("cp.async.commit_group;\n" ::: "memory");
    };

    issue(0, 0);
    for (int kt = 0; kt < F_IN / 32; kt++) {
        if (kt < F_IN / 32 - 1) {
            issue(kt + 1, (kt + 1) & 1);
            asm volatile("cp.async.wait_group 1;\n" ::: "memory");
        } else {
            asm volatile("cp.async.wait_group 0;\n" ::: "memory");
        }
        __syncthreads();
        unsigned sb = sbase + (kt & 1) * G1_STAGE;
#pragma unroll
        for (int s = 0; s < 2; s++) {
            unsigned ah[4][4];
#pragma unroll
            for (int mt = 0; mt < 4; mt++)
                ldsm_x4(ah[mt][0], ah[mt][1], ah[mt][2], ah[mt][3],
                        sb + aLane + mt * 1280 + s * 32);
#pragma unroll
            for (int p = 0; p < 2; p++) {
                unsigned h0, h1, h2, h3;
                ldsm_x4_t(h0, h1, h2, h3, sb + G1_BH + bLane + s * 4352 + p * 32);
#pragma unroll
                for (int mt = 0; mt < 4; mt++) {
                    mma_f16(acc[mt][p * 2],     ah[mt], h0, h1);
                    mma_f16(acc[mt][p * 2 + 1], ah[mt], h2, h3);
                }
            }
        }
        __syncthreads();
    }
    // store C tile as fp16
#pragma unroll
    for (int mt = 0; mt < 4; mt++) {
        int r0 = gRow0 + wm * 64 + mt * 16 + g;
        int r1 = r0 + 8;
#pragma unroll
        for (int nt = 0; nt < 4; nt++) {
            int col = bx * 128 + wn * 32 + nt * 8 + 2 * t;
            if (r0 < M) *(__half2*)(C + (size_t)r0 * HC + col) = __floats2half2_rn(acc[mt][nt][0], acc[mt][nt][1]);
            if (r1 < M) *(__half2*)(C + (size_t)r1 * HC + col) = __floats2half2_rn(acc[mt][nt][2], acc[mt][nt][3]);
        }
    }
    // fused score epilogue (sred aliases stage smem; safe after trailing barrier)
    float* sred = reinterpret_cast<float*>(dsm);   // [4][128][2]
    const float* as = att_s + bx * CDIM;
    const float* ad = att_d + bx * CDIM;
    float pss[4][2] = {}, psd[4][2] = {};
#pragma unroll
    for (int nt = 0; nt < 4; nt++) {
        int col = wn * 32 + nt * 8 + 2 * t;
        float a0 = as[col], a1 = as[col + 1];
        float e0 = ad[col], e1 = ad[col + 1];
#pragma unroll
        for (int mt = 0; mt < 4; mt++) {
            pss[mt][0] += acc[mt][nt][0] * a0 + acc[mt][nt][1] * a1;
            pss[mt][1] += acc[mt][nt][2] * a0 + acc[mt][nt][3] * a1;
            psd[mt][0] += acc[mt][nt][0] * e0 + acc[mt][nt][1] * e1;
            psd[mt][1] += acc[mt][nt][2] * e0 + acc[mt][nt][3] * e1;
        }
    }
#pragma unroll
    for (int o = 1; o <= 2; o <<= 1)
#pragma unroll
        for (int mt = 0; mt < 4; mt++)
#pragma unroll
            for (int rh = 0; rh < 2; rh++) {
                pss[mt][rh] += __shfl_xor_sync(0xFFFFFFFFu, pss[mt][rh], o);
                psd[mt][rh] += __shfl_xor_sync(0xFFFFFFFFu, psd[mt][rh], o);
            }
    if (t == 0) {
#pragma unroll
        for (int mt = 0; mt < 4; mt++)
#pragma unroll
            for (int rh = 0; rh < 2; rh++) {
                int rl = wm * 64 + mt * 16 + rh * 8 + g;
                sred[(wn * 128 + rl) * 2 + 0] = pss[mt][rh];
                sred[(wn * 128 + rl) * 2 + 1] = psd[mt][rh];
            }
    }
    __syncthreads();
    {
        int rl = tid >> 1, which = tid & 1;
        float sum = sred[(0 * 128 + rl) * 2 + which] + sred[(1 * 128 + rl) * 2 + which]
                  + sred[(2 * 128 + rl) * 2 + which] + sred[(3 * 128 + rl) * 2 + which];
        int row = gRow0 + rl;
        if (row < M) {
            if (which) d_adst1[row * HEADS + bx] = sum;
            else       d_asrc1[row * HEADS + bx] = sum;
        }
    }
}

// ---------------- layer-1 aggregation: per 4-head group, fused bias+ELU, fp16 out ----------------
__global__ __launch_bounds__(128) void agg1_k(const float* __restrict__ b1, int h0)
{
    __shared__ int   s_src[32];
    __shared__ float s_w[4][32];
    const int n = blockIdx.x;
    const int hw = threadIdx.x >> 5, lane = threadIdx.x & 31;
    const int h = h0 + hw;
    const float adst = d_adst1[n * HEADS + h];
    const float ws = __expf(lrelu(d_asrc1[n * HEADS + h] + adst));
    const size_t rowoff = (size_t)h * CDIM + lane * 4;

    float4 acc = make_float4(0.f, 0.f, 0.f, 0.f);
    acc_h4(acc, d_h1h + (size_t)n * HC + rowoff, ws);
    float denom = ws;

    const int beg = d_rowptr[n], end = d_rowptr[n + 1];
    for (int c0 = beg; c0 < end; c0 += 32) {
        const int m = min(32, end - c0);
        if (hw == 0 && lane < m) s_src[lane] = d_csr_src[c0 + lane];
        __syncthreads();
        if (lane < m)
            s_w[hw][lane] = __expf(lrelu(__ldg(&d_asrc1[s_src[lane] * HEADS + h]) + adst));
        __syncwarp();
        int jm = m & ~3;
        for (int j = 0; j < jm; j += 4) {
            int s0 = s_src[j], s1 = s_src[j + 1], s2 = s_src[j + 2], s3 = s_src[j + 3];
            float w0 = s_w[hw][j], w1 = s_w[hw][j + 1], w2 = s_w[hw][j + 2], w3 = s_w[hw][j + 3];
            uint2 r0 = *(const uint2*)(d_h1h + (size_t)s0 * HC + rowoff);
            uint2 r1 = *(const uint2*)(d_h1h + (size_t)s1 * HC + rowoff);
            uint2 r2 = *(const uint2*)(d_h1h + (size_t)s2 * HC + rowoff);
            uint2 r3 = *(const uint2*)(d_h1h + (size_t)s3 * HC + rowoff);
            float2 a0 = __half22float2(*reinterpret_cast<const __half2*>(&r0.x));
            float2 b0 = __half22float2(*reinterpret_cast<const __half2*>(&r0.y));
            float2 a1 = __half22float2(*reinterpret_cast<const __half2*>(&r1.x));
            float2 b1v = __half22float2(*reinterpret_cast<const __half2*>(&r1.y));
            float2 a2 = __half22float2(*reinterpret_cast<const __half2*>(&r2.x));
            float2 b2v = __half22float2(*reinterpret_cast<const __half2*>(&r2.y));
            float2 a3 = __half22float2(*reinterpret_cast<const __half2*>(&r3.x));
            float2 b3v = __half22float2(*reinterpret_cast<const __half2*>(&r3.y));
            acc.x += w0 * a0.x + w1 * a1.x + w2 * a2.x + w3 * a3.x;
            acc.y += w0 * a0.y + w1 * a1.y + w2 * a2.y + w3 * a3.y;
            acc.z += w0 * b0.x + w1 * b1v.x + w2 * b2v.x + w3 * b3v.x;
            acc.w += w0 * b0.y + w1 * b1v.y + w2 * b2v.y + w3 * b3v.y;
            denom += w0 + w1 + w2 + w3;
        }
        for (int j = jm; j < m; j++) {
            float w = s_w[hw][j];
            acc_h4(acc, d_h1h + (size_t)s_src[j] * HC + rowoff, w);
            denom += w;
        }
        __syncthreads();
    }
    float inv = 1.f / (denom + 1e-16f);
    float4 bv = *(const float4*)(b1 + rowoff);
    float4 r;
    r.x = acc.x * inv + bv.x;
    r.y = acc.y * inv + bv.y;
    r.z = acc.z * inv + bv.z;
    r.w = acc.w * inv + bv.w;
    r.x = r.x > 0.f ? r.x : expm1f(r.x);
    r.y = r.y > 0.f ? r.y : expm1f(r.y);
    r.z = r.z > 0.f ? r.z : expm1f(r.z);
    r.w = r.w > 0.f ? r.w : expm1f(r.w);
    __half2 o0 = __floats2half2_rn(r.x, r.y);
    __half2 o1 = __floats2half2_rn(r.z, r.w);
    unsigned long long pack = (unsigned long long)*reinterpret_cast<unsigned*>(&o0)
                            | ((unsigned long long)*reinterpret_cast<unsigned*>(&o1) << 32);
    __stcs((unsigned long long*)(d_agg1h + (size_t)n * HC + rowoff), pack);
}

// ---------------- GEMM2 (fp16 A direct, B fp16 hi+lo, 2-term mma) + fused scores ----------------
__global__ __launch_bounds__(256, 1) void gemm2_mma(
    const __half* __restrict__ A, const float* __restrict__ B,
    const float* __restrict__ att_s, const float* __restrict__ att_d,
    float* __restrict__ C, int M)
{
    __shared__ unsigned As_f[16][136];
    __shared__ unsigned Bs_h[16][72], Bs_l[16][72];
    __shared__ float sred[2][128][2];
    const int tid = threadIdx.x, lane = tid & 31, wid = tid >> 5;
    const int g = lane >> 2, t = lane & 3;
    const int wm = wid >> 1, wn = wid & 1;     // 4x2 warps, warp tile 32x32
    const int by = blockIdx.x;
    float acc[2][4][4] = {};

    const int arow = tid >> 1, akoff = (tid & 1) * 16;
    const int gArow = by * 128 + arow;
    const bool aval = gArow < M;
    const __half* Ap = A + (size_t)gArow * HC + akoff;
    const int bk2 = tid >> 4, bcol = (tid & 15) * 4;
    const float* Bp = B + (size_t)(2 * bk2) * OUTD + bcol;

    uint2 sA[4];
    float4 sB0, sB1;
    {
#pragma unroll
        for (int i = 0; i < 4; i++)
            sA[i] = aval ? __ldcs((const uint2*)(Ap + 4 * i)) : make_uint2(0u, 0u);
        sB0 = *(const float4*)Bp;
        sB1 = *(const float4*)(Bp + OUTD);
    }

    for (int kt = 0; kt < HC / 32; kt++) {
#pragma unroll
        for (int i = 0; i < 4; i++) {
            int k2 = (akoff >> 1) + 2 * i;
            As_f[k2][arow]     = sA[i].x;
            As_f[k2 + 1][arow] = sA[i].y;
        }
        {
            unsigned h, l;
            split2h(sB0.x, sB1.x, h, l); Bs_h[bk2][bcol] = h;     Bs_l[bk2][bcol] = l;
            split2h(sB0.y, sB1.y, h, l); Bs_h[bk2][bcol + 1] = h; Bs_l[bk2][bcol + 1] = l;
            split2h(sB0.z, sB1.z, h, l); Bs_h[bk2][bcol + 2] = h; Bs_l[bk2][bcol + 2] = l;
            split2h(sB0.w, sB1.w, h, l); Bs_h[bk2][bcol + 3] = h; Bs_l[bk2][bcol + 3] = l;
        }
        __syncthreads();
        if (kt < HC / 32 - 1) {
            const __half* Ap2 = Ap + 32 * (kt + 1);
#pragma unroll
            for (int i = 0; i < 4; i++)
                sA[i] = aval ? __ldcs((const uint2*)(Ap2 + 4 * i)) : make_uint2(0u, 0u);
            const float* Bp2 = Bp + (size_t)32 * OUTD * (kt + 1);
            sB0 = *(const float4*)Bp2;
            sB1 = *(const float4*)(Bp2 + OUTD);
        }
#pragma unroll
        for (int s = 0; s < 2; s++) {
            unsigned ah[2][4];
#pragma unroll
            for (int mt = 0; mt < 2; mt++) {
                int m0 = wm * 32 + mt * 16 + g;
                ah[mt][0] = As_f[s * 8 + t][m0];
                ah[mt][1] = As_f[s * 8 + t][m0 + 8];
                ah[mt][2] = As_f[s * 8 + t + 4][m0];
                ah[mt][3] = As_f[s * 8 + t + 4][m0 + 8];
            }
#pragma unroll
            for (int nt = 0; nt < 4; nt++) {
                int n0 = wn * 32 + nt * 8 + g;
                unsigned bh0 = Bs_h[s * 8 + t][n0], bh1 = Bs_h[s * 8 + t + 4][n0];
                unsigned bl0 = Bs_l[s * 8 + t][n0], bl1 = Bs_l[s * 8 + t + 4][n0];
#pragma unroll
                for (int mt = 0; mt < 2; mt++) {
                    mma_f16(acc[mt][nt], ah[mt], bh0, bh1);
                    mma_f16(acc[mt][nt], ah[mt], bl0, bl1);
                }
            }
        }
        __syncthreads();
    }
#pragma unroll
    for (int mt = 0; mt < 2; mt++) {
        int r0 = by * 128 + wm * 32 + mt * 16 + g;
        int r1 = r0 + 8;
#pragma unroll
        for (int nt = 0; nt < 4; nt++) {
            int col = wn * 32 + nt * 8 + 2 * t;
            if (r0 < M) *(float2*)(C + (size_t)r0 * OUTD + col) = make_float2(acc[mt][nt][0], acc[mt][nt][1]);
            if (r1 < M) *(float2*)(C + (size_t)r1 * OUTD + col) = make_float2(acc[mt][nt][2], acc[mt][nt][3]);
        }
    }
    // fused score epilogue
    float pss[2][2] = {}, psd[2][2] = {};
#pragma unroll
    for (int nt = 0; nt < 4; nt++) {
        int col = wn * 32 + nt * 8 + 2 * t;
        float a0 = att_s[col], a1 = att_s[col + 1];
        float e0 = att_d[col], e1 = att_d[col + 1];
#pragma unroll
        for (int mt = 0; mt < 2; mt++) {
            pss[mt][0] += acc[mt][nt][0] * a0 + acc[mt][nt][1] * a1;
            pss[mt][1] += acc[mt][nt][2] * a0 + acc[mt][nt][3] * a1;
            psd[mt][0] += acc[mt][nt][0] * e0 + acc[mt][nt][1] * e1;
            psd[mt][1] += acc[mt][nt][2] * e0 + acc[mt][nt][3] * e1;
        }
    }
#pragma unroll
    for (int o = 1; o <= 2; o <<= 1)
#pragma unroll
        for (int mt = 0; mt < 2; mt++)
#pragma unroll
            for (int rh = 0; rh < 2; rh++) {
                pss[mt][rh] += __shfl_xor_sync(0xFFFFFFFFu, pss[mt][rh], o);
                psd[mt][rh] += __shfl_xor_sync(0xFFFFFFFFu, psd[mt][rh], o);
            }
    if (t == 0) {
#pragma unroll
        for (int mt = 0; mt < 2; mt++)
#pragma unroll
            for (int rh = 0; rh < 2; rh++) {
                int rl = wm * 32 + mt * 16 + rh * 8 + g;
                sred[wn][rl][0] = pss[mt][rh];
                sred[wn][rl][1] = psd[mt][rh];
            }
    }
    __syncthreads();
    {
        int rl = tid >> 1, which = tid & 1;
        float sum = sred[0][rl][which] + sred[1][rl][which];
        int row = by * 128 + rl;
        if (row < M) {
            if (which) d_adst2[row] = sum;
            else       d_asrc2[row] = sum;
        }
    }
}

// ---------------- layer-2 one-pass aggregation + bias + log_softmax (MLP-4) ----------------
__global__ __launch_bounds__(256) void agg2_k(float* __restrict__ out, const float* __restrict__ b2)
{
    int n = blockIdx.x * 8 + (threadIdx.x >> 5);
    int lane = threadIdx.x & 31;
    if (n >= N_NODES) return;
    float adst = d_adst2[n];
    float ws = __expf(lrelu(d_asrc2[n] + adst));
    const float* hp = d_h2 + (size_t)n * OUTD;
    float acc0 = ws * hp[lane], acc1 = ws * hp[lane + 32];
    float denom = ws;
    const int beg = d_rowptr[n], end = d_rowptr[n + 1];
    int j = beg;
    for (; j + 4 <= end; j += 4) {
        int s0 = __ldg(&d_csr_src[j]);
        int s1 = __ldg(&d_csr_src[j + 1]);
        int s2 = __ldg(&d_csr_src[j + 2]);
        int s3 = __ldg(&d_csr_src[j + 3]);
        float w0 = __expf(lrelu(__ldg(&d_asrc2[s0]) + adst));
        float w1 = __expf(lrelu(__ldg(&d_asrc2[s1]) + adst));
        float w2 = __expf(lrelu(__ldg(&d_asrc2[s2]) + adst));
        float w3 = __expf(lrelu(__ldg(&d_asrc2[s3]) + adst));
        const float* p0 = d_h2 + (size_t)s0 * OUTD;
        const float* p1 = d_h2 + (size_t)s1 * OUTD;
        const float* p2 = d_h2 + (size_t)s2 * OUTD;
        const float* p3 = d_h2 + (size_t)s3 * OUTD;
        float f00 = p0[lane], f01 = p0[lane + 32];
        float f10 = p1[lane], f11 = p1[lane + 32];
        float f20 = p2[lane], f21 = p2[lane + 32];
        float f30 = p3[lane], f31 = p3[lane + 32];
        acc0 += w0 * f00 + w1 * f10 + w2 * f20 + w3 * f30;
        acc1 += w0 * f01 + w1 * f11 + w2 * f21 + w3 * f31;
        denom += w0 + w1 + w2 + w3;
    }
    for (; j < end; j++) {
        int s = __ldg(&d_csr_src[j]);
        float w = __expf(lrelu(__ldg(&d_asrc2[s]) + adst));
        const float* sp = d_h2 + (size_t)s * OUTD;
        acc0 += w * sp[lane];
        acc1 += w * sp[lane + 32];
        denom += w;
    }
    float inv = 1.f / (denom + 1e-16f);
    float x0 = acc0 * inv + b2[lane];
    float x1 = acc1 * inv + b2[lane + 32];
    float mx = fmaxf(x0, x1);
#pragma unroll
    for (int o = 16; o; o >>= 1) mx = fmaxf(mx, __shfl_xor_sync(0xFFFFFFFFu, mx, o));
    float sm = __expf(x0 - mx) + __expf(x1 - mx);
#pragma unroll
    for (int o = 16; o; o >>= 1) sm += __shfl_xor_sync(0xFFFFFFFFu, sm, o);
    float lse = mx + logf(sm);
    out[(size_t)n * OUTD + lane] = x0 - lse;
    out[(size_t)n * OUTD + lane + 32] = x1 - lse;
}

// ---------------- launch ----------------
extern "C" void kernel_launch(void* const* d_in, const int* in_sizes, int n_in,
                              void* d_out, int out_size)
{
    const float* x   = (const float*)d_in[0];
    const int*   ei  = (const int*)  d_in[1];
    const float* W1  = (const float*)d_in[2];
    const float* as1 = (const float*)d_in[3];
    const float* ad1 = (const float*)d_in[4];
    const float* b1  = (const float*)d_in[5];
    const float* W2  = (const float*)d_in[6];
    const float* as2 = (const float*)d_in[7];
    const float* ad2 = (const float*)d_in[8];
    const float* b2  = (const float*)d_in[9];
    float* out = (float*)d_out;

    __half *h1p, *agg1hp, *xhp, *w1hp;
    float *h2p;
    cudaGetSymbolAddress((void**)&h1p,    d_h1h);
    cudaGetSymbolAddress((void**)&agg1hp, d_agg1h);
    cudaGetSymbolAddress((void**)&xhp,    d_xh);
    cudaGetSymbolAddress((void**)&w1hp,   d_w1h);
    cudaGetSymbolAddress((void**)&h2p,    d_h2);

    cudaFuncSetAttribute(gemm1_mma, cudaFuncAttributeMaxDynamicSharedMemorySize, 2 * G1_STAGE);

    // launch order keeps gemm1 in the profiled slot (#4)
    zero_deg_k<<<(N_NODES + 255) / 256, 256>>>();
    convx_k<<<(N_NODES * F_IN / 4 + 255) / 256, 256>>>(x);
    convw1_k<<<(F_IN * HC / 4 + 255) / 256, 256>>>(W1);
    {
        dim3 g(HC / 128, (N_NODES + 127) / 128);
        gemm1_mma<<<g, 256, 2 * G1_STAGE>>>(xhp, w1hp, as1, ad1, h1p, N_NODES);
    }
    hist_k<<<(N_EDGES + 255) / 256, 256>>>(ei);
    scan_k<<<1, 1024>>>();
    scatter_k<<<(N_EDGES + 255) / 256, 256>>>(ei);

    // layer-1 aggregation: two serialized head-group passes (30.7 MB L2-resident each)
    agg1_k<<<N_NODES, 128>>>(b1, 0);
    agg1_k<<<N_NODES, 128>>>(b1, 4);

    // layer 2
    gemm2_mma<<<(N_NODES + 127) / 128, 256>>>(agg1hp, W2, as2, ad2, h2p, N_NODES);
    agg2_k<<<(N_NODES + 7) / 8, 256>>>(out, b2);
}

// round 14
// speedup vs baseline: 4.1308x; 1.0766x over previous
#include <cuda_runtime.h>
#include <cuda_bf16.h>
#include <cuda_fp16.h>
#include <math.h>

#define N_NODES 30000
#define F_IN    256
#define N_EDGES 300000
#define HEADS   8
#define CDIM    128
#define HC      1024
#define OUTD    64
#define NEG_SLOPE 0.2f

// ---------------- scratch ----------------
__device__ __align__(256) __half d_h1h  [(size_t)N_NODES * HC];  // 61.4 MB
__device__ __align__(256) __half d_agg1h[(size_t)N_NODES * HC];  // 61.4 MB
__device__ __align__(256) __half d_xh   [(size_t)N_NODES * F_IN]; // 15.4 MB
__device__ __align__(256) __half d_w1h  [F_IN * HC];              // W1 fp16
__device__ __align__(256) __half d_w2h  [HC * OUTD];              // W2 hi fp16
__device__ __align__(256) __half d_w2l  [HC * OUTD];              // W2 lo fp16
__device__ __align__(256) float  d_asrc1[N_NODES * HEADS];
__device__ __align__(256) float  d_adst1[N_NODES * HEADS];
__device__ __align__(256) float  d_h2  [(size_t)N_NODES * OUTD];
__device__ __align__(256) float  d_asrc2[N_NODES];
__device__ __align__(256) float  d_adst2[N_NODES];
__device__ __align__(256) int    d_deg   [N_NODES];
__device__ __align__(256) int    d_rowptr[N_NODES + 1];
__device__ __align__(256) int    d_cursor[N_NODES];
__device__ __align__(256) int    d_csr_src[N_EDGES];

// ---------------- helpers ----------------
__device__ __forceinline__ float lrelu(float x) { return x > 0.f ? x : NEG_SLOPE * x; }

__device__ __forceinline__ unsigned smem_u32(const void* p) {
    unsigned a;
    asm("{ .reg .u64 t; cvta.to.shared.u64 t, %1; cvt.u32.u64 %0, t; }" : "=r"(a) : "l"(p));
    return a;
}

__device__ __forceinline__ void split2h(float x, float y, unsigned& h, unsigned& l) {
    __half hx = __float2half_rn(x);
    __half hy = __float2half_rn(y);
    float rx = x - __half2float(hx);
    float ry = y - __half2float(hy);
    __half lx = __float2half_rn(rx);
    __half ly = __float2half_rn(ry);
    h = (unsigned)__half_as_ushort(hx) | ((unsigned)__half_as_ushort(hy) << 16);
    l = (unsigned)__half_as_ushort(lx) | ((unsigned)__half_as_ushort(ly) << 16);
}

__device__ __forceinline__ void mma_f16(float* c, const unsigned* a, unsigned b0, unsigned b1) {
    asm volatile("mma.sync.aligned.m16n8k16.row.col.f32.f16.f16.f32 "
                 "{%0,%1,%2,%3}, {%4,%5,%6,%7}, {%8,%9}, {%0,%1,%2,%3};\n"
                 : "+f"(c[0]), "+f"(c[1]), "+f"(c[2]), "+f"(c[3])
                 : "r"(a[0]), "r"(a[1]), "r"(a[2]), "r"(a[3]), "r"(b0), "r"(b1));
}

__device__ __forceinline__ void ldsm_x4(unsigned& r0, unsigned& r1, unsigned& r2, unsigned& r3, unsigned a) {
    asm volatile("ldmatrix.sync.aligned.m8n8.x4.shared.b16 {%0,%1,%2,%3}, [%4];"
                 : "=r"(r0), "=r"(r1), "=r"(r2), "=r"(r3) : "r"(a));
}
__device__ __forceinline__ void ldsm_x4_t(unsigned& r0, unsigned& r1, unsigned& r2, unsigned& r3, unsigned a) {
    asm volatile("ldmatrix.sync.aligned.m8n8.x4.trans.shared.b16 {%0,%1,%2,%3}, [%4];"
                 : "=r"(r0), "=r"(r1), "=r"(r2), "=r"(r3) : "r"(a));
}

#define CPA16(dst, src, sz) \
    asm volatile("cp.async.cg.shared.global [%0], [%1], 16, %2;\n" :: "r"(dst), "l"(src), "r"(sz))

__device__ __forceinline__ void acc_h4(float4& acc, const __half* base, float w) {
    uint2 raw = *(const uint2*)base;
    float2 u0 = __half22float2(*reinterpret_cast<const __half2*>(&raw.x));
    float2 u1 = __half22float2(*reinterpret_cast<const __half2*>(&raw.y));
    acc.x += w * u0.x; acc.y += w * u0.y; acc.z += w * u1.x; acc.w += w * u1.y;
}

// ---------------- conversion kernels ----------------
__global__ void convx_k(const float* __restrict__ x)
{
    int i = blockIdx.x * 256 + threadIdx.x;
    if (i >= N_NODES * F_IN / 4) return;
    float4 v = ((const float4*)x)[i];
    __half2 h0 = __floats2half2_rn(v.x, v.y), h1 = __floats2half2_rn(v.z, v.w);
    uint2 o;
    o.x = *reinterpret_cast<unsigned*>(&h0);
    o.y = *reinterpret_cast<unsigned*>(&h1);
    ((uint2*)d_xh)[i] = o;
}

__global__ void convw1_k(const float* __restrict__ W)
{
    int i = blockIdx.x * 256 + threadIdx.x;
    if (i >= F_IN * HC / 4) return;
    float4 v = ((const float4*)W)[i];
    __half2 h0 = __floats2half2_rn(v.x, v.y), h1 = __floats2half2_rn(v.z, v.w);
    uint2 o;
    o.x = *reinterpret_cast<unsigned*>(&h0);
    o.y = *reinterpret_cast<unsigned*>(&h1);
    ((uint2*)d_w1h)[i] = o;
}

__global__ void convw2_k(const float* __restrict__ W)
{
    int i = blockIdx.x * 256 + threadIdx.x;
    if (i >= HC * OUTD / 2) return;
    float2 v = ((const float2*)W)[i];
    unsigned h, l;
    split2h(v.x, v.y, h, l);
    ((unsigned*)d_w2h)[i] = h;
    ((unsigned*)d_w2l)[i] = l;
}

// ---------------- CSR build ----------------
__global__ void zero_deg_k()
{
    int i = blockIdx.x * blockDim.x + threadIdx.x;
    if (i < N_NODES) d_deg[i] = 0;
}

__global__ void hist_k(const int* __restrict__ ei)
{
    int e = blockIdx.x * blockDim.x + threadIdx.x;
    if (e >= N_EDGES) return;
    atomicAdd(&d_deg[ei[N_EDGES + e]], 1);
}

__global__ __launch_bounds__(1024) void scan_k()
{
    __shared__ int wsum[32];
    const int tid = threadIdx.x;
    const int ITEMS = (N_NODES + 1023) / 1024;   // 30
    int base = tid * ITEMS;
    int sum = 0;
#pragma unroll 4
    for (int i = 0; i < ITEMS; i++) {
        int idx = base + i;
        if (idx < N_NODES) sum += d_deg[idx];
    }
    int lane = tid & 31, wid = tid >> 5;
    int v = sum;
#pragma unroll
    for (int o = 1; o < 32; o <<= 1) {
        int y = __shfl_up_sync(0xFFFFFFFFu, v, o);
        if (lane >= o) v += y;
    }
    if (lane == 31) wsum[wid] = v;
    __syncthreads();
    if (wid == 0) {
        int w = wsum[lane];
#pragma unroll
        for (int o = 1; o < 32; o <<= 1) {
            int y = __shfl_up_sync(0xFFFFFFFFu, w, o);
            if (lane >= o) w += y;
        }
        wsum[lane] = w;
    }
    __syncthreads();
    int run = v - sum + (wid ? wsum[wid - 1] : 0);
#pragma unroll 4
    for (int i = 0; i < ITEMS; i++) {
        int idx = base + i;
        if (idx < N_NODES) {
            d_rowptr[idx] = run;
            d_cursor[idx] = run;
            run += d_deg[idx];
        }
    }
    if (tid == 1023) d_rowptr[N_NODES] = wsum[31];
}

__global__ void scatter_k(const int* __restrict__ ei)
{
    int e = blockIdx.x * blockDim.x + threadIdx.x;
    if (e >= N_EDGES) return;
    int s = ei[e], d = ei[N_EDGES + e];
    int p = atomicAdd(&d_cursor[d], 1);
    d_csr_src[p] = s;
}

// ---------------- GEMM1: fp16 A, fp16 B (single-term), cp.async 2-stage, ldmatrix ----------------
// smem stage layout: [A: 128 rows x 40 halves = 10240 B][B: 32 rows x 136 halves = 8704 B]
#define G1_BH    10240
#define G1_STAGE 18944

__global__ __launch_bounds__(256, 2) void gemm1_mma(
    const __half* __restrict__ Ax, const __half* __restrict__ Bh16,
    const float* __restrict__ att_s, const float* __restrict__ att_d,
    __half* __restrict__ C, int M)
{
    extern __shared__ char dsm[];
    const unsigned sbase = smem_u32(dsm);
    const int tid = threadIdx.x, lane = tid & 31, wid = tid >> 5;
    const int g = lane >> 2, t = lane & 3;
    const int wm = wid >> 2, wn = wid & 3;     // 2x4 warps, warp tile 64x32
    const int by = blockIdx.y, bx = blockIdx.x;
    const int gRow0 = by * 128;
    float acc[4][4][4] = {};

    const int ar0 = tid >> 2, ar1 = (tid + 256) >> 2, acc4 = (tid & 3);
    const int br0 = tid >> 4, br1 = (tid + 256) >> 4, bcc = (tid & 15);

    const unsigned aLane = (unsigned)((wm * 64 + (lane & 15)) * 80 + ((lane & 16) ? 16 : 0));
    const unsigned bLane = (unsigned)((lane & 15) * 272 + wn * 64 + ((lane & 16) ? 16 : 0));

    auto issue = [&](int kt, int st) {
        unsigned sb = sbase + st * G1_STAGE;
        {
            long r = gRow0 + ar0;
            CPA16(sb + ar0 * 80 + acc4 * 16, Ax + (size_t)r * F_IN + kt * 32 + acc4 * 8, (r < M) ? 16 : 0);
            r = gRow0 + ar1;
            CPA16(sb + ar1 * 80 + acc4 * 16, Ax + (size_t)r * F_IN + kt * 32 + acc4 * 8, (r < M) ? 16 : 0);
        }
        CPA16(sb + G1_BH + br0 * 272 + bcc * 16, Bh16 + (size_t)(kt * 32 + br0) * HC + bx * 128 + bcc * 8, 16);
        CPA16(sb + G1_BH + br1 * 272 + bcc * 16, Bh16 + (size_t)(kt * 32 + br1) * HC + bx * 128 + bcc * 8, 16);
        asm volatile("cp.async.commit_group;\n" ::: "memory");
    };

    issue(0, 0);
    for (int kt = 0; kt < F_IN / 32; kt++) {
        if (kt < F_IN / 32 - 1) {
            issue(kt + 1, (kt + 1) & 1);
            asm volatile("cp.async.wait_group 1;\n" ::: "memory");
        } else {
            asm volatile("cp.async.wait_group 0;\n" ::: "memory");
        }
        __syncthreads();
        unsigned sb = sbase + (kt & 1) * G1_STAGE;
#pragma unroll
        for (int s = 0; s < 2; s++) {
            unsigned ah[4][4];
#pragma unroll
            for (int mt = 0; mt < 4; mt++)
                ldsm_x4(ah[mt][0], ah[mt][1], ah[mt][2], ah[mt][3],
                        sb + aLane + mt * 1280 + s * 32);
#pragma unroll
            for (int p = 0; p < 2; p++) {
                unsigned h0, h1, h2, h3;
                ldsm_x4_t(h0, h1, h2, h3, sb + G1_BH + bLane + s * 4352 + p * 32);
#pragma unroll
                for (int mt = 0; mt < 4; mt++) {
                    mma_f16(acc[mt][p * 2],     ah[mt], h0, h1);
                    mma_f16(acc[mt][p * 2 + 1], ah[mt], h2, h3);
                }
            }
        }
        __syncthreads();
    }
    // store C tile as fp16
#pragma unroll
    for (int mt = 0; mt < 4; mt++) {
        int r0 = gRow0 + wm * 64 + mt * 16 + g;
        int r1 = r0 + 8;
#pragma unroll
        for (int nt = 0; nt < 4; nt++) {
            int col = bx * 128 + wn * 32 + nt * 8 + 2 * t;
            if (r0 < M) *(__half2*)(C + (size_t)r0 * HC + col) = __floats2half2_rn(acc[mt][nt][0], acc[mt][nt][1]);
            if (r1 < M) *(__half2*)(C + (size_t)r1 * HC + col) = __floats2half2_rn(acc[mt][nt][2], acc[mt][nt][3]);
        }
    }
    // fused score epilogue
    float* sred = reinterpret_cast<float*>(dsm);   // [4][128][2]
    const float* as = att_s + bx * CDIM;
    const float* ad = att_d + bx * CDIM;
    float pss[4][2] = {}, psd[4][2] = {};
#pragma unroll
    for (int nt = 0; nt < 4; nt++) {
        int col = wn * 32 + nt * 8 + 2 * t;
        float a0 = as[col], a1 = as[col + 1];
        float e0 = ad[col], e1 = ad[col + 1];
#pragma unroll
        for (int mt = 0; mt < 4; mt++) {
            pss[mt][0] += acc[mt][nt][0] * a0 + acc[mt][nt][1] * a1;
            pss[mt][1] += acc[mt][nt][2] * a0 + acc[mt][nt][3] * a1;
            psd[mt][0] += acc[mt][nt][0] * e0 + acc[mt][nt][1] * e1;
            psd[mt][1] += acc[mt][nt][2] * e0 + acc[mt][nt][3] * e1;
        }
    }
#pragma unroll
    for (int o = 1; o <= 2; o <<= 1)
#pragma unroll
        for (int mt = 0; mt < 4; mt++)
#pragma unroll
            for (int rh = 0; rh < 2; rh++) {
                pss[mt][rh] += __shfl_xor_sync(0xFFFFFFFFu, pss[mt][rh], o);
                psd[mt][rh] += __shfl_xor_sync(0xFFFFFFFFu, psd[mt][rh], o);
            }
    if (t == 0) {
#pragma unroll
        for (int mt = 0; mt < 4; mt++)
#pragma unroll
            for (int rh = 0; rh < 2; rh++) {
                int rl = wm * 64 + mt * 16 + rh * 8 + g;
                sred[(wn * 128 + rl) * 2 + 0] = pss[mt][rh];
                sred[(wn * 128 + rl) * 2 + 1] = psd[mt][rh];
            }
    }
    __syncthreads();
    {
        int rl = tid >> 1, which = tid & 1;
        float sum = sred[(0 * 128 + rl) * 2 + which] + sred[(1 * 128 + rl) * 2 + which]
                  + sred[(2 * 128 + rl) * 2 + which] + sred[(3 * 128 + rl) * 2 + which];
        int row = gRow0 + rl;
        if (row < M) {
            if (which) d_adst1[row * HEADS + bx] = sum;
            else       d_asrc1[row * HEADS + bx] = sum;
        }
    }
}

// ---------------- layer-1 aggregation: per 4-head group, fused bias+ELU, fp16 out ----------------
__global__ __launch_bounds__(128) void agg1_k(const float* __restrict__ b1, int h0)
{
    __shared__ int   s_src[32];
    __shared__ float s_w[4][32];
    const int n = blockIdx.x;
    const int hw = threadIdx.x >> 5, lane = threadIdx.x & 31;
    const int h = h0 + hw;
    const float adst = d_adst1[n * HEADS + h];
    const float ws = __expf(lrelu(d_asrc1[n * HEADS + h] + adst));
    const size_t rowoff = (size_t)h * CDIM + lane * 4;

    float4 acc = make_float4(0.f, 0.f, 0.f, 0.f);
    acc_h4(acc, d_h1h + (size_t)n * HC + rowoff, ws);
    float denom = ws;

    const int beg = d_rowptr[n], end = d_rowptr[n + 1];
    for (int c0 = beg; c0 < end; c0 += 32) {
        const int m = min(32, end - c0);
        if (hw == 0 && lane < m) s_src[lane] = d_csr_src[c0 + lane];
        __syncthreads();
        if (lane < m)
            s_w[hw][lane] = __expf(lrelu(__ldg(&d_asrc1[s_src[lane] * HEADS + h]) + adst));
        __syncwarp();
        int jm = m & ~3;
        for (int j = 0; j < jm; j += 4) {
            int s0 = s_src[j], s1 = s_src[j + 1], s2 = s_src[j + 2], s3 = s_src[j + 3];
            float w0 = s_w[hw][j], w1 = s_w[hw][j + 1], w2 = s_w[hw][j + 2], w3 = s_w[hw][j + 3];
            uint2 r0 = *(const uint2*)(d_h1h + (size_t)s0 * HC + rowoff);
            uint2 r1 = *(const uint2*)(d_h1h + (size_t)s1 * HC + rowoff);
            uint2 r2 = *(const uint2*)(d_h1h + (size_t)s2 * HC + rowoff);
            uint2 r3 = *(const uint2*)(d_h1h + (size_t)s3 * HC + rowoff);
            float2 a0 = __half22float2(*reinterpret_cast<const __half2*>(&r0.x));
            float2 b0 = __half22float2(*reinterpret_cast<const __half2*>(&r0.y));
            float2 a1 = __half22float2(*reinterpret_cast<const __half2*>(&r1.x));
            float2 b1v = __half22float2(*reinterpret_cast<const __half2*>(&r1.y));
            float2 a2 = __half22float2(*reinterpret_cast<const __half2*>(&r2.x));
            float2 b2v = __half22float2(*reinterpret_cast<const __half2*>(&r2.y));
            float2 a3 = __half22float2(*reinterpret_cast<const __half2*>(&r3.x));
            float2 b3v = __half22float2(*reinterpret_cast<const __half2*>(&r3.y));
            acc.x += w0 * a0.x + w1 * a1.x + w2 * a2.x + w3 * a3.x;
            acc.y += w0 * a0.y + w1 * a1.y + w2 * a2.y + w3 * a3.y;
            acc.z += w0 * b0.x + w1 * b1v.x + w2 * b2v.x + w3 * b3v.x;
            acc.w += w0 * b0.y + w1 * b1v.y + w2 * b2v.y + w3 * b3v.y;
            denom += w0 + w1 + w2 + w3;
        }
        for (int j = jm; j < m; j++) {
            float w = s_w[hw][j];
            acc_h4(acc, d_h1h + (size_t)s_src[j] * HC + rowoff, w);
            denom += w;
        }
        __syncthreads();
    }
    float inv = 1.f / (denom + 1e-16f);
    float4 bv = *(const float4*)(b1 + rowoff);
    float4 r;
    r.x = acc.x * inv + bv.x;
    r.y = acc.y * inv + bv.y;
    r.z = acc.z * inv + bv.z;
    r.w = acc.w * inv + bv.w;
    r.x = r.x > 0.f ? r.x : expm1f(r.x);
    r.y = r.y > 0.f ? r.y : expm1f(r.y);
    r.z = r.z > 0.f ? r.z : expm1f(r.z);
    r.w = r.w > 0.f ? r.w : expm1f(r.w);
    __half2 o0 = __floats2half2_rn(r.x, r.y);
    __half2 o1 = __floats2half2_rn(r.z, r.w);
    unsigned long long pack = (unsigned long long)*reinterpret_cast<unsigned*>(&o0)
                            | ((unsigned long long)*reinterpret_cast<unsigned*>(&o1) << 32);
    __stcs((unsigned long long*)(d_agg1h + (size_t)n * HC + rowoff), pack);
}

// ---------------- GEMM2: fp16 A, W2 fp16 hi+lo, cp.async 2-stage, ldmatrix, 2 CTA/SM ------------
// stage layout: [A: 128 x 40 halves = 10240 B][Bh: 32 x 72 halves = 4608 B][Bl: 4608 B]
#define G2_BHOF  10240
#define G2_BLOF  14848
#define G2_STAGE 19456

__global__ __launch_bounds__(256, 2) void gemm2_mma(
    const __half* __restrict__ A, const __half* __restrict__ Bh16, const __half* __restrict__ Bl16,
    const float* __restrict__ att_s, const float* __restrict__ att_d,
    float* __restrict__ C, int M)
{
    extern __shared__ char dsm[];
    const unsigned sbase = smem_u32(dsm);
    const int tid = threadIdx.x, lane = tid & 31, wid = tid >> 5;
    const int g = lane >> 2, t = lane & 3;
    const int wm = wid >> 2, wn = wid & 3;     // 2x4 warps, warp tile 64x16
    const int by = blockIdx.x;
    const int gRow0 = by * 128;
    float acc[4][2][4] = {};

    const int ar0 = tid >> 2, ar1 = (tid + 256) >> 2, acc4 = (tid & 3);
    const int br = tid >> 3, bcc = (tid & 7);

    const unsigned aLane = (unsigned)((wm * 64 + (lane & 15)) * 80 + ((lane & 16) ? 16 : 0));
    const unsigned bLane = (unsigned)((lane & 15) * 144 + wn * 32 + ((lane & 16) ? 16 : 0));

    auto issue = [&](int kt, int st) {
        unsigned sb = sbase + st * G2_STAGE;
        {
            long r = gRow0 + ar0;
            CPA16(sb + ar0 * 80 + acc4 * 16, A + (size_t)r * HC + kt * 32 + acc4 * 8, (r < M) ? 16 : 0);
            r = gRow0 + ar1;
            CPA16(sb + ar1 * 80 + acc4 * 16, A + (size_t)r * HC + kt * 32 + acc4 * 8, (r < M) ? 16 : 0);
        }
        CPA16(sb + G2_BHOF + br * 144 + bcc * 16, Bh16 + (size_t)(kt * 32 + br) * OUTD + bcc * 8, 16);
        CPA16(sb + G2_BLOF + br * 144 + bcc * 16, Bl16 + (size_t)(kt * 32 + br) * OUTD + bcc * 8, 16);
        asm volatile("cp.async.commit_group;\n" ::: "memory");
    };

    issue(0, 0);
    for (int kt = 0; kt < HC / 32; kt++) {
        if (kt < HC / 32 - 1) {
            issue(kt + 1, (kt + 1) & 1);
            asm volatile("cp.async.wait_group 1;\n" ::: "memory");
        } else {
            asm volatile("cp.async.wait_group 0;\n" ::: "memory");
        }
        __syncthreads();
        unsigned sb = sbase + (kt & 1) * G2_STAGE;
#pragma unroll
        for (int s = 0; s < 2; s++) {
            unsigned ah[4][4];
#pragma unroll
            for (int mt = 0; mt < 4; mt++)
                ldsm_x4(ah[mt][0], ah[mt][1], ah[mt][2], ah[mt][3],
                        sb + aLane + mt * 1280 + s * 32);
            unsigned h0, h1, h2, h3, l0, l1, l2, l3;
            ldsm_x4_t(h0, h1, h2, h3, sb + G2_BHOF + bLane + s * 2304);
            ldsm_x4_t(l0, l1, l2, l3, sb + G2_BLOF + bLane + s * 2304);
#pragma unroll
            for (int mt = 0; mt < 4; mt++) {
                mma_f16(acc[mt][0], ah[mt], h0, h1);
                mma_f16(acc[mt][0], ah[mt], l0, l1);
                mma_f16(acc[mt][1], ah[mt], h2, h3);
                mma_f16(acc[mt][1], ah[mt], l2, l3);
            }
        }
        __syncthreads();
    }
    // store C tile (fp32)
#pragma unroll
    for (int mt = 0; mt < 4; mt++) {
        int r0 = gRow0 + wm * 64 + mt * 16 + g;
        int r1 = r0 + 8;
#pragma unroll
        for (int nt = 0; nt < 2; nt++) {
            int col = wn * 16 + nt * 8 + 2 * t;
            if (r0 < M) *(float2*)(C + (size_t)r0 * OUTD + col) = make_float2(acc[mt][nt][0], acc[mt][nt][1]);
            if (r1 < M) *(float2*)(C + (size_t)r1 * OUTD + col) = make_float2(acc[mt][nt][2], acc[mt][nt][3]);
        }
    }
    // fused score epilogue
    float* sred = reinterpret_cast<float*>(dsm);   // [4][128][2]
    float pss[4][2] = {}, psd[4][2] = {};
#pragma unroll
    for (int nt = 0; nt < 2; nt++) {
        int col = wn * 16 + nt * 8 + 2 * t;
        float a0 = att_s[col], a1 = att_s[col + 1];
        float e0 = att_d[col], e1 = att_d[col + 1];
#pragma unroll
        for (int mt = 0; mt < 4; mt++) {
            pss[mt][0] += acc[mt][nt][0] * a0 + acc[mt][nt][1] * a1;
            pss[mt][1] += acc[mt][nt][2] * a0 + acc[mt][nt][3] * a1;
            psd[mt][0] += acc[mt][nt][0] * e0 + acc[mt][nt][1] * e1;
            psd[mt][1] += acc[mt][nt][2] * e0 + acc[mt][nt][3] * e1;
        }
    }
#pragma unroll
    for (int o = 1; o <= 2; o <<= 1)
#pragma unroll
        for (int mt = 0; mt < 4; mt++)
#pragma unroll
            for (int rh = 0; rh < 2; rh++) {
                pss[mt][rh] += __shfl_xor_sync(0xFFFFFFFFu, pss[mt][rh], o);
                psd[mt][rh] += __shfl_xor_sync(0xFFFFFFFFu, psd[mt][rh], o);
            }
    if (t == 0) {
#pragma unroll
        for (int mt = 0; mt < 4; mt++)
#pragma unroll
            for (int rh = 0; rh < 2; rh++) {
                int rl = wm * 64 + mt * 16 + rh * 8 + g;
                sred[(wn * 128 + rl) * 2 + 0] = pss[mt][rh];
                sred[(wn * 128 + rl) * 2 + 1] = psd[mt][rh];
            }
    }
    __syncthreads();
    {
        int rl = tid >> 1, which = tid & 1;
        float sum = sred[(0 * 128 + rl) * 2 + which] + sred[(1 * 128 + rl) * 2 + which]
                  + sred[(2 * 128 + rl) * 2 + which] + sred[(3 * 128 + rl) * 2 + which];
        int row = gRow0 + rl;
        if (row < M) {
            if (which) d_adst2[row] = sum;
            else       d_asrc2[row] = sum;
        }
    }
}

// ---------------- layer-2 one-pass aggregation + bias + log_softmax (MLP-4) ----------------
__global__ __launch_bounds__(256) void agg2_k(float* __restrict__ out, const float* __restrict__ b2)
{
    int n = blockIdx.x * 8 + (threadIdx.x >> 5);
    int lane = threadIdx.x & 31;
    if (n >= N_NODES) return;
    float adst = d_adst2[n];
    float ws = __expf(lrelu(d_asrc2[n] + adst));
    const float* hp = d_h2 + (size_t)n * OUTD;
    float acc0 = ws * hp[lane], acc1 = ws * hp[lane + 32];
    float denom = ws;
    const int beg = d_rowptr[n], end = d_rowptr[n + 1];
    int j = beg;
    for (; j + 4 <= end; j += 4) {
        int s0 = __ldg(&d_csr_src[j]);
        int s1 = __ldg(&d_csr_src[j + 1]);
        int s2 = __ldg(&d_csr_src[j + 2]);
        int s3 = __ldg(&d_csr_src[j + 3]);
        float w0 = __expf(lrelu(__ldg(&d_asrc2[s0]) + adst));
        float w1 = __expf(lrelu(__ldg(&d_asrc2[s1]) + adst));
        float w2 = __expf(lrelu(__ldg(&d_asrc2[s2]) + adst));
        float w3 = __expf(lrelu(__ldg(&d_asrc2[s3]) + adst));
        const float* p0 = d_h2 + (size_t)s0 * OUTD;
        const float* p1 = d_h2 + (size_t)s1 * OUTD;
        const float* p2 = d_h2 + (size_t)s2 * OUTD;
        const float* p3 = d_h2 + (size_t)s3 * OUTD;
        float f00 = p0[lane], f01 = p0[lane + 32];
        float f10 = p1[lane], f11 = p1[lane + 32];
        float f20 = p2[lane], f21 = p2[lane + 32];
        float f30 = p3[lane], f31 = p3[lane + 32];
        acc0 += w0 * f00 + w1 * f10 + w2 * f20 + w3 * f30;
        acc1 += w0 * f01 + w1 * f11 + w2 * f21 + w3 * f31;
        denom += w0 + w1 + w2 + w3;
    }
    for (; j < end; j++) {
        int s = __ldg(&d_csr_src[j]);
        float w = __expf(lrelu(__ldg(&d_asrc2[s]) + adst));
        const float* sp = d_h2 + (size_t)s * OUTD;
        acc0 += w * sp[lane];
        acc1 += w * sp[lane + 32];
        denom += w;
    }
    float inv = 1.f / (denom + 1e-16f);
    float x0 = acc0 * inv + b2[lane];
    float x1 = acc1 * inv + b2[lane + 32];
    float mx = fmaxf(x0, x1);
#pragma unroll
    for (int o = 16; o; o >>= 1) mx = fmaxf(mx, __shfl_xor_sync(0xFFFFFFFFu, mx, o));
    float sm = __expf(x0 - mx) + __expf(x1 - mx);
#pragma unroll
    for (int o = 16; o; o >>= 1) sm += __shfl_xor_sync(0xFFFFFFFFu, sm, o);
    float lse = mx + logf(sm);
    out[(size_t)n * OUTD + lane] = x0 - lse;
    out[(size_t)n * OUTD + lane + 32] = x1 - lse;
}

// ---------------- launch ----------------
extern "C" void kernel_launch(void* const* d_in, const int* in_sizes, int n_in,
                              void* d_out, int out_size)
{
    const float* x   = (const float*)d_in[0];
    const int*   ei  = (const int*)  d_in[1];
    const float* W1  = (const float*)d_in[2];
    const float* as1 = (const float*)d_in[3];
    const float* ad1 = (const float*)d_in[4];
    const float* b1  = (const float*)d_in[5];
    const float* W2  = (const float*)d_in[6];
    const float* as2 = (const float*)d_in[7];
    const float* ad2 = (const float*)d_in[8];
    const float* b2  = (const float*)d_in[9];
    float* out = (float*)d_out;

    __half *h1p, *agg1hp, *xhp, *w1hp, *w2hp, *w2lp;
    float *h2p;
    cudaGetSymbolAddress((void**)&h1p,    d_h1h);
    cudaGetSymbolAddress((void**)&agg1hp, d_agg1h);
    cudaGetSymbolAddress((void**)&xhp,    d_xh);
    cudaGetSymbolAddress((void**)&w1hp,   d_w1h);
    cudaGetSymbolAddress((void**)&w2hp,   d_w2h);
    cudaGetSymbolAddress((void**)&w2lp,   d_w2l);
    cudaGetSymbolAddress((void**)&h2p,    d_h2);

    cudaFuncSetAttribute(gemm1_mma, cudaFuncAttributeMaxDynamicSharedMemorySize, 2 * G1_STAGE);
    cudaFuncSetAttribute(gemm2_mma, cudaFuncAttributeMaxDynamicSharedMemorySize, 2 * G2_STAGE);

    // launch order keeps gemm1 in the profiled slot (#4)
    zero_deg_k<<<(N_NODES + 255) / 256, 256>>>();
    convx_k<<<(N_NODES * F_IN / 4 + 255) / 256, 256>>>(x);
    convw1_k<<<(F_IN * HC / 4 + 255) / 256, 256>>>(W1);
    {
        dim3 g(HC / 128, (N_NODES + 127) / 128);
        gemm1_mma<<<g, 256, 2 * G1_STAGE>>>(xhp, w1hp, as1, ad1, h1p, N_NODES);
    }
    convw2_k<<<(HC * OUTD / 2 + 255) / 256, 256>>>(W2);
    hist_k<<<(N_EDGES + 255) / 256, 256>>>(ei);
    scan_k<<<1, 1024>>>();
    scatter_k<<<(N_EDGES + 255) / 256, 256>>>(ei);

    // layer-1 aggregation: two serialized head-group passes (30.7 MB L2-resident each)
    agg1_k<<<N_NODES, 128>>>(b1, 0);
    agg1_k<<<N_NODES, 128>>>(b1, 4);

    // layer 2
    gemm2_mma<<<(N_NODES + 127) / 128, 256, 2 * G2_STAGE>>>(agg1hp, w2hp, w2lp, as2, ad2, h2p, N_NODES);
    agg2_k<<<(N_NODES + 7) / 8, 256>>>(out, b2);
}